// round 8
// baseline (speedup 1.0000x reference)
#include <cuda_runtime.h>
#include <cuda_fp16.h>
#include <math.h>
#include <stdint.h>

// Problem constants
#define SEQ    4096
#define DMODEL 2048
#define NHEAD  16
#define NKV    4
#define HDIM   128
#define NQKV   3072
#define SCALE  0.08838834764831845f   // 1/sqrt(128)

// ---------------------------------------------------------------------------
// Scratch (device globals; no allocation allowed)
// ---------------------------------------------------------------------------
__device__ float  g_QKV[SEQ * NQKV];          // fused Q|K|V fp32 (gemm out)
__device__ __half g_Wt[NQKV * DMODEL];        // fused Wq|Wk|Wv transposed [N,K]
__device__ __half g_Wot[DMODEL * DMODEL];     // Wo transposed [N,K]
__device__ __half g_Xhi[SEQ * DMODEL];        // X hi/lo split
__device__ __half g_Xlo[SEQ * DMODEL];
__device__ __half g_Qh[NHEAD * SEQ * HDIM];   // per-head planes, rope+scale
__device__ __half g_Kh[NKV * SEQ * HDIM];     // rope applied
__device__ __half g_Vh[NKV * SEQ * HDIM];
__device__ __half g_AOhi[SEQ * DMODEL];       // attention out hi/lo split
__device__ __half g_AOlo[SEQ * DMODEL];

// ---------------------------------------------------------------------------
// helpers
// ---------------------------------------------------------------------------
__device__ __forceinline__ void mma_f16(float c[4], const uint32_t a[4], const uint32_t b[2]) {
    asm volatile(
        "mma.sync.aligned.m16n8k16.row.col.f32.f16.f16.f32 "
        "{%0,%1,%2,%3}, {%4,%5,%6,%7}, {%8,%9}, {%0,%1,%2,%3};\n"
        : "+f"(c[0]), "+f"(c[1]), "+f"(c[2]), "+f"(c[3])
        : "r"(a[0]), "r"(a[1]), "r"(a[2]), "r"(a[3]), "r"(b[0]), "r"(b[1]));
}

__device__ __forceinline__ uint32_t pack_h2(float x, float y) {
    __half2 h = __floats2half2_rn(x, y);
    return *(uint32_t*)&h;
}

__device__ __forceinline__ void cpa16(uint32_t saddr, const void* g) {
    asm volatile("cp.async.cg.shared.global [%0], [%1], 16;" :: "r"(saddr), "l"(g));
}
#define CP_COMMIT() asm volatile("cp.async.commit_group;" ::: "memory")
#define CP_WAIT(n)  asm volatile("cp.async.wait_group %0;" :: "n"(n) : "memory")

__device__ __forceinline__ void ldsm4(uint32_t& r0, uint32_t& r1, uint32_t& r2, uint32_t& r3,
                                      uint32_t addr) {
    asm volatile("ldmatrix.sync.aligned.m8n8.x4.shared.b16 {%0,%1,%2,%3}, [%4];"
                 : "=r"(r0), "=r"(r1), "=r"(r2), "=r"(r3) : "r"(addr));
}
__device__ __forceinline__ void ldsm4t(uint32_t& r0, uint32_t& r1, uint32_t& r2, uint32_t& r3,
                                       uint32_t addr) {
    asm volatile("ldmatrix.sync.aligned.m8n8.x4.trans.shared.b16 {%0,%1,%2,%3}, [%4];"
                 : "=r"(r0), "=r"(r1), "=r"(r2), "=r"(r3) : "r"(addr));
}
__device__ __forceinline__ void stsm4(uint32_t addr, uint32_t r0, uint32_t r1,
                                      uint32_t r2, uint32_t r3) {
    asm volatile("stmatrix.sync.aligned.m8n8.x4.shared.b16 [%0], {%1,%2,%3,%4};"
                 :: "r"(addr), "r"(r0), "r"(r1), "r"(r2), "r"(r3) : "memory");
}

// ---------------------------------------------------------------------------
// prep kernels
// ---------------------------------------------------------------------------
__global__ __launch_bounds__(256) void transpose_f16(const float* __restrict__ W,
                                                     __half* __restrict__ T,
                                                     int K, int N) {
    __shared__ float t[32][33];
    int tx = threadIdx.x, ty = threadIdx.y;
    int n0 = blockIdx.x * 32, k0 = blockIdx.y * 32;
#pragma unroll
    for (int i = 0; i < 4; i++)
        t[ty + 8 * i][tx] = W[(size_t)(k0 + ty + 8 * i) * N + n0 + tx];
    __syncthreads();
#pragma unroll
    for (int i = 0; i < 4; i++)
        T[(size_t)(n0 + ty + 8 * i) * K + k0 + tx] = __float2half(t[tx][ty + 8 * i]);
}

__global__ __launch_bounds__(256) void split_x(const float* __restrict__ src,
                                               __half* __restrict__ hi,
                                               __half* __restrict__ lo, int n4) {
    int i = blockIdx.x * blockDim.x + threadIdx.x;
    if (i >= n4) return;
    float4 v = ((const float4*)src)[i];
    float f[4] = {v.x, v.y, v.z, v.w};
    __half h[4], l[4];
#pragma unroll
    for (int j = 0; j < 4; j++) {
        h[j] = __float2half(f[j]);
        l[j] = __float2half(f[j] - __half2float(h[j]));
    }
    ((uint2*)hi)[i] = *(uint2*)h;
    ((uint2*)lo)[i] = *(uint2*)l;
}

// ---------------------------------------------------------------------------
// GEMM with A hi/lo split: C[M,N] fp32 = (Ahi+Alo)[M,K]h @ Bt[N,K]h^T
// Block 128x128, BK=64, 2-stage cp.async, ldmatrix fragments. 256 thr.
// smem stride 72 halfs (144B = 9x16B): ldmatrix banks 4r%32 -> conflict-free.
// ---------------------------------------------------------------------------
#define GSS 72
#define GS_TILE  (128 * GSS)
#define GS_STAGE (3 * GS_TILE)
#define GEMM_SMEM_BYTES (2 * GS_STAGE * 2)

__global__ __launch_bounds__(256, 2) void gemm_asplit(
    const __half* __restrict__ Ahi, const __half* __restrict__ Alo,
    const __half* __restrict__ Bt, float* __restrict__ C, int N, int K) {
    extern __shared__ __half gsm[];
    const uint32_t sb = (uint32_t)__cvta_generic_to_shared(gsm);
    const int tid = threadIdx.x, wid = tid >> 5, lane = tid & 31;
    const int gr = lane >> 2, qc = lane & 3;
    const int bm = blockIdx.y * 128, bn = blockIdx.x * 128;
    const int wm = (wid & 3) * 32, wn = (wid >> 2) * 64;
    const int T = K >> 6;

    float acc[2][8][4];
#pragma unroll
    for (int mt = 0; mt < 2; mt++)
#pragma unroll
        for (int nt = 0; nt < 8; nt++)
#pragma unroll
            for (int i = 0; i < 4; i++) acc[mt][nt][i] = 0.f;

    // each tile = 128 rows x 64 halfs = 1024 x 16B chunks
    auto load_chunk = [&](int t) {
        const int k0 = t * 64;
        const uint32_t stage = (t & 1) ? (uint32_t)GS_STAGE : 0u;
#pragma unroll
        for (int tile = 0; tile < 3; tile++) {
            const __half* g = (tile == 0) ? Ahi : (tile == 1) ? Alo : Bt;
            const int gbase = (tile == 2) ? bn : bm;
#pragma unroll
            for (int i = 0; i < 4; i++) {
                int idx = tid + 256 * i;
                int r = idx >> 3, c = idx & 7;
                cpa16(sb + (stage + tile * GS_TILE + r * GSS + c * 8) * 2,
                      g + (size_t)(gbase + r) * K + k0 + c * 8);
            }
        }
    };

    load_chunk(0);
    CP_COMMIT();

    for (int t = 0; t < T; t++) {
        if (t + 1 < T) { load_chunk(t + 1); CP_COMMIT(); CP_WAIT(1); }
        else           { CP_WAIT(0); }
        __syncthreads();
        const uint32_t stage = (t & 1) ? (uint32_t)GS_STAGE : 0u;

#pragma unroll
        for (int kk = 0; kk < 4; kk++) {
            uint32_t b[8][2];
#pragma unroll
            for (int ntp = 0; ntp < 4; ntp++) {
                int row = wn + ntp * 16 + (lane & 7) + ((lane >> 4) & 1) * 8;
                int col = kk * 16 + ((lane >> 3) & 1) * 8;
                ldsm4(b[2 * ntp][0], b[2 * ntp][1], b[2 * ntp + 1][0], b[2 * ntp + 1][1],
                      sb + (stage + 2 * GS_TILE + row * GSS + col) * 2);
            }
#pragma unroll
            for (int sp = 0; sp < 2; sp++) {
                uint32_t a[2][4];
#pragma unroll
                for (int mt = 0; mt < 2; mt++) {
                    int row = wm + mt * 16 + (lane & 15);
                    int col = kk * 16 + (lane >> 4) * 8;
                    ldsm4(a[mt][0], a[mt][1], a[mt][2], a[mt][3],
                          sb + (stage + sp * GS_TILE + row * GSS + col) * 2);
                }
#pragma unroll
                for (int mt = 0; mt < 2; mt++)
#pragma unroll
                    for (int nt = 0; nt < 8; nt++)
                        mma_f16(acc[mt][nt], a[mt], b[nt]);
            }
        }
        __syncthreads();
    }

#pragma unroll
    for (int mt = 0; mt < 2; mt++) {
        int r = bm + wm + mt * 16 + gr;
#pragma unroll
        for (int nt = 0; nt < 8; nt++) {
            int c = bn + wn + nt * 8 + 2 * qc;
            *(float2*)(C + (size_t)r * N + c)       = make_float2(acc[mt][nt][0], acc[mt][nt][1]);
            *(float2*)(C + (size_t)(r + 8) * N + c) = make_float2(acc[mt][nt][2], acc[mt][nt][3]);
        }
    }
}

// ---------------------------------------------------------------------------
// RoPE + fp16 conversion into per-head planes
// ---------------------------------------------------------------------------
__global__ __launch_bounds__(256) void rope_convert(const float* __restrict__ qkv,
                                                    __half* __restrict__ Qh,
                                                    __half* __restrict__ Kh,
                                                    __half* __restrict__ Vh) {
    __shared__ float cs[64], sn[64];
    const int pos = blockIdx.x, tid = threadIdx.x;
    if (tid < 64) {
        double inv = exp(-(double)tid * (log(10000.0) / 64.0));
        double s, c;
        sincos((double)pos * inv, &s, &c);
        cs[tid] = (float)c;
        sn[tid] = (float)s;
    }
    __syncthreads();
    const float* row = qkv + (size_t)pos * NQKV;
#pragma unroll
    for (int it = 0; it < 4; it++) {            // Q: 1024 pairs, scaled
        int p = tid + it * 256;
        int head = p >> 6, d = p & 63;
        float c = cs[d], s = sn[d];
        const float* base = row + head * HDIM;
        float xr = base[d], xi = base[d + 64];
        __half* o = Qh + (size_t)head * SEQ * HDIM + (size_t)pos * HDIM;
        o[d]      = __float2half((xr * c - xi * s) * SCALE);
        o[d + 64] = __float2half((xr * s + xi * c) * SCALE);
    }
    {                                            // K: 256 pairs
        int kvh = tid >> 6, d = tid & 63;
        float c = cs[d], s = sn[d];
        const float* base = row + 2048 + kvh * HDIM;
        float xr = base[d], xi = base[d + 64];
        __half* o = Kh + (size_t)kvh * SEQ * HDIM + (size_t)pos * HDIM;
        o[d]      = __float2half(xr * c - xi * s);
        o[d + 64] = __float2half(xr * s + xi * c);
    }
#pragma unroll
    for (int j = 0; j < 2; j++) {                // V: 512 values
        int e = tid * 2 + j;
        int kvh = e >> 7, d = e & 127;
        Vh[(size_t)kvh * SEQ * HDIM + (size_t)pos * HDIM + d] =
            __float2half(row[2560 + e]);
    }
}

// ---------------------------------------------------------------------------
// Flash attention: 64q x 128kv tiles (32 iters), 256 thr, ldmatrix/stmatrix,
// cp.async double-buffered K/V. Writes AOhi/AOlo fp16 split directly.
// smem stride 136 halfs (272B = 17x16B): all LDSM patterns conflict-free.
// LOADER INVARIANT: threads*iters*16B == rows*256B  (row = 128 halfs = 16 chunks)
//   Q:   64 rows -> 1024 chunks -> i<4, r=lin>>4, c=lin&15
//   K/V: 128 rows -> 2048 chunks -> i<8, r=lin>>4, c=lin&15
// ---------------------------------------------------------------------------
#define AST 136
#define KVT 128
#define NIT (SEQ / KVT)                 // 32
#define AS_Q  0                         // 64 x 136
#define AS_K  (64 * AST)                // 2 x 128 x 136
#define AS_V  (AS_K + 2 * KVT * AST)    // 2 x 128 x 136
#define AS_P  (AS_V + 2 * KVT * AST)    // 64 x 136
#define AS_ST (AS_P + 64 * AST)
#define ATTN_SMEM_BYTES (AS_ST * 2 + 3 * 64 * 4)

__global__ __launch_bounds__(256, 1) void attn3(const __half* __restrict__ Qh,
                                                const __half* __restrict__ Kh,
                                                const __half* __restrict__ Vh,
                                                __half* __restrict__ AOhi,
                                                __half* __restrict__ AOlo) {
    extern __shared__ __half smh[];
    const uint32_t sb = (uint32_t)__cvta_generic_to_shared(smh);
    float* ms  = (float*)(smh + AS_ST);
    float* ls  = ms + 64;
    float* als = ls + 64;

    const int tid = threadIdx.x, wid = tid >> 5, lane = tid & 31;
    const int gr = lane >> 2, qc = lane & 3;
    const int q0 = blockIdx.x * 64;
    const int h  = blockIdx.y;
    const int kvh = h >> 2;
    const int wm16 = (wid & 3) * 16;     // warp q-row base (4-way m split)
    const int wn   = (wid >> 2) * 64;    // warp col base (2-way n split, 128 cols)
    const int srow = tid >> 2;
    const int sseg = (tid & 3) * 32;

    const __half* Kp = Kh + (size_t)kvh * SEQ * HDIM;
    const __half* Vp = Vh + (size_t)kvh * SEQ * HDIM;

    // prologue: Q tile (64x128: 1024 chunks) + K0/V0 (128x128: 2048 chunks each)
    {
        const __half* Qp = Qh + (size_t)h * SEQ * HDIM + (size_t)q0 * HDIM;
#pragma unroll
        for (int i = 0; i < 4; i++) {
            int lin = tid + 256 * i;
            int r = lin >> 4, c = lin & 15;
            cpa16(sb + (AS_Q + r * AST + c * 8) * 2, Qp + (size_t)r * HDIM + c * 8);
        }
#pragma unroll
        for (int i = 0; i < 8; i++) {
            int lin = tid + 256 * i;
            int r = lin >> 4, c = lin & 15;
            cpa16(sb + (AS_K + r * AST + c * 8) * 2, Kp + (size_t)r * HDIM + c * 8);
            cpa16(sb + (AS_V + r * AST + c * 8) * 2, Vp + (size_t)r * HDIM + c * 8);
        }
        CP_COMMIT();
    }
    if (tid < 64) { ms[tid] = -INFINITY; ls[tid] = 0.f; }

    float o[8][4];
#pragma unroll
    for (int nt = 0; nt < 8; nt++)
#pragma unroll
        for (int i = 0; i < 4; i++) o[nt][i] = 0.f;

    for (int t = 0; t < NIT; t++) {
        if (t + 1 < NIT) {
            const int k1 = (t + 1) * KVT, buf = (t + 1) & 1;
#pragma unroll
            for (int i = 0; i < 8; i++) {
                int lin = tid + 256 * i;
                int r = lin >> 4, c = lin & 15;
                cpa16(sb + (AS_K + buf * KVT * AST + r * AST + c * 8) * 2,
                      Kp + (size_t)(k1 + r) * HDIM + c * 8);
                cpa16(sb + (AS_V + buf * KVT * AST + r * AST + c * 8) * 2,
                      Vp + (size_t)(k1 + r) * HDIM + c * 8);
            }
            CP_COMMIT();
            CP_WAIT(1);
        } else {
            CP_WAIT(0);
        }
        __syncthreads();
        const uint32_t kbase = AS_K + (uint32_t)(t & 1) * KVT * AST;
        const uint32_t vbase = AS_V + (uint32_t)(t & 1) * KVT * AST;

        // ---- scores: S[64,128] = Q @ K^T (warp: 16q x 64k) ----
        float s[8][4];
#pragma unroll
        for (int nt = 0; nt < 8; nt++)
#pragma unroll
            for (int i = 0; i < 4; i++) s[nt][i] = 0.f;

#pragma unroll
        for (int kk = 0; kk < 8; kk++) {
            uint32_t a[4], b[8][2];
            {
                int row = wm16 + (lane & 15);
                int col = kk * 16 + (lane >> 4) * 8;
                ldsm4(a[0], a[1], a[2], a[3], sb + (AS_Q + row * AST + col) * 2);
            }
#pragma unroll
            for (int ntp = 0; ntp < 4; ntp++) {
                int row = wn + ntp * 16 + (lane & 7) + ((lane >> 4) & 1) * 8;
                int col = kk * 16 + ((lane >> 3) & 1) * 8;
                ldsm4(b[2 * ntp][0], b[2 * ntp][1], b[2 * ntp + 1][0], b[2 * ntp + 1][1],
                      sb + (kbase + row * AST + col) * 2);
            }
#pragma unroll
            for (int nt = 0; nt < 8; nt++)
                mma_f16(s[nt], a, b[nt]);
        }
        // P writeback via stmatrix (4 x4 per warp, 16 rows x 64 cols)
#pragma unroll
        for (int ntp = 0; ntp < 4; ntp++) {
            int tl = lane >> 3;
            int g2 = tl & 1, ntl = ntp * 2 + (tl >> 1);
            int row = wm16 + 8 * g2 + (lane & 7);
            int col = wn + 8 * ntl;
            stsm4(sb + (AS_P + row * AST + col) * 2,
                  pack_h2(s[2 * ntp][0], s[2 * ntp][1]),
                  pack_h2(s[2 * ntp][2], s[2 * ntp][3]),
                  pack_h2(s[2 * ntp + 1][0], s[2 * ntp + 1][1]),
                  pack_h2(s[2 * ntp + 1][2], s[2 * ntp + 1][3]));
        }
        __syncthreads();

        // ---- online softmax (4 threads/row x 32 cols, fp32 stats) ----
        {
            __half2* prow = (__half2*)(smh + AS_P + srow * AST + sseg);
            float pv[32];
            float mloc = -INFINITY;
#pragma unroll
            for (int j = 0; j < 16; j++) {
                float2 f = __half22float2(prow[j]);
                pv[2 * j] = f.x; pv[2 * j + 1] = f.y;
                mloc = fmaxf(mloc, fmaxf(f.x, f.y));
            }
            mloc = fmaxf(mloc, __shfl_xor_sync(0xffffffffu, mloc, 1));
            mloc = fmaxf(mloc, __shfl_xor_sync(0xffffffffu, mloc, 2));
            float mold = ms[srow];
            float mnew = fmaxf(mold, mloc);
            float sum = 0.f;
#pragma unroll
            for (int j = 0; j < 16; j++) {
                float e0 = __expf(pv[2 * j] - mnew);
                float e1 = __expf(pv[2 * j + 1] - mnew);
                prow[j] = __floats2half2_rn(e0, e1);
                sum += e0 + e1;
            }
            sum += __shfl_xor_sync(0xffffffffu, sum, 1);
            sum += __shfl_xor_sync(0xffffffffu, sum, 2);
            if ((tid & 3) == 0) {
                float a = __expf(mold - mnew);
                als[srow] = a;
                ms[srow] = mnew;
                ls[srow] = ls[srow] * a + sum;
            }
        }
        __syncthreads();

        // ---- rescale, then O[64,128] += P[64,128] @ V[128,128] ----
        {
            float a_lo = als[wm16 + gr];
            float a_hi = als[wm16 + gr + 8];
#pragma unroll
            for (int nt = 0; nt < 8; nt++) {
                o[nt][0] *= a_lo; o[nt][1] *= a_lo;
                o[nt][2] *= a_hi; o[nt][3] *= a_hi;
            }
        }
#pragma unroll
        for (int kk = 0; kk < 8; kk++) {
            uint32_t a[4];
            {
                int row = wm16 + (lane & 15);
                int col = kk * 16 + (lane >> 4) * 8;
                ldsm4(a[0], a[1], a[2], a[3], sb + (AS_P + row * AST + col) * 2);
            }
            const int vrow = kk * 16 + (lane & 7) + ((lane >> 4) << 3);
#pragma unroll
            for (int nt2 = 0; nt2 < 4; nt2++) {
                int vcol = wn + nt2 * 16 + ((lane >> 3) & 1) * 8;
                uint32_t r0, r1, r2, r3;
                ldsm4t(r0, r1, r2, r3, sb + (vbase + vrow * AST + vcol) * 2);
                uint32_t b0[2] = {r0, r2};
                uint32_t b1[2] = {r1, r3};
                mma_f16(o[nt2 * 2],     a, b0);
                mma_f16(o[nt2 * 2 + 1], a, b1);
            }
        }
        __syncthreads();
    }

    // ---- finalize: divide by l, hi/lo split store ----
    {
        int r = wm16 + gr;
        float inv_lo = 1.f / ls[r];
        float inv_hi = 1.f / ls[r + 8];
#pragma unroll
        for (int nt = 0; nt < 8; nt++) {
            int c = wn + nt * 8 + 2 * qc;
            size_t o0 = (size_t)(q0 + r) * DMODEL + h * HDIM + c;
            size_t o1 = (size_t)(q0 + r + 8) * DMODEL + h * HDIM + c;
            float v00 = o[nt][0] * inv_lo, v01 = o[nt][1] * inv_lo;
            float v10 = o[nt][2] * inv_hi, v11 = o[nt][3] * inv_hi;
            __half h00 = __float2half(v00), h01 = __float2half(v01);
            __half h10 = __float2half(v10), h11 = __float2half(v11);
            *(uint32_t*)(AOhi + o0) = pack_h2(__half2float(h00), __half2float(h01));
            *(uint32_t*)(AOhi + o1) = pack_h2(__half2float(h10), __half2float(h11));
            *(uint32_t*)(AOlo + o0) = pack_h2(v00 - __half2float(h00), v01 - __half2float(h01));
            *(uint32_t*)(AOlo + o1) = pack_h2(v10 - __half2float(h10), v11 - __half2float(h11));
        }
    }
}

// ---------------------------------------------------------------------------
// launch
// ---------------------------------------------------------------------------
extern "C" void kernel_launch(void* const* d_in, const int* in_sizes, int n_in,
                              void* d_out, int out_size) {
    (void)in_sizes; (void)n_in; (void)out_size;
    const float* X  = (const float*)d_in[0];
    const float* Wq = (const float*)d_in[1];
    const float* Wk = (const float*)d_in[2];
    const float* Wv = (const float*)d_in[3];
    const float* Wo = (const float*)d_in[4];
    float* out = (float*)d_out;

    float* QKVp;
    __half *Wt, *Wot, *Xhi, *Xlo, *Qh, *Kh, *Vh, *AOhi, *AOlo;
    cudaGetSymbolAddress((void**)&QKVp, g_QKV);
    cudaGetSymbolAddress((void**)&Wt, g_Wt);
    cudaGetSymbolAddress((void**)&Wot, g_Wot);
    cudaGetSymbolAddress((void**)&Xhi, g_Xhi);
    cudaGetSymbolAddress((void**)&Xlo, g_Xlo);
    cudaGetSymbolAddress((void**)&Qh, g_Qh);
    cudaGetSymbolAddress((void**)&Kh, g_Kh);
    cudaGetSymbolAddress((void**)&Vh, g_Vh);
    cudaGetSymbolAddress((void**)&AOhi, g_AOhi);
    cudaGetSymbolAddress((void**)&AOlo, g_AOlo);

    cudaFuncSetAttribute(gemm_asplit, cudaFuncAttributeMaxDynamicSharedMemorySize,
                         GEMM_SMEM_BYTES);
    cudaFuncSetAttribute(attn3, cudaFuncAttributeMaxDynamicSharedMemorySize,
                         ATTN_SMEM_BYTES);

    // 1) weight transposes + X split
    transpose_f16<<<dim3(64, 64), dim3(32, 8)>>>(Wq, Wt, DMODEL, 2048);
    transpose_f16<<<dim3(16, 64), dim3(32, 8)>>>(Wk, Wt + 2048 * DMODEL, DMODEL, 512);
    transpose_f16<<<dim3(16, 64), dim3(32, 8)>>>(Wv, Wt + 2560 * DMODEL, DMODEL, 512);
    transpose_f16<<<dim3(64, 64), dim3(32, 8)>>>(Wo, Wot, DMODEL, 2048);
    split_x<<<SEQ * DMODEL / 4 / 256, 256>>>(X, Xhi, Xlo, SEQ * DMODEL / 4);

    // 2) fused QKV projection (A-split fp16 tensor path)
    gemm_asplit<<<dim3(NQKV / 128, SEQ / 128), 256, GEMM_SMEM_BYTES>>>(
        Xhi, Xlo, Wt, QKVp, NQKV, DMODEL);

    // 3) RoPE + per-head fp16 planes
    rope_convert<<<SEQ, 256>>>(QKVp, Qh, Kh, Vh);

    // 4) attention (64q x 128kv tiles; writes AO hi/lo split)
    attn3<<<dim3(SEQ / 64, NHEAD), 256, ATTN_SMEM_BYTES>>>(Qh, Kh, Vh, AOhi, AOlo);

    // 5) output projection (A-split exact)
    gemm_asplit<<<dim3(DMODEL / 128, SEQ / 128), 256, GEMM_SMEM_BYTES>>>(
        AOhi, AOlo, Wot, out, DMODEL, DMODEL);
}

// round 9
// speedup vs baseline: 1.2975x; 1.2975x over previous
#include <cuda_runtime.h>
#include <cuda_fp16.h>
#include <math.h>
#include <stdint.h>

// Problem constants
#define SEQ    4096
#define DMODEL 2048
#define NHEAD  16
#define NKV    4
#define HDIM   128
#define NQKV   3072
#define SCALE  0.08838834764831845f   // 1/sqrt(128)

// ---------------------------------------------------------------------------
// Scratch (device globals; no allocation allowed)
// ---------------------------------------------------------------------------
__device__ float  g_QKV[SEQ * NQKV];          // fused Q|K|V fp32 (gemm out)
__device__ __half g_Wt[NQKV * DMODEL];        // fused Wq|Wk|Wv transposed [N,K]
__device__ __half g_Wot[DMODEL * DMODEL];     // Wo transposed [N,K]
__device__ __half g_Xh[SEQ * DMODEL];         // X fp16
__device__ __half g_Qh[NHEAD * SEQ * HDIM];   // per-head planes, rope+scale
__device__ __half g_Kh[NKV * SEQ * HDIM];     // rope applied
__device__ __half g_Vh[NKV * SEQ * HDIM];
__device__ __half g_AOh[SEQ * DMODEL];        // attention out fp16

// ---------------------------------------------------------------------------
// helpers
// ---------------------------------------------------------------------------
__device__ __forceinline__ void mma_f16(float c[4], const uint32_t a[4], const uint32_t b[2]) {
    asm volatile(
        "mma.sync.aligned.m16n8k16.row.col.f32.f16.f16.f32 "
        "{%0,%1,%2,%3}, {%4,%5,%6,%7}, {%8,%9}, {%0,%1,%2,%3};\n"
        : "+f"(c[0]), "+f"(c[1]), "+f"(c[2]), "+f"(c[3])
        : "r"(a[0]), "r"(a[1]), "r"(a[2]), "r"(a[3]), "r"(b[0]), "r"(b[1]));
}

__device__ __forceinline__ uint32_t pack_h2(float x, float y) {
    __half2 h = __floats2half2_rn(x, y);
    return *(uint32_t*)&h;
}

__device__ __forceinline__ void cpa16(uint32_t saddr, const void* g) {
    asm volatile("cp.async.cg.shared.global [%0], [%1], 16;" :: "r"(saddr), "l"(g));
}
#define CP_COMMIT() asm volatile("cp.async.commit_group;" ::: "memory")
#define CP_WAIT(n)  asm volatile("cp.async.wait_group %0;" :: "n"(n) : "memory")

__device__ __forceinline__ void ldsm4(uint32_t& r0, uint32_t& r1, uint32_t& r2, uint32_t& r3,
                                      uint32_t addr) {
    asm volatile("ldmatrix.sync.aligned.m8n8.x4.shared.b16 {%0,%1,%2,%3}, [%4];"
                 : "=r"(r0), "=r"(r1), "=r"(r2), "=r"(r3) : "r"(addr));
}
__device__ __forceinline__ void ldsm4t(uint32_t& r0, uint32_t& r1, uint32_t& r2, uint32_t& r3,
                                       uint32_t addr) {
    asm volatile("ldmatrix.sync.aligned.m8n8.x4.trans.shared.b16 {%0,%1,%2,%3}, [%4];"
                 : "=r"(r0), "=r"(r1), "=r"(r2), "=r"(r3) : "r"(addr));
}
__device__ __forceinline__ void stsm4(uint32_t addr, uint32_t r0, uint32_t r1,
                                      uint32_t r2, uint32_t r3) {
    asm volatile("stmatrix.sync.aligned.m8n8.x4.shared.b16 [%0], {%1,%2,%3,%4};"
                 :: "r"(addr), "r"(r0), "r"(r1), "r"(r2), "r"(r3) : "memory");
}

// ---------------------------------------------------------------------------
// prep kernels
// ---------------------------------------------------------------------------
__global__ __launch_bounds__(256) void transpose_f16(const float* __restrict__ W,
                                                     __half* __restrict__ T,
                                                     int K, int N) {
    __shared__ float t[32][33];
    int tx = threadIdx.x, ty = threadIdx.y;
    int n0 = blockIdx.x * 32, k0 = blockIdx.y * 32;
#pragma unroll
    for (int i = 0; i < 4; i++)
        t[ty + 8 * i][tx] = W[(size_t)(k0 + ty + 8 * i) * N + n0 + tx];
    __syncthreads();
#pragma unroll
    for (int i = 0; i < 4; i++)
        T[(size_t)(n0 + ty + 8 * i) * K + k0 + tx] = __float2half(t[tx][ty + 8 * i]);
}

__global__ __launch_bounds__(256) void convert_f16(const float* __restrict__ src,
                                                   __half* __restrict__ dst, int n4) {
    int i = blockIdx.x * blockDim.x + threadIdx.x;
    if (i >= n4) return;
    float4 v = ((const float4*)src)[i];
    uint2 p;
    p.x = pack_h2(v.x, v.y);
    p.y = pack_h2(v.z, v.w);
    ((uint2*)dst)[i] = p;
}

// ---------------------------------------------------------------------------
// fp16 GEMM (no split): C[M,N] fp32 = A[M,K]h @ Bt[N,K]h^T
// Block 128x128, BK=64, 2-stage cp.async, ldmatrix fragments. 256 thr, occ 2.
// smem stride 72 halfs (144B = 9x16B): ldmatrix banks 4r%32 -> conflict-free.
// ---------------------------------------------------------------------------
#define GSS 72
#define GS_TILE  (128 * GSS)
#define GS_STAGE (2 * GS_TILE)
#define GEMM_SMEM_BYTES (2 * GS_STAGE * 2)

__global__ __launch_bounds__(256, 2) void gemm_f16(
    const __half* __restrict__ A, const __half* __restrict__ Bt,
    float* __restrict__ C, int N, int K) {
    extern __shared__ __half gsm[];
    const uint32_t sb = (uint32_t)__cvta_generic_to_shared(gsm);
    const int tid = threadIdx.x, wid = tid >> 5, lane = tid & 31;
    const int gr = lane >> 2, qc = lane & 3;
    const int bm = blockIdx.y * 128, bn = blockIdx.x * 128;
    const int wm = (wid & 3) * 32, wn = (wid >> 2) * 64;
    const int T = K >> 6;

    float acc[2][8][4];
#pragma unroll
    for (int mt = 0; mt < 2; mt++)
#pragma unroll
        for (int nt = 0; nt < 8; nt++)
#pragma unroll
            for (int i = 0; i < 4; i++) acc[mt][nt][i] = 0.f;

    // each tile = 128 rows x 64 halfs = 1024 x 16B chunks (8 per row)
    auto load_chunk = [&](int t) {
        const int k0 = t * 64;
        const uint32_t stage = (t & 1) ? (uint32_t)GS_STAGE : 0u;
#pragma unroll
        for (int tile = 0; tile < 2; tile++) {
            const __half* g = (tile == 0) ? A : Bt;
            const int gbase = (tile == 0) ? bm : bn;
#pragma unroll
            for (int i = 0; i < 4; i++) {
                int idx = tid + 256 * i;
                int r = idx >> 3, c = idx & 7;
                cpa16(sb + (stage + tile * GS_TILE + r * GSS + c * 8) * 2,
                      g + (size_t)(gbase + r) * K + k0 + c * 8);
            }
        }
    };

    load_chunk(0);
    CP_COMMIT();

    for (int t = 0; t < T; t++) {
        if (t + 1 < T) { load_chunk(t + 1); CP_COMMIT(); CP_WAIT(1); }
        else           { CP_WAIT(0); }
        __syncthreads();
        const uint32_t stage = (t & 1) ? (uint32_t)GS_STAGE : 0u;

#pragma unroll
        for (int kk = 0; kk < 4; kk++) {
            uint32_t b[8][2];
#pragma unroll
            for (int ntp = 0; ntp < 4; ntp++) {
                int row = wn + ntp * 16 + (lane & 7) + ((lane >> 4) & 1) * 8;
                int col = kk * 16 + ((lane >> 3) & 1) * 8;
                ldsm4(b[2 * ntp][0], b[2 * ntp][1], b[2 * ntp + 1][0], b[2 * ntp + 1][1],
                      sb + (stage + GS_TILE + row * GSS + col) * 2);
            }
            uint32_t a[2][4];
#pragma unroll
            for (int mt = 0; mt < 2; mt++) {
                int row = wm + mt * 16 + (lane & 15);
                int col = kk * 16 + (lane >> 4) * 8;
                ldsm4(a[mt][0], a[mt][1], a[mt][2], a[mt][3],
                      sb + (stage + row * GSS + col) * 2);
            }
#pragma unroll
            for (int mt = 0; mt < 2; mt++)
#pragma unroll
                for (int nt = 0; nt < 8; nt++)
                    mma_f16(acc[mt][nt], a[mt], b[nt]);
        }
        __syncthreads();
    }

#pragma unroll
    for (int mt = 0; mt < 2; mt++) {
        int r = bm + wm + mt * 16 + gr;
#pragma unroll
        for (int nt = 0; nt < 8; nt++) {
            int c = bn + wn + nt * 8 + 2 * qc;
            *(float2*)(C + (size_t)r * N + c)       = make_float2(acc[mt][nt][0], acc[mt][nt][1]);
            *(float2*)(C + (size_t)(r + 8) * N + c) = make_float2(acc[mt][nt][2], acc[mt][nt][3]);
        }
    }
}

// ---------------------------------------------------------------------------
// RoPE + fp16 conversion into per-head planes
// ---------------------------------------------------------------------------
__global__ __launch_bounds__(256) void rope_convert(const float* __restrict__ qkv,
                                                    __half* __restrict__ Qh,
                                                    __half* __restrict__ Kh,
                                                    __half* __restrict__ Vh) {
    __shared__ float cs[64], sn[64];
    const int pos = blockIdx.x, tid = threadIdx.x;
    if (tid < 64) {
        double inv = exp(-(double)tid * (log(10000.0) / 64.0));
        double s, c;
        sincos((double)pos * inv, &s, &c);
        cs[tid] = (float)c;
        sn[tid] = (float)s;
    }
    __syncthreads();
    const float* row = qkv + (size_t)pos * NQKV;
#pragma unroll
    for (int it = 0; it < 4; it++) {            // Q: 1024 pairs, scaled
        int p = tid + it * 256;
        int head = p >> 6, d = p & 63;
        float c = cs[d], s = sn[d];
        const float* base = row + head * HDIM;
        float xr = base[d], xi = base[d + 64];
        __half* o = Qh + (size_t)head * SEQ * HDIM + (size_t)pos * HDIM;
        o[d]      = __float2half((xr * c - xi * s) * SCALE);
        o[d + 64] = __float2half((xr * s + xi * c) * SCALE);
    }
    {                                            // K: 256 pairs
        int kvh = tid >> 6, d = tid & 63;
        float c = cs[d], s = sn[d];
        const float* base = row + 2048 + kvh * HDIM;
        float xr = base[d], xi = base[d + 64];
        __half* o = Kh + (size_t)kvh * SEQ * HDIM + (size_t)pos * HDIM;
        o[d]      = __float2half(xr * c - xi * s);
        o[d + 64] = __float2half(xr * s + xi * c);
    }
#pragma unroll
    for (int j = 0; j < 2; j++) {                // V: 512 values
        int e = tid * 2 + j;
        int kvh = e >> 7, d = e & 127;
        Vh[(size_t)kvh * SEQ * HDIM + (size_t)pos * HDIM + d] =
            __float2half(row[2560 + e]);
    }
}

// ---------------------------------------------------------------------------
// Flash attention: 64q x 64kv tiles (round-6 proven config, occ 2), 256 thr,
// fp16 ldmatrix everywhere, cp.async double-buffered K/V. Writes AOh fp16.
// smem stride 136 halfs (272B = 17x16B): all LDSM patterns conflict-free.
// LOADER INVARIANT: 64 rows x 256B = 1024 x 16B chunks -> i<4, r=lin>>4, c=lin&15
// ---------------------------------------------------------------------------
#define AST 136
#define APS 72
#define AS_Q  0
#define AS_K  (64 * AST)          // 2 buffers
#define AS_V  (64 * AST * 3)      // 2 buffers
#define AS_P  (64 * AST * 5)
#define AS_ST (AS_P + 64 * APS)   // fp32 stats after this (half offset)
#define ATTN_SMEM_BYTES (AS_ST * 2 + 3 * 64 * 4)

__global__ __launch_bounds__(256, 2) void attn2(const __half* __restrict__ Qh,
                                                const __half* __restrict__ Kh,
                                                const __half* __restrict__ Vh,
                                                __half* __restrict__ AOh) {
    extern __shared__ __half smh[];
    const uint32_t sb = (uint32_t)__cvta_generic_to_shared(smh);
    float* ms  = (float*)(smh + AS_ST);
    float* ls  = ms + 64;
    float* als = ls + 64;

    const int tid = threadIdx.x, wid = tid >> 5, lane = tid & 31;
    const int gr = lane >> 2, qc = lane & 3;
    const int q0 = blockIdx.x * 64;
    const int h  = blockIdx.y;
    const int kvh = h >> 2;
    const int wm16 = (wid & 3) * 16;
    const int wn32 = (wid >> 2) * 32;
    const int wn64 = (wid >> 2) * 64;
    const int srow = tid >> 2;
    const int sseg = (tid & 3) * 16;

    const __half* Kp = Kh + (size_t)kvh * SEQ * HDIM;
    const __half* Vp = Vh + (size_t)kvh * SEQ * HDIM;

    // prologue: Q tile + K0/V0 in one commit group
    {
        const __half* Qp = Qh + (size_t)h * SEQ * HDIM + (size_t)q0 * HDIM;
#pragma unroll
        for (int i = 0; i < 4; i++) {
            int lin = tid + 256 * i;
            int r = lin >> 4, c = lin & 15;
            cpa16(sb + (AS_Q + r * AST + c * 8) * 2, Qp + (size_t)r * HDIM + c * 8);
            cpa16(sb + (AS_K + r * AST + c * 8) * 2, Kp + (size_t)r * HDIM + c * 8);
            cpa16(sb + (AS_V + r * AST + c * 8) * 2, Vp + (size_t)r * HDIM + c * 8);
        }
        CP_COMMIT();
    }
    if (tid < 64) { ms[tid] = -INFINITY; ls[tid] = 0.f; }

    float o[8][4];
#pragma unroll
    for (int nt = 0; nt < 8; nt++)
#pragma unroll
        for (int i = 0; i < 4; i++) o[nt][i] = 0.f;

    for (int t = 0; t < 64; t++) {
        if (t + 1 < 64) {
            const int k1 = (t + 1) * 64, buf = (t + 1) & 1;
#pragma unroll
            for (int i = 0; i < 4; i++) {
                int lin = tid + 256 * i;
                int r = lin >> 4, c = lin & 15;
                cpa16(sb + (AS_K + buf * 64 * AST + r * AST + c * 8) * 2,
                      Kp + (size_t)(k1 + r) * HDIM + c * 8);
                cpa16(sb + (AS_V + buf * 64 * AST + r * AST + c * 8) * 2,
                      Vp + (size_t)(k1 + r) * HDIM + c * 8);
            }
            CP_COMMIT();
            CP_WAIT(1);
        } else {
            CP_WAIT(0);
        }
        __syncthreads();
        const uint32_t kbase = AS_K + (uint32_t)(t & 1) * 64 * AST;
        const uint32_t vbase = AS_V + (uint32_t)(t & 1) * 64 * AST;

        // ---- scores: S = Q @ K^T (warp 16q x 32k) ----
        float s[4][4];
#pragma unroll
        for (int nt = 0; nt < 4; nt++)
#pragma unroll
            for (int i = 0; i < 4; i++) s[nt][i] = 0.f;

#pragma unroll
        for (int kk = 0; kk < 8; kk++) {
            uint32_t a[4], b[4][2];
            {
                int row = wm16 + (lane & 15);
                int col = kk * 16 + (lane >> 4) * 8;
                ldsm4(a[0], a[1], a[2], a[3], sb + (AS_Q + row * AST + col) * 2);
            }
#pragma unroll
            for (int ntp = 0; ntp < 2; ntp++) {
                int row = wn32 + ntp * 16 + (lane & 7) + ((lane >> 4) & 1) * 8;
                int col = kk * 16 + ((lane >> 3) & 1) * 8;
                ldsm4(b[2 * ntp][0], b[2 * ntp][1], b[2 * ntp + 1][0], b[2 * ntp + 1][1],
                      sb + (kbase + row * AST + col) * 2);
            }
#pragma unroll
            for (int nt = 0; nt < 4; nt++)
                mma_f16(s[nt], a, b[nt]);
        }
        // P writeback via stmatrix (2 x4 per warp)
#pragma unroll
        for (int ntp = 0; ntp < 2; ntp++) {
            int tl = lane >> 3;
            int g2 = tl & 1, ntl = ntp * 2 + (tl >> 1);
            int row = wm16 + 8 * g2 + (lane & 7);
            int col = wn32 + 8 * ntl;
            stsm4(sb + (AS_P + row * APS + col) * 2,
                  pack_h2(s[2 * ntp][0], s[2 * ntp][1]),
                  pack_h2(s[2 * ntp][2], s[2 * ntp][3]),
                  pack_h2(s[2 * ntp + 1][0], s[2 * ntp + 1][1]),
                  pack_h2(s[2 * ntp + 1][2], s[2 * ntp + 1][3]));
        }
        __syncthreads();

        // ---- online softmax (4 threads/row, fp32 stats) ----
        {
            __half2* prow = (__half2*)(smh + AS_P + srow * APS + sseg);
            float pv[16];
            float mloc = -INFINITY;
#pragma unroll
            for (int j = 0; j < 8; j++) {
                float2 f = __half22float2(prow[j]);
                pv[2 * j] = f.x; pv[2 * j + 1] = f.y;
                mloc = fmaxf(mloc, fmaxf(f.x, f.y));
            }
            mloc = fmaxf(mloc, __shfl_xor_sync(0xffffffffu, mloc, 1));
            mloc = fmaxf(mloc, __shfl_xor_sync(0xffffffffu, mloc, 2));
            float mold = ms[srow];
            float mnew = fmaxf(mold, mloc);
            float sum = 0.f;
#pragma unroll
            for (int j = 0; j < 8; j++) {
                float e0 = __expf(pv[2 * j] - mnew);
                float e1 = __expf(pv[2 * j + 1] - mnew);
                prow[j] = __floats2half2_rn(e0, e1);
                sum += e0 + e1;
            }
            sum += __shfl_xor_sync(0xffffffffu, sum, 1);
            sum += __shfl_xor_sync(0xffffffffu, sum, 2);
            if ((tid & 3) == 0) {
                float a = __expf(mold - mnew);
                als[srow] = a;
                ms[srow] = mnew;
                ls[srow] = ls[srow] * a + sum;
            }
        }
        __syncthreads();

        // ---- rescale, then O += P @ V ----
        {
            float a_lo = als[wm16 + gr];
            float a_hi = als[wm16 + gr + 8];
#pragma unroll
            for (int nt = 0; nt < 8; nt++) {
                o[nt][0] *= a_lo; o[nt][1] *= a_lo;
                o[nt][2] *= a_hi; o[nt][3] *= a_hi;
            }
        }
#pragma unroll
        for (int kk = 0; kk < 4; kk++) {
            uint32_t a[4];
            {
                int row = wm16 + (lane & 15);
                int col = kk * 16 + (lane >> 4) * 8;
                ldsm4(a[0], a[1], a[2], a[3], sb + (AS_P + row * APS + col) * 2);
            }
            const int vrow = kk * 16 + (lane & 7) + ((lane >> 4) << 3);
#pragma unroll
            for (int nt2 = 0; nt2 < 4; nt2++) {
                int vcol = wn64 + nt2 * 16 + ((lane >> 3) & 1) * 8;
                uint32_t r0, r1, r2, r3;
                ldsm4t(r0, r1, r2, r3, sb + (vbase + vrow * AST + vcol) * 2);
                uint32_t b0[2] = {r0, r2};
                uint32_t b1[2] = {r1, r3};
                mma_f16(o[nt2 * 2],     a, b0);
                mma_f16(o[nt2 * 2 + 1], a, b1);
            }
        }
        __syncthreads();
    }

    // ---- finalize: divide by l, fp16 store ----
    {
        int r = wm16 + gr;
        float inv_lo = 1.f / ls[r];
        float inv_hi = 1.f / ls[r + 8];
#pragma unroll
        for (int nt = 0; nt < 8; nt++) {
            int c = wn64 + nt * 8 + 2 * qc;
            size_t o0 = (size_t)(q0 + r) * DMODEL + h * HDIM + c;
            size_t o1 = (size_t)(q0 + r + 8) * DMODEL + h * HDIM + c;
            *(uint32_t*)(AOh + o0) = pack_h2(o[nt][0] * inv_lo, o[nt][1] * inv_lo);
            *(uint32_t*)(AOh + o1) = pack_h2(o[nt][2] * inv_hi, o[nt][3] * inv_hi);
        }
    }
}

// ---------------------------------------------------------------------------
// launch
// ---------------------------------------------------------------------------
extern "C" void kernel_launch(void* const* d_in, const int* in_sizes, int n_in,
                              void* d_out, int out_size) {
    (void)in_sizes; (void)n_in; (void)out_size;
    const float* X  = (const float*)d_in[0];
    const float* Wq = (const float*)d_in[1];
    const float* Wk = (const float*)d_in[2];
    const float* Wv = (const float*)d_in[3];
    const float* Wo = (const float*)d_in[4];
    float* out = (float*)d_out;

    float* QKVp;
    __half *Wt, *Wot, *Xh, *Qh, *Kh, *Vh, *AOh;
    cudaGetSymbolAddress((void**)&QKVp, g_QKV);
    cudaGetSymbolAddress((void**)&Wt, g_Wt);
    cudaGetSymbolAddress((void**)&Wot, g_Wot);
    cudaGetSymbolAddress((void**)&Xh, g_Xh);
    cudaGetSymbolAddress((void**)&Qh, g_Qh);
    cudaGetSymbolAddress((void**)&Kh, g_Kh);
    cudaGetSymbolAddress((void**)&Vh, g_Vh);
    cudaGetSymbolAddress((void**)&AOh, g_AOh);

    cudaFuncSetAttribute(gemm_f16, cudaFuncAttributeMaxDynamicSharedMemorySize,
                         GEMM_SMEM_BYTES);
    cudaFuncSetAttribute(attn2, cudaFuncAttributeMaxDynamicSharedMemorySize,
                         ATTN_SMEM_BYTES);

    // 1) weight transposes + X fp16 conversion
    transpose_f16<<<dim3(64, 64), dim3(32, 8)>>>(Wq, Wt, DMODEL, 2048);
    transpose_f16<<<dim3(16, 64), dim3(32, 8)>>>(Wk, Wt + 2048 * DMODEL, DMODEL, 512);
    transpose_f16<<<dim3(16, 64), dim3(32, 8)>>>(Wv, Wt + 2560 * DMODEL, DMODEL, 512);
    transpose_f16<<<dim3(64, 64), dim3(32, 8)>>>(Wo, Wot, DMODEL, 2048);
    convert_f16<<<SEQ * DMODEL / 4 / 256, 256>>>(X, Xh, SEQ * DMODEL / 4);

    // 2) fused QKV projection
    gemm_f16<<<dim3(NQKV / 128, SEQ / 128), 256, GEMM_SMEM_BYTES>>>(
        Xh, Wt, QKVp, NQKV, DMODEL);

    // 3) RoPE + per-head fp16 planes
    rope_convert<<<SEQ, 256>>>(QKVp, Qh, Kh, Vh);

    // 4) attention (round-6 proven 64x64 config; writes AOh fp16)
    attn2<<<dim3(SEQ / 64, NHEAD), 256, ATTN_SMEM_BYTES>>>(Qh, Kh, Vh, AOh);

    // 5) output projection
    gemm_f16<<<dim3(DMODEL / 128, SEQ / 128), 256, GEMM_SMEM_BYTES>>>(
        AOh, Wot, out, DMODEL, DMODEL);
}

// round 10
// speedup vs baseline: 1.2985x; 1.0008x over previous
#include <cuda_runtime.h>
#include <cuda_fp16.h>
#include <math.h>
#include <stdint.h>

// Problem constants
#define SEQ    4096
#define DMODEL 2048
#define NHEAD  16
#define NKV    4
#define HDIM   128
#define NQKV   3072
#define SCALE  0.08838834764831845f   // 1/sqrt(128)

// ---------------------------------------------------------------------------
// Scratch (device globals; no allocation allowed)
// ---------------------------------------------------------------------------
__device__ float  g_QKV[SEQ * NQKV];          // fused Q|K|V fp32 (gemm out)
__device__ __half g_Wt[NQKV * DMODEL];        // fused Wq|Wk|Wv transposed [N,K]
__device__ __half g_Wot[DMODEL * DMODEL];     // Wo transposed [N,K]
__device__ __half g_Xh[SEQ * DMODEL];         // X fp16
__device__ __half g_Qh[NHEAD * SEQ * HDIM];   // per-head planes, rope+scale
__device__ __half g_Kh[NKV * SEQ * HDIM];     // rope applied
__device__ __half g_Vh[NKV * SEQ * HDIM];
__device__ __half g_AOh[SEQ * DMODEL];        // attention out fp16

// ---------------------------------------------------------------------------
// helpers
// ---------------------------------------------------------------------------
__device__ __forceinline__ void mma_f16(float c[4], const uint32_t a[4], const uint32_t b[2]) {
    asm volatile(
        "mma.sync.aligned.m16n8k16.row.col.f32.f16.f16.f32 "
        "{%0,%1,%2,%3}, {%4,%5,%6,%7}, {%8,%9}, {%0,%1,%2,%3};\n"
        : "+f"(c[0]), "+f"(c[1]), "+f"(c[2]), "+f"(c[3])
        : "r"(a[0]), "r"(a[1]), "r"(a[2]), "r"(a[3]), "r"(b[0]), "r"(b[1]));
}

__device__ __forceinline__ uint32_t pack_h2(float x, float y) {
    __half2 h = __floats2half2_rn(x, y);
    return *(uint32_t*)&h;
}

__device__ __forceinline__ void cpa16(uint32_t saddr, const void* g) {
    asm volatile("cp.async.cg.shared.global [%0], [%1], 16;" :: "r"(saddr), "l"(g));
}
#define CP_COMMIT() asm volatile("cp.async.commit_group;" ::: "memory")
#define CP_WAIT(n)  asm volatile("cp.async.wait_group %0;" :: "n"(n) : "memory")

__device__ __forceinline__ void ldsm4(uint32_t& r0, uint32_t& r1, uint32_t& r2, uint32_t& r3,
                                      uint32_t addr) {
    asm volatile("ldmatrix.sync.aligned.m8n8.x4.shared.b16 {%0,%1,%2,%3}, [%4];"
                 : "=r"(r0), "=r"(r1), "=r"(r2), "=r"(r3) : "r"(addr));
}
__device__ __forceinline__ void ldsm4t(uint32_t& r0, uint32_t& r1, uint32_t& r2, uint32_t& r3,
                                       uint32_t addr) {
    asm volatile("ldmatrix.sync.aligned.m8n8.x4.trans.shared.b16 {%0,%1,%2,%3}, [%4];"
                 : "=r"(r0), "=r"(r1), "=r"(r2), "=r"(r3) : "r"(addr));
}
__device__ __forceinline__ void stsm4(uint32_t addr, uint32_t r0, uint32_t r1,
                                      uint32_t r2, uint32_t r3) {
    asm volatile("stmatrix.sync.aligned.m8n8.x4.shared.b16 [%0], {%1,%2,%3,%4};"
                 :: "r"(addr), "r"(r0), "r"(r1), "r"(r2), "r"(r3) : "memory");
}

// ---------------------------------------------------------------------------
// prep kernels
// ---------------------------------------------------------------------------
__global__ __launch_bounds__(256) void transpose_f16(const float* __restrict__ W,
                                                     __half* __restrict__ T,
                                                     int K, int N) {
    __shared__ float t[32][33];
    int tx = threadIdx.x, ty = threadIdx.y;
    int n0 = blockIdx.x * 32, k0 = blockIdx.y * 32;
#pragma unroll
    for (int i = 0; i < 4; i++)
        t[ty + 8 * i][tx] = W[(size_t)(k0 + ty + 8 * i) * N + n0 + tx];
    __syncthreads();
#pragma unroll
    for (int i = 0; i < 4; i++)
        T[(size_t)(n0 + ty + 8 * i) * K + k0 + tx] = __float2half(t[tx][ty + 8 * i]);
}

__global__ __launch_bounds__(256) void convert_f16(const float* __restrict__ src,
                                                   __half* __restrict__ dst, int n4) {
    int i = blockIdx.x * blockDim.x + threadIdx.x;
    if (i >= n4) return;
    float4 v = ((const float4*)src)[i];
    uint2 p;
    p.x = pack_h2(v.x, v.y);
    p.y = pack_h2(v.z, v.w);
    ((uint2*)dst)[i] = p;
}

// ---------------------------------------------------------------------------
// fp16 GEMM (no split): C[M,N] fp32 = A[M,K]h @ Bt[N,K]h^T
// Block 128x128, BK=64, 2-stage cp.async, ldmatrix fragments. 256 thr, occ 2.
// smem stride 72 halfs (144B = 9x16B): ldmatrix banks 4r%32 -> conflict-free.
// ---------------------------------------------------------------------------
#define GSS 72
#define GS_TILE  (128 * GSS)
#define GS_STAGE (2 * GS_TILE)
#define GEMM_SMEM_BYTES (2 * GS_STAGE * 2)

__global__ __launch_bounds__(256, 2) void gemm_f16(
    const __half* __restrict__ A, const __half* __restrict__ Bt,
    float* __restrict__ C, int N, int K) {
    extern __shared__ __half gsm[];
    const uint32_t sb = (uint32_t)__cvta_generic_to_shared(gsm);
    const int tid = threadIdx.x, wid = tid >> 5, lane = tid & 31;
    const int gr = lane >> 2, qc = lane & 3;
    const int bm = blockIdx.y * 128, bn = blockIdx.x * 128;
    const int wm = (wid & 3) * 32, wn = (wid >> 2) * 64;
    const int T = K >> 6;

    float acc[2][8][4];
#pragma unroll
    for (int mt = 0; mt < 2; mt++)
#pragma unroll
        for (int nt = 0; nt < 8; nt++)
#pragma unroll
            for (int i = 0; i < 4; i++) acc[mt][nt][i] = 0.f;

    // each tile = 128 rows x 64 halfs = 1024 x 16B chunks (8 per row)
    auto load_chunk = [&](int t) {
        const int k0 = t * 64;
        const uint32_t stage = (t & 1) ? (uint32_t)GS_STAGE : 0u;
#pragma unroll
        for (int tile = 0; tile < 2; tile++) {
            const __half* g = (tile == 0) ? A : Bt;
            const int gbase = (tile == 0) ? bm : bn;
#pragma unroll
            for (int i = 0; i < 4; i++) {
                int idx = tid + 256 * i;
                int r = idx >> 3, c = idx & 7;
                cpa16(sb + (stage + tile * GS_TILE + r * GSS + c * 8) * 2,
                      g + (size_t)(gbase + r) * K + k0 + c * 8);
            }
        }
    };

    load_chunk(0);
    CP_COMMIT();

    for (int t = 0; t < T; t++) {
        if (t + 1 < T) { load_chunk(t + 1); CP_COMMIT(); CP_WAIT(1); }
        else           { CP_WAIT(0); }
        __syncthreads();
        const uint32_t stage = (t & 1) ? (uint32_t)GS_STAGE : 0u;

#pragma unroll
        for (int kk = 0; kk < 4; kk++) {
            uint32_t b[8][2];
#pragma unroll
            for (int ntp = 0; ntp < 4; ntp++) {
                int row = wn + ntp * 16 + (lane & 7) + ((lane >> 4) & 1) * 8;
                int col = kk * 16 + ((lane >> 3) & 1) * 8;
                ldsm4(b[2 * ntp][0], b[2 * ntp][1], b[2 * ntp + 1][0], b[2 * ntp + 1][1],
                      sb + (stage + GS_TILE + row * GSS + col) * 2);
            }
            uint32_t a[2][4];
#pragma unroll
            for (int mt = 0; mt < 2; mt++) {
                int row = wm + mt * 16 + (lane & 15);
                int col = kk * 16 + (lane >> 4) * 8;
                ldsm4(a[mt][0], a[mt][1], a[mt][2], a[mt][3],
                      sb + (stage + row * GSS + col) * 2);
            }
#pragma unroll
            for (int mt = 0; mt < 2; mt++)
#pragma unroll
                for (int nt = 0; nt < 8; nt++)
                    mma_f16(acc[mt][nt], a[mt], b[nt]);
        }
        __syncthreads();
    }

#pragma unroll
    for (int mt = 0; mt < 2; mt++) {
        int r = bm + wm + mt * 16 + gr;
#pragma unroll
        for (int nt = 0; nt < 8; nt++) {
            int c = bn + wn + nt * 8 + 2 * qc;
            *(float2*)(C + (size_t)r * N + c)       = make_float2(acc[mt][nt][0], acc[mt][nt][1]);
            *(float2*)(C + (size_t)(r + 8) * N + c) = make_float2(acc[mt][nt][2], acc[mt][nt][3]);
        }
    }
}

// ---------------------------------------------------------------------------
// RoPE + fp16 conversion into per-head planes
// ---------------------------------------------------------------------------
__global__ __launch_bounds__(256) void rope_convert(const float* __restrict__ qkv,
                                                    __half* __restrict__ Qh,
                                                    __half* __restrict__ Kh,
                                                    __half* __restrict__ Vh) {
    __shared__ float cs[64], sn[64];
    const int pos = blockIdx.x, tid = threadIdx.x;
    if (tid < 64) {
        double inv = exp(-(double)tid * (log(10000.0) / 64.0));
        double s, c;
        sincos((double)pos * inv, &s, &c);
        cs[tid] = (float)c;
        sn[tid] = (float)s;
    }
    __syncthreads();
    const float* row = qkv + (size_t)pos * NQKV;
#pragma unroll
    for (int it = 0; it < 4; it++) {            // Q: 1024 pairs, scaled
        int p = tid + it * 256;
        int head = p >> 6, d = p & 63;
        float c = cs[d], s = sn[d];
        const float* base = row + head * HDIM;
        float xr = base[d], xi = base[d + 64];
        __half* o = Qh + (size_t)head * SEQ * HDIM + (size_t)pos * HDIM;
        o[d]      = __float2half((xr * c - xi * s) * SCALE);
        o[d + 64] = __float2half((xr * s + xi * c) * SCALE);
    }
    {                                            // K: 256 pairs
        int kvh = tid >> 6, d = tid & 63;
        float c = cs[d], s = sn[d];
        const float* base = row + 2048 + kvh * HDIM;
        float xr = base[d], xi = base[d + 64];
        __half* o = Kh + (size_t)kvh * SEQ * HDIM + (size_t)pos * HDIM;
        o[d]      = __float2half(xr * c - xi * s);
        o[d + 64] = __float2half(xr * s + xi * c);
    }
#pragma unroll
    for (int j = 0; j < 2; j++) {                // V: 512 values
        int e = tid * 2 + j;
        int kvh = e >> 7, d = e & 127;
        Vh[(size_t)kvh * SEQ * HDIM + (size_t)pos * HDIM + d] =
            __float2half(row[2560 + e]);
    }
}

// ---------------------------------------------------------------------------
// Flash attention: 64q x 64kv tiles (round-6 proven config, occ 2), 256 thr,
// fp16 ldmatrix everywhere, cp.async double-buffered K/V. Writes AOh fp16.
// smem stride 136 halfs (272B = 17x16B): all LDSM patterns conflict-free.
// LOADER INVARIANT: 64 rows x 256B = 1024 x 16B chunks -> i<4, r=lin>>4, c=lin&15
// ---------------------------------------------------------------------------
#define AST 136
#define APS 72
#define AS_Q  0
#define AS_K  (64 * AST)          // 2 buffers
#define AS_V  (64 * AST * 3)      // 2 buffers
#define AS_P  (64 * AST * 5)
#define AS_ST (AS_P + 64 * APS)   // fp32 stats after this (half offset)
#define ATTN_SMEM_BYTES (AS_ST * 2 + 3 * 64 * 4)

__global__ __launch_bounds__(256, 2) void attn2(const __half* __restrict__ Qh,
                                                const __half* __restrict__ Kh,
                                                const __half* __restrict__ Vh,
                                                __half* __restrict__ AOh) {
    extern __shared__ __half smh[];
    const uint32_t sb = (uint32_t)__cvta_generic_to_shared(smh);
    float* ms  = (float*)(smh + AS_ST);
    float* ls  = ms + 64;
    float* als = ls + 64;

    const int tid = threadIdx.x, wid = tid >> 5, lane = tid & 31;
    const int gr = lane >> 2, qc = lane & 3;
    const int q0 = blockIdx.x * 64;
    const int h  = blockIdx.y;
    const int kvh = h >> 2;
    const int wm16 = (wid & 3) * 16;
    const int wn32 = (wid >> 2) * 32;
    const int wn64 = (wid >> 2) * 64;
    const int srow = tid >> 2;
    const int sseg = (tid & 3) * 16;

    const __half* Kp = Kh + (size_t)kvh * SEQ * HDIM;
    const __half* Vp = Vh + (size_t)kvh * SEQ * HDIM;

    // prologue: Q tile + K0/V0 in one commit group
    {
        const __half* Qp = Qh + (size_t)h * SEQ * HDIM + (size_t)q0 * HDIM;
#pragma unroll
        for (int i = 0; i < 4; i++) {
            int lin = tid + 256 * i;
            int r = lin >> 4, c = lin & 15;
            cpa16(sb + (AS_Q + r * AST + c * 8) * 2, Qp + (size_t)r * HDIM + c * 8);
            cpa16(sb + (AS_K + r * AST + c * 8) * 2, Kp + (size_t)r * HDIM + c * 8);
            cpa16(sb + (AS_V + r * AST + c * 8) * 2, Vp + (size_t)r * HDIM + c * 8);
        }
        CP_COMMIT();
    }
    if (tid < 64) { ms[tid] = -INFINITY; ls[tid] = 0.f; }

    float o[8][4];
#pragma unroll
    for (int nt = 0; nt < 8; nt++)
#pragma unroll
        for (int i = 0; i < 4; i++) o[nt][i] = 0.f;

    for (int t = 0; t < 64; t++) {
        if (t + 1 < 64) {
            const int k1 = (t + 1) * 64, buf = (t + 1) & 1;
#pragma unroll
            for (int i = 0; i < 4; i++) {
                int lin = tid + 256 * i;
                int r = lin >> 4, c = lin & 15;
                cpa16(sb + (AS_K + buf * 64 * AST + r * AST + c * 8) * 2,
                      Kp + (size_t)(k1 + r) * HDIM + c * 8);
                cpa16(sb + (AS_V + buf * 64 * AST + r * AST + c * 8) * 2,
                      Vp + (size_t)(k1 + r) * HDIM + c * 8);
            }
            CP_COMMIT();
            CP_WAIT(1);
        } else {
            CP_WAIT(0);
        }
        __syncthreads();
        const uint32_t kbase = AS_K + (uint32_t)(t & 1) * 64 * AST;
        const uint32_t vbase = AS_V + (uint32_t)(t & 1) * 64 * AST;

        // ---- scores: S = Q @ K^T (warp 16q x 32k) ----
        float s[4][4];
#pragma unroll
        for (int nt = 0; nt < 4; nt++)
#pragma unroll
            for (int i = 0; i < 4; i++) s[nt][i] = 0.f;

#pragma unroll
        for (int kk = 0; kk < 8; kk++) {
            uint32_t a[4], b[4][2];
            {
                int row = wm16 + (lane & 15);
                int col = kk * 16 + (lane >> 4) * 8;
                ldsm4(a[0], a[1], a[2], a[3], sb + (AS_Q + row * AST + col) * 2);
            }
#pragma unroll
            for (int ntp = 0; ntp < 2; ntp++) {
                int row = wn32 + ntp * 16 + (lane & 7) + ((lane >> 4) & 1) * 8;
                int col = kk * 16 + ((lane >> 3) & 1) * 8;
                ldsm4(b[2 * ntp][0], b[2 * ntp][1], b[2 * ntp + 1][0], b[2 * ntp + 1][1],
                      sb + (kbase + row * AST + col) * 2);
            }
#pragma unroll
            for (int nt = 0; nt < 4; nt++)
                mma_f16(s[nt], a, b[nt]);
        }
        // P writeback via stmatrix (2 x4 per warp)
#pragma unroll
        for (int ntp = 0; ntp < 2; ntp++) {
            int tl = lane >> 3;
            int g2 = tl & 1, ntl = ntp * 2 + (tl >> 1);
            int row = wm16 + 8 * g2 + (lane & 7);
            int col = wn32 + 8 * ntl;
            stsm4(sb + (AS_P + row * APS + col) * 2,
                  pack_h2(s[2 * ntp][0], s[2 * ntp][1]),
                  pack_h2(s[2 * ntp][2], s[2 * ntp][3]),
                  pack_h2(s[2 * ntp + 1][0], s[2 * ntp + 1][1]),
                  pack_h2(s[2 * ntp + 1][2], s[2 * ntp + 1][3]));
        }
        __syncthreads();

        // ---- online softmax (4 threads/row, fp32 stats) ----
        {
            __half2* prow = (__half2*)(smh + AS_P + srow * APS + sseg);
            float pv[16];
            float mloc = -INFINITY;
#pragma unroll
            for (int j = 0; j < 8; j++) {
                float2 f = __half22float2(prow[j]);
                pv[2 * j] = f.x; pv[2 * j + 1] = f.y;
                mloc = fmaxf(mloc, fmaxf(f.x, f.y));
            }
            mloc = fmaxf(mloc, __shfl_xor_sync(0xffffffffu, mloc, 1));
            mloc = fmaxf(mloc, __shfl_xor_sync(0xffffffffu, mloc, 2));
            float mold = ms[srow];
            float mnew = fmaxf(mold, mloc);
            float sum = 0.f;
#pragma unroll
            for (int j = 0; j < 8; j++) {
                float e0 = __expf(pv[2 * j] - mnew);
                float e1 = __expf(pv[2 * j + 1] - mnew);
                prow[j] = __floats2half2_rn(e0, e1);
                sum += e0 + e1;
            }
            sum += __shfl_xor_sync(0xffffffffu, sum, 1);
            sum += __shfl_xor_sync(0xffffffffu, sum, 2);
            if ((tid & 3) == 0) {
                float a = __expf(mold - mnew);
                als[srow] = a;
                ms[srow] = mnew;
                ls[srow] = ls[srow] * a + sum;
            }
        }
        __syncthreads();

        // ---- rescale, then O += P @ V ----
        {
            float a_lo = als[wm16 + gr];
            float a_hi = als[wm16 + gr + 8];
#pragma unroll
            for (int nt = 0; nt < 8; nt++) {
                o[nt][0] *= a_lo; o[nt][1] *= a_lo;
                o[nt][2] *= a_hi; o[nt][3] *= a_hi;
            }
        }
#pragma unroll
        for (int kk = 0; kk < 4; kk++) {
            uint32_t a[4];
            {
                int row = wm16 + (lane & 15);
                int col = kk * 16 + (lane >> 4) * 8;
                ldsm4(a[0], a[1], a[2], a[3], sb + (AS_P + row * APS + col) * 2);
            }
            const int vrow = kk * 16 + (lane & 7) + ((lane >> 4) << 3);
#pragma unroll
            for (int nt2 = 0; nt2 < 4; nt2++) {
                int vcol = wn64 + nt2 * 16 + ((lane >> 3) & 1) * 8;
                uint32_t r0, r1, r2, r3;
                ldsm4t(r0, r1, r2, r3, sb + (vbase + vrow * AST + vcol) * 2);
                uint32_t b0[2] = {r0, r2};
                uint32_t b1[2] = {r1, r3};
                mma_f16(o[nt2 * 2],     a, b0);
                mma_f16(o[nt2 * 2 + 1], a, b1);
            }
        }
        __syncthreads();
    }

    // ---- finalize: divide by l, fp16 store ----
    {
        int r = wm16 + gr;
        float inv_lo = 1.f / ls[r];
        float inv_hi = 1.f / ls[r + 8];
#pragma unroll
        for (int nt = 0; nt < 8; nt++) {
            int c = wn64 + nt * 8 + 2 * qc;
            size_t o0 = (size_t)(q0 + r) * DMODEL + h * HDIM + c;
            size_t o1 = (size_t)(q0 + r + 8) * DMODEL + h * HDIM + c;
            *(uint32_t*)(AOh + o0) = pack_h2(o[nt][0] * inv_lo, o[nt][1] * inv_lo);
            *(uint32_t*)(AOh + o1) = pack_h2(o[nt][2] * inv_hi, o[nt][3] * inv_hi);
        }
    }
}

// ---------------------------------------------------------------------------
// launch
// ---------------------------------------------------------------------------
extern "C" void kernel_launch(void* const* d_in, const int* in_sizes, int n_in,
                              void* d_out, int out_size) {
    (void)in_sizes; (void)n_in; (void)out_size;
    const float* X  = (const float*)d_in[0];
    const float* Wq = (const float*)d_in[1];
    const float* Wk = (const float*)d_in[2];
    const float* Wv = (const float*)d_in[3];
    const float* Wo = (const float*)d_in[4];
    float* out = (float*)d_out;

    float* QKVp;
    __half *Wt, *Wot, *Xh, *Qh, *Kh, *Vh, *AOh;
    cudaGetSymbolAddress((void**)&QKVp, g_QKV);
    cudaGetSymbolAddress((void**)&Wt, g_Wt);
    cudaGetSymbolAddress((void**)&Wot, g_Wot);
    cudaGetSymbolAddress((void**)&Xh, g_Xh);
    cudaGetSymbolAddress((void**)&Qh, g_Qh);
    cudaGetSymbolAddress((void**)&Kh, g_Kh);
    cudaGetSymbolAddress((void**)&Vh, g_Vh);
    cudaGetSymbolAddress((void**)&AOh, g_AOh);

    cudaFuncSetAttribute(gemm_f16, cudaFuncAttributeMaxDynamicSharedMemorySize,
                         GEMM_SMEM_BYTES);
    cudaFuncSetAttribute(attn2, cudaFuncAttributeMaxDynamicSharedMemorySize,
                         ATTN_SMEM_BYTES);

    // 1) weight transposes + X fp16 conversion
    transpose_f16<<<dim3(64, 64), dim3(32, 8)>>>(Wq, Wt, DMODEL, 2048);
    transpose_f16<<<dim3(16, 64), dim3(32, 8)>>>(Wk, Wt + 2048 * DMODEL, DMODEL, 512);
    transpose_f16<<<dim3(16, 64), dim3(32, 8)>>>(Wv, Wt + 2560 * DMODEL, DMODEL, 512);
    transpose_f16<<<dim3(64, 64), dim3(32, 8)>>>(Wo, Wot, DMODEL, 2048);
    convert_f16<<<SEQ * DMODEL / 4 / 256, 256>>>(X, Xh, SEQ * DMODEL / 4);

    // 2) fused QKV projection
    gemm_f16<<<dim3(NQKV / 128, SEQ / 128), 256, GEMM_SMEM_BYTES>>>(
        Xh, Wt, QKVp, NQKV, DMODEL);

    // 3) RoPE + per-head fp16 planes
    rope_convert<<<SEQ, 256>>>(QKVp, Qh, Kh, Vh);

    // 4) attention (round-6 proven 64x64 config; writes AOh fp16)
    attn2<<<dim3(SEQ / 64, NHEAD), 256, ATTN_SMEM_BYTES>>>(Qh, Kh, Vh, AOh);

    // 5) output projection
    gemm_f16<<<dim3(DMODEL / 128, SEQ / 128), 256, GEMM_SMEM_BYTES>>>(
        AOh, Wot, out, DMODEL, DMODEL);
}

// round 11
// speedup vs baseline: 1.3637x; 1.0502x over previous
#include <cuda_runtime.h>
#include <cuda_fp16.h>
#include <math.h>
#include <stdint.h>

// Problem constants
#define SEQ    4096
#define DMODEL 2048
#define NHEAD  16
#define NKV    4
#define HDIM   128
#define NQKV   3072
#define SCALE  0.08838834764831845f   // 1/sqrt(128)

// ---------------------------------------------------------------------------
// Scratch (device globals; no allocation allowed)
// ---------------------------------------------------------------------------
__device__ float  g_QKV[SEQ * NQKV];          // fused Q|K|V fp32 (gemm out)
__device__ __half g_Wt[NQKV * DMODEL];        // fused Wq|Wk|Wv transposed [N,K]
__device__ __half g_Wot[DMODEL * DMODEL];     // Wo transposed [N,K]
__device__ __half g_Xh[SEQ * DMODEL];         // X fp16
__device__ __half g_Qh[NHEAD * SEQ * HDIM];   // per-head planes, rope+scale
__device__ __half g_Kh[NKV * SEQ * HDIM];     // rope applied
__device__ __half g_Vh[NKV * SEQ * HDIM];
__device__ __half g_AOh[SEQ * DMODEL];        // attention out fp16

// ---------------------------------------------------------------------------
// helpers
// ---------------------------------------------------------------------------
__device__ __forceinline__ void mma_f16(float c[4], const uint32_t a[4], const uint32_t b[2]) {
    asm volatile(
        "mma.sync.aligned.m16n8k16.row.col.f32.f16.f16.f32 "
        "{%0,%1,%2,%3}, {%4,%5,%6,%7}, {%8,%9}, {%0,%1,%2,%3};\n"
        : "+f"(c[0]), "+f"(c[1]), "+f"(c[2]), "+f"(c[3])
        : "r"(a[0]), "r"(a[1]), "r"(a[2]), "r"(a[3]), "r"(b[0]), "r"(b[1]));
}

__device__ __forceinline__ uint32_t pack_h2(float x, float y) {
    __half2 h = __floats2half2_rn(x, y);
    return *(uint32_t*)&h;
}

__device__ __forceinline__ void cpa16(uint32_t saddr, const void* g) {
    asm volatile("cp.async.cg.shared.global [%0], [%1], 16;" :: "r"(saddr), "l"(g));
}
#define CP_COMMIT() asm volatile("cp.async.commit_group;" ::: "memory")
#define CP_WAIT(n)  asm volatile("cp.async.wait_group %0;" :: "n"(n) : "memory")

__device__ __forceinline__ void ldsm4(uint32_t& r0, uint32_t& r1, uint32_t& r2, uint32_t& r3,
                                      uint32_t addr) {
    asm volatile("ldmatrix.sync.aligned.m8n8.x4.shared.b16 {%0,%1,%2,%3}, [%4];"
                 : "=r"(r0), "=r"(r1), "=r"(r2), "=r"(r3) : "r"(addr));
}
__device__ __forceinline__ void ldsm4t(uint32_t& r0, uint32_t& r1, uint32_t& r2, uint32_t& r3,
                                       uint32_t addr) {
    asm volatile("ldmatrix.sync.aligned.m8n8.x4.trans.shared.b16 {%0,%1,%2,%3}, [%4];"
                 : "=r"(r0), "=r"(r1), "=r"(r2), "=r"(r3) : "r"(addr));
}

// ---------------------------------------------------------------------------
// prep kernels
// ---------------------------------------------------------------------------
__global__ __launch_bounds__(256) void transpose_f16(const float* __restrict__ W,
                                                     __half* __restrict__ T,
                                                     int K, int N) {
    __shared__ float t[32][33];
    int tx = threadIdx.x, ty = threadIdx.y;
    int n0 = blockIdx.x * 32, k0 = blockIdx.y * 32;
#pragma unroll
    for (int i = 0; i < 4; i++)
        t[ty + 8 * i][tx] = W[(size_t)(k0 + ty + 8 * i) * N + n0 + tx];
    __syncthreads();
#pragma unroll
    for (int i = 0; i < 4; i++)
        T[(size_t)(n0 + ty + 8 * i) * K + k0 + tx] = __float2half(t[tx][ty + 8 * i]);
}

__global__ __launch_bounds__(256) void convert_f16(const float* __restrict__ src,
                                                   __half* __restrict__ dst, int n4) {
    int i = blockIdx.x * blockDim.x + threadIdx.x;
    if (i >= n4) return;
    float4 v = ((const float4*)src)[i];
    uint2 p;
    p.x = pack_h2(v.x, v.y);
    p.y = pack_h2(v.z, v.w);
    ((uint2*)dst)[i] = p;
}

// ---------------------------------------------------------------------------
// fp16 GEMM: C[M,N] fp32 = A[M,K]h @ Bt[N,K]h^T  (unchanged from round 10)
// ---------------------------------------------------------------------------
#define GSS 72
#define GS_TILE  (128 * GSS)
#define GS_STAGE (2 * GS_TILE)
#define GEMM_SMEM_BYTES (2 * GS_STAGE * 2)

__global__ __launch_bounds__(256, 2) void gemm_f16(
    const __half* __restrict__ A, const __half* __restrict__ Bt,
    float* __restrict__ C, int N, int K) {
    extern __shared__ __half gsm[];
    const uint32_t sb = (uint32_t)__cvta_generic_to_shared(gsm);
    const int tid = threadIdx.x, wid = tid >> 5, lane = tid & 31;
    const int gr = lane >> 2, qc = lane & 3;
    const int bm = blockIdx.y * 128, bn = blockIdx.x * 128;
    const int wm = (wid & 3) * 32, wn = (wid >> 2) * 64;
    const int T = K >> 6;

    float acc[2][8][4];
#pragma unroll
    for (int mt = 0; mt < 2; mt++)
#pragma unroll
        for (int nt = 0; nt < 8; nt++)
#pragma unroll
            for (int i = 0; i < 4; i++) acc[mt][nt][i] = 0.f;

    auto load_chunk = [&](int t) {
        const int k0 = t * 64;
        const uint32_t stage = (t & 1) ? (uint32_t)GS_STAGE : 0u;
#pragma unroll
        for (int tile = 0; tile < 2; tile++) {
            const __half* g = (tile == 0) ? A : Bt;
            const int gbase = (tile == 0) ? bm : bn;
#pragma unroll
            for (int i = 0; i < 4; i++) {
                int idx = tid + 256 * i;
                int r = idx >> 3, c = idx & 7;
                cpa16(sb + (stage + tile * GS_TILE + r * GSS + c * 8) * 2,
                      g + (size_t)(gbase + r) * K + k0 + c * 8);
            }
        }
    };

    load_chunk(0);
    CP_COMMIT();

    for (int t = 0; t < T; t++) {
        if (t + 1 < T) { load_chunk(t + 1); CP_COMMIT(); CP_WAIT(1); }
        else           { CP_WAIT(0); }
        __syncthreads();
        const uint32_t stage = (t & 1) ? (uint32_t)GS_STAGE : 0u;

#pragma unroll
        for (int kk = 0; kk < 4; kk++) {
            uint32_t b[8][2];
#pragma unroll
            for (int ntp = 0; ntp < 4; ntp++) {
                int row = wn + ntp * 16 + (lane & 7) + ((lane >> 4) & 1) * 8;
                int col = kk * 16 + ((lane >> 3) & 1) * 8;
                ldsm4(b[2 * ntp][0], b[2 * ntp][1], b[2 * ntp + 1][0], b[2 * ntp + 1][1],
                      sb + (stage + GS_TILE + row * GSS + col) * 2);
            }
            uint32_t a[2][4];
#pragma unroll
            for (int mt = 0; mt < 2; mt++) {
                int row = wm + mt * 16 + (lane & 15);
                int col = kk * 16 + (lane >> 4) * 8;
                ldsm4(a[mt][0], a[mt][1], a[mt][2], a[mt][3],
                      sb + (stage + row * GSS + col) * 2);
            }
#pragma unroll
            for (int mt = 0; mt < 2; mt++)
#pragma unroll
                for (int nt = 0; nt < 8; nt++)
                    mma_f16(acc[mt][nt], a[mt], b[nt]);
        }
        __syncthreads();
    }

#pragma unroll
    for (int mt = 0; mt < 2; mt++) {
        int r = bm + wm + mt * 16 + gr;
#pragma unroll
        for (int nt = 0; nt < 8; nt++) {
            int c = bn + wn + nt * 8 + 2 * qc;
            *(float2*)(C + (size_t)r * N + c)       = make_float2(acc[mt][nt][0], acc[mt][nt][1]);
            *(float2*)(C + (size_t)(r + 8) * N + c) = make_float2(acc[mt][nt][2], acc[mt][nt][3]);
        }
    }
}

// ---------------------------------------------------------------------------
// RoPE + fp16 conversion into per-head planes (unchanged)
// ---------------------------------------------------------------------------
__global__ __launch_bounds__(256) void rope_convert(const float* __restrict__ qkv,
                                                    __half* __restrict__ Qh,
                                                    __half* __restrict__ Kh,
                                                    __half* __restrict__ Vh) {
    __shared__ float cs[64], sn[64];
    const int pos = blockIdx.x, tid = threadIdx.x;
    if (tid < 64) {
        double inv = exp(-(double)tid * (log(10000.0) / 64.0));
        double s, c;
        sincos((double)pos * inv, &s, &c);
        cs[tid] = (float)c;
        sn[tid] = (float)s;
    }
    __syncthreads();
    const float* row = qkv + (size_t)pos * NQKV;
#pragma unroll
    for (int it = 0; it < 4; it++) {
        int p = tid + it * 256;
        int head = p >> 6, d = p & 63;
        float c = cs[d], s = sn[d];
        const float* base = row + head * HDIM;
        float xr = base[d], xi = base[d + 64];
        __half* o = Qh + (size_t)head * SEQ * HDIM + (size_t)pos * HDIM;
        o[d]      = __float2half((xr * c - xi * s) * SCALE);
        o[d + 64] = __float2half((xr * s + xi * c) * SCALE);
    }
    {
        int kvh = tid >> 6, d = tid & 63;
        float c = cs[d], s = sn[d];
        const float* base = row + 2048 + kvh * HDIM;
        float xr = base[d], xi = base[d + 64];
        __half* o = Kh + (size_t)kvh * SEQ * HDIM + (size_t)pos * HDIM;
        o[d]      = __float2half(xr * c - xi * s);
        o[d + 64] = __float2half(xr * s + xi * c);
    }
#pragma unroll
    for (int j = 0; j < 2; j++) {
        int e = tid * 2 + j;
        int kvh = e >> 7, d = e & 127;
        Vh[(size_t)kvh * SEQ * HDIM + (size_t)pos * HDIM + d] =
            __float2half(row[2560 + e]);
    }
}

// ---------------------------------------------------------------------------
// Flash attention v4: register-resident P (fragment identity), 2 barriers/iter.
// 8 warps = 4 row-groups x 2 kv-groups. Each warp: S for its 32-kv slice in
// regs -> softmax on regs (cross-warp max/sum partials via tiny smem) -> P
// packed directly into mma A-fragments -> partial O over all 128 d cols.
// Partial O and partial l combined at finalize (obuf aliases dead K region).
// smem stride 136 halfs: all LDSM patterns conflict-free.
// ---------------------------------------------------------------------------
#define AST 136
#define AS_Q  0
#define AS_K  (64 * AST)          // 2 buffers (also aliased as obuf at finalize)
#define AS_V  (AS_K + 2 * 64 * AST)
#define AS_ST (AS_V + 2 * 64 * AST)   // halfs offset; then 320 floats of stats
#define ATTN_SMEM_BYTES (AS_ST * 2 + 320 * 4)
#define OBUF_STRIDE 132

__global__ __launch_bounds__(256, 2) void attn4(const __half* __restrict__ Qh,
                                                const __half* __restrict__ Kh,
                                                const __half* __restrict__ Vh,
                                                __half* __restrict__ AOh) {
    extern __shared__ __half smh[];
    const uint32_t sb = (uint32_t)__cvta_generic_to_shared(smh);
    float* pstat = (float*)(smh + AS_ST);
    float* pmax = pstat;          // [2][64]
    float* ms   = pstat + 128;    // [64]
    float* lsw  = pstat + 192;    // [2][64]
    float* obuf = (float*)(smh + AS_K);   // 64 x 132 fp32, valid only at finalize

    const int tid = threadIdx.x, wid = tid >> 5, lane = tid & 31;
    const int gr = lane >> 2, qc = lane & 3;
    const int q0 = blockIdx.x * 64;
    const int h  = blockIdx.y;
    const int kvh = h >> 2;
    const int wg   = wid >> 2;           // kv-group: 0 -> kv cols 0-31, 1 -> 32-63
    const int wrow = (wid & 3) * 16;     // q-row base
    const int wn32 = wg * 32;
    const int r0 = wrow + gr, r1 = wrow + gr + 8;

    const __half* Kp = Kh + (size_t)kvh * SEQ * HDIM;
    const __half* Vp = Vh + (size_t)kvh * SEQ * HDIM;

    // prologue: Q + K0/V0 (each tile: 64 rows x 256B = 1024 x 16B chunks)
    {
        const __half* Qp = Qh + (size_t)h * SEQ * HDIM + (size_t)q0 * HDIM;
#pragma unroll
        for (int i = 0; i < 4; i++) {
            int lin = tid + 256 * i;
            int r = lin >> 4, c = lin & 15;
            cpa16(sb + (AS_Q + r * AST + c * 8) * 2, Qp + (size_t)r * HDIM + c * 8);
            cpa16(sb + (AS_K + r * AST + c * 8) * 2, Kp + (size_t)r * HDIM + c * 8);
            cpa16(sb + (AS_V + r * AST + c * 8) * 2, Vp + (size_t)r * HDIM + c * 8);
        }
        CP_COMMIT();
    }
    if (tid < 64) ms[tid] = -INFINITY;
    if (tid < 128) lsw[tid] = 0.f;

    float o[16][4];
#pragma unroll
    for (int j = 0; j < 16; j++)
#pragma unroll
        for (int i = 0; i < 4; i++) o[j][i] = 0.f;

    for (int t = 0; t < 64; t++) {
        CP_WAIT(0);
        __syncthreads();   // sync1: tile t ready; iter t-1 fully done everywhere
        if (t + 1 < 64) {  // prefetch t+1 into buffer last read at iter t-1
            const int k1 = (t + 1) * 64, buf = (t + 1) & 1;
#pragma unroll
            for (int i = 0; i < 4; i++) {
                int lin = tid + 256 * i;
                int r = lin >> 4, c = lin & 15;
                cpa16(sb + (AS_K + buf * 64 * AST + r * AST + c * 8) * 2,
                      Kp + (size_t)(k1 + r) * HDIM + c * 8);
                cpa16(sb + (AS_V + buf * 64 * AST + r * AST + c * 8) * 2,
                      Vp + (size_t)(k1 + r) * HDIM + c * 8);
            }
            CP_COMMIT();
        }
        const uint32_t kbase = AS_K + (uint32_t)(t & 1) * 64 * AST;
        const uint32_t vbase = AS_V + (uint32_t)(t & 1) * 64 * AST;

        // ---- scores: warp computes S[16 rows][32 kv] in regs ----
        float s[4][4];
#pragma unroll
        for (int nt = 0; nt < 4; nt++)
#pragma unroll
            for (int i = 0; i < 4; i++) s[nt][i] = 0.f;

#pragma unroll
        for (int kk = 0; kk < 8; kk++) {
            uint32_t a[4], b[4][2];
            {
                int row = wrow + (lane & 15);
                int col = kk * 16 + (lane >> 4) * 8;
                ldsm4(a[0], a[1], a[2], a[3], sb + (AS_Q + row * AST + col) * 2);
            }
#pragma unroll
            for (int ntp = 0; ntp < 2; ntp++) {
                int row = wn32 + ntp * 16 + (lane & 7) + ((lane >> 4) & 1) * 8;
                int col = kk * 16 + ((lane >> 3) & 1) * 8;
                ldsm4(b[2 * ntp][0], b[2 * ntp][1], b[2 * ntp + 1][0], b[2 * ntp + 1][1],
                      sb + (kbase + row * AST + col) * 2);
            }
#pragma unroll
            for (int nt = 0; nt < 4; nt++)
                mma_f16(s[nt], a, b[nt]);
        }

        // read previous m BEFORE the stat-exchange barrier (stable since t-1)
        float mold0 = ms[r0], mold1 = ms[r1];

        // warp-local row max over this warp's 32 kv cols
        float rmax0 = -INFINITY, rmax1 = -INFINITY;
#pragma unroll
        for (int nt = 0; nt < 4; nt++) {
            rmax0 = fmaxf(rmax0, fmaxf(s[nt][0], s[nt][1]));
            rmax1 = fmaxf(rmax1, fmaxf(s[nt][2], s[nt][3]));
        }
        rmax0 = fmaxf(rmax0, __shfl_xor_sync(0xffffffffu, rmax0, 1));
        rmax0 = fmaxf(rmax0, __shfl_xor_sync(0xffffffffu, rmax0, 2));
        rmax1 = fmaxf(rmax1, __shfl_xor_sync(0xffffffffu, rmax1, 1));
        rmax1 = fmaxf(rmax1, __shfl_xor_sync(0xffffffffu, rmax1, 2));
        if (qc == 0) {
            pmax[wg * 64 + r0] = rmax0;
            pmax[wg * 64 + r1] = rmax1;
        }
        __syncthreads();   // sync2: max partials visible

        float mnew0 = fmaxf(mold0, fmaxf(pmax[r0], pmax[64 + r0]));
        float mnew1 = fmaxf(mold1, fmaxf(pmax[r1], pmax[64 + r1]));
        float als0 = __expf(mold0 - mnew0);
        float als1 = __expf(mold1 - mnew1);

        // exp in place + warp-partial row sums
        float sum0 = 0.f, sum1 = 0.f;
#pragma unroll
        for (int nt = 0; nt < 4; nt++) {
            s[nt][0] = __expf(s[nt][0] - mnew0);
            s[nt][1] = __expf(s[nt][1] - mnew0);
            s[nt][2] = __expf(s[nt][2] - mnew1);
            s[nt][3] = __expf(s[nt][3] - mnew1);
            sum0 += s[nt][0] + s[nt][1];
            sum1 += s[nt][2] + s[nt][3];
        }
        sum0 += __shfl_xor_sync(0xffffffffu, sum0, 1);
        sum0 += __shfl_xor_sync(0xffffffffu, sum0, 2);
        sum1 += __shfl_xor_sync(0xffffffffu, sum1, 1);
        sum1 += __shfl_xor_sync(0xffffffffu, sum1, 2);
        if (qc == 0) {
            lsw[wg * 64 + r0] = lsw[wg * 64 + r0] * als0 + sum0;
            lsw[wg * 64 + r1] = lsw[wg * 64 + r1] * als1 + sum1;
            if (wg == 0) { ms[r0] = mnew0; ms[r1] = mnew1; }   // all molds read pre-sync2
        }

        // ---- rescale partial O, then O += P @ V (P from regs, fragment identity) ----
#pragma unroll
        for (int j = 0; j < 16; j++) {
            o[j][0] *= als0; o[j][1] *= als0;
            o[j][2] *= als1; o[j][3] *= als1;
        }
#pragma unroll
        for (int c = 0; c < 2; c++) {
            uint32_t a[4];
            a[0] = pack_h2(s[2 * c][0], s[2 * c][1]);
            a[1] = pack_h2(s[2 * c][2], s[2 * c][3]);
            a[2] = pack_h2(s[2 * c + 1][0], s[2 * c + 1][1]);
            a[3] = pack_h2(s[2 * c + 1][2], s[2 * c + 1][3]);
            const int vrow = wn32 + c * 16 + (lane & 7) + ((lane >> 4) << 3);
#pragma unroll
            for (int nt2 = 0; nt2 < 8; nt2++) {
                int vcol = nt2 * 16 + ((lane >> 3) & 1) * 8;
                uint32_t b0, b1, b2, b3;
                ldsm4t(b0, b1, b2, b3, sb + (vbase + vrow * AST + vcol) * 2);
                uint32_t p0[2] = {b0, b2};
                uint32_t p1[2] = {b1, b3};
                mma_f16(o[nt2 * 2],     a, p0);
                mma_f16(o[nt2 * 2 + 1], a, p1);
            }
        }
        // no end-of-iteration barrier: next iter's sync1 protects buffer reuse
    }

    // ---- finalize: combine kv-group partials (obuf aliases K region) ----
    __syncthreads();
    if (wg == 1) {
#pragma unroll
        for (int j = 0; j < 16; j++) {
            *(float2*)&obuf[r0 * OBUF_STRIDE + j * 8 + 2 * qc] = make_float2(o[j][0], o[j][1]);
            *(float2*)&obuf[r1 * OBUF_STRIDE + j * 8 + 2 * qc] = make_float2(o[j][2], o[j][3]);
        }
    }
    __syncthreads();
    if (wg == 0) {
        float inv0 = 1.f / (lsw[r0] + lsw[64 + r0]);
        float inv1 = 1.f / (lsw[r1] + lsw[64 + r1]);
#pragma unroll
        for (int j = 0; j < 16; j++) {
            float2 p0 = *(float2*)&obuf[r0 * OBUF_STRIDE + j * 8 + 2 * qc];
            float2 p1 = *(float2*)&obuf[r1 * OBUF_STRIDE + j * 8 + 2 * qc];
            int c = j * 8 + 2 * qc;
            size_t o0 = (size_t)(q0 + r0) * DMODEL + h * HDIM + c;
            size_t o1 = (size_t)(q0 + r1) * DMODEL + h * HDIM + c;
            *(uint32_t*)(AOh + o0) = pack_h2((o[j][0] + p0.x) * inv0, (o[j][1] + p0.y) * inv0);
            *(uint32_t*)(AOh + o1) = pack_h2((o[j][2] + p1.x) * inv1, (o[j][3] + p1.y) * inv1);
        }
    }
}

// ---------------------------------------------------------------------------
// launch
// ---------------------------------------------------------------------------
extern "C" void kernel_launch(void* const* d_in, const int* in_sizes, int n_in,
                              void* d_out, int out_size) {
    (void)in_sizes; (void)n_in; (void)out_size;
    const float* X  = (const float*)d_in[0];
    const float* Wq = (const float*)d_in[1];
    const float* Wk = (const float*)d_in[2];
    const float* Wv = (const float*)d_in[3];
    const float* Wo = (const float*)d_in[4];
    float* out = (float*)d_out;

    float* QKVp;
    __half *Wt, *Wot, *Xh, *Qh, *Kh, *Vh, *AOh;
    cudaGetSymbolAddress((void**)&QKVp, g_QKV);
    cudaGetSymbolAddress((void**)&Wt, g_Wt);
    cudaGetSymbolAddress((void**)&Wot, g_Wot);
    cudaGetSymbolAddress((void**)&Xh, g_Xh);
    cudaGetSymbolAddress((void**)&Qh, g_Qh);
    cudaGetSymbolAddress((void**)&Kh, g_Kh);
    cudaGetSymbolAddress((void**)&Vh, g_Vh);
    cudaGetSymbolAddress((void**)&AOh, g_AOh);

    cudaFuncSetAttribute(gemm_f16, cudaFuncAttributeMaxDynamicSharedMemorySize,
                         GEMM_SMEM_BYTES);
    cudaFuncSetAttribute(attn4, cudaFuncAttributeMaxDynamicSharedMemorySize,
                         ATTN_SMEM_BYTES);

    // 1) weight transposes + X fp16 conversion
    transpose_f16<<<dim3(64, 64), dim3(32, 8)>>>(Wq, Wt, DMODEL, 2048);
    transpose_f16<<<dim3(16, 64), dim3(32, 8)>>>(Wk, Wt + 2048 * DMODEL, DMODEL, 512);
    transpose_f16<<<dim3(16, 64), dim3(32, 8)>>>(Wv, Wt + 2560 * DMODEL, DMODEL, 512);
    transpose_f16<<<dim3(64, 64), dim3(32, 8)>>>(Wo, Wot, DMODEL, 2048);
    convert_f16<<<SEQ * DMODEL / 4 / 256, 256>>>(X, Xh, SEQ * DMODEL / 4);

    // 2) fused QKV projection
    gemm_f16<<<dim3(NQKV / 128, SEQ / 128), 256, GEMM_SMEM_BYTES>>>(
        Xh, Wt, QKVp, NQKV, DMODEL);

    // 3) RoPE + per-head fp16 planes
    rope_convert<<<SEQ, 256>>>(QKVp, Qh, Kh, Vh);

    // 4) attention (register-P, 2 barriers/iter)
    attn4<<<dim3(SEQ / 64, NHEAD), 256, ATTN_SMEM_BYTES>>>(Qh, Kh, Vh, AOh);

    // 5) output projection
    gemm_f16<<<dim3(DMODEL / 128, SEQ / 128), 256, GEMM_SMEM_BYTES>>>(
        AOh, Wot, out, DMODEL, DMODEL);
}

// round 12
// speedup vs baseline: 1.4220x; 1.0427x over previous
#include <cuda_runtime.h>
#include <cuda_fp16.h>
#include <math.h>
#include <stdint.h>

// Problem constants
#define SEQ    4096
#define DMODEL 2048
#define NHEAD  16
#define NKV    4
#define HDIM   128
#define NQKV   3072
#define SCALE  0.08838834764831845f   // 1/sqrt(128)

// ---------------------------------------------------------------------------
// Scratch (device globals; no allocation allowed)
// ---------------------------------------------------------------------------
__device__ __half g_QKVh[SEQ * NQKV];         // fused Q|K|V fp16 (gemm out)
__device__ __half g_Wt[NQKV * DMODEL];        // fused Wq|Wk|Wv transposed [N,K]
__device__ __half g_Wot[DMODEL * DMODEL];     // Wo transposed [N,K]
__device__ __half g_Xh[SEQ * DMODEL];         // X fp16
__device__ __half g_Qh[NHEAD * SEQ * HDIM];   // per-head planes, rope+scale
__device__ __half g_Kh[NKV * SEQ * HDIM];     // rope applied
__device__ __half g_Vh[NKV * SEQ * HDIM];
__device__ __half g_AOh[SEQ * DMODEL];        // attention out fp16

// ---------------------------------------------------------------------------
// helpers
// ---------------------------------------------------------------------------
__device__ __forceinline__ void mma_f16(float c[4], const uint32_t a[4], const uint32_t b[2]) {
    asm volatile(
        "mma.sync.aligned.m16n8k16.row.col.f32.f16.f16.f32 "
        "{%0,%1,%2,%3}, {%4,%5,%6,%7}, {%8,%9}, {%0,%1,%2,%3};\n"
        : "+f"(c[0]), "+f"(c[1]), "+f"(c[2]), "+f"(c[3])
        : "r"(a[0]), "r"(a[1]), "r"(a[2]), "r"(a[3]), "r"(b[0]), "r"(b[1]));
}

__device__ __forceinline__ uint32_t pack_h2(float x, float y) {
    __half2 h = __floats2half2_rn(x, y);
    return *(uint32_t*)&h;
}

__device__ __forceinline__ void cpa16(uint32_t saddr, const void* g) {
    asm volatile("cp.async.cg.shared.global [%0], [%1], 16;" :: "r"(saddr), "l"(g));
}
#define CP_COMMIT() asm volatile("cp.async.commit_group;" ::: "memory")
#define CP_WAIT(n)  asm volatile("cp.async.wait_group %0;" :: "n"(n) : "memory")

__device__ __forceinline__ void ldsm4(uint32_t& r0, uint32_t& r1, uint32_t& r2, uint32_t& r3,
                                      uint32_t addr) {
    asm volatile("ldmatrix.sync.aligned.m8n8.x4.shared.b16 {%0,%1,%2,%3}, [%4];"
                 : "=r"(r0), "=r"(r1), "=r"(r2), "=r"(r3) : "r"(addr));
}
__device__ __forceinline__ void ldsm4t(uint32_t& r0, uint32_t& r1, uint32_t& r2, uint32_t& r3,
                                       uint32_t addr) {
    asm volatile("ldmatrix.sync.aligned.m8n8.x4.trans.shared.b16 {%0,%1,%2,%3}, [%4];"
                 : "=r"(r0), "=r"(r1), "=r"(r2), "=r"(r3) : "r"(addr));
}

// ---------------------------------------------------------------------------
// prep kernels
// ---------------------------------------------------------------------------
__global__ __launch_bounds__(256) void transpose_f16(const float* __restrict__ W,
                                                     __half* __restrict__ T,
                                                     int K, int N) {
    __shared__ float t[32][33];
    int tx = threadIdx.x, ty = threadIdx.y;
    int n0 = blockIdx.x * 32, k0 = blockIdx.y * 32;
#pragma unroll
    for (int i = 0; i < 4; i++)
        t[ty + 8 * i][tx] = W[(size_t)(k0 + ty + 8 * i) * N + n0 + tx];
    __syncthreads();
#pragma unroll
    for (int i = 0; i < 4; i++)
        T[(size_t)(n0 + ty + 8 * i) * K + k0 + tx] = __float2half(t[tx][ty + 8 * i]);
}

__global__ __launch_bounds__(256) void convert_f16(const float* __restrict__ src,
                                                   __half* __restrict__ dst, int n4) {
    int i = blockIdx.x * blockDim.x + threadIdx.x;
    if (i >= n4) return;
    float4 v = ((const float4*)src)[i];
    uint2 p;
    p.x = pack_h2(v.x, v.y);
    p.y = pack_h2(v.z, v.w);
    ((uint2*)dst)[i] = p;
}

// ---------------------------------------------------------------------------
// fp16 GEMM core. Two epilogue variants: fp32 C (out-proj) and fp16 C (QKV).
// Block 128x128, BK=64, 2-stage cp.async, ldmatrix fragments. 256 thr, occ 2.
// ---------------------------------------------------------------------------
#define GSS 72
#define GS_TILE  (128 * GSS)
#define GS_STAGE (2 * GS_TILE)
#define GEMM_SMEM_BYTES (2 * GS_STAGE * 2)

#define GEMM_BODY(EPILOGUE)                                                     \
    extern __shared__ __half gsm[];                                             \
    const uint32_t sb = (uint32_t)__cvta_generic_to_shared(gsm);                \
    const int tid = threadIdx.x, wid = tid >> 5, lane = tid & 31;               \
    const int gr = lane >> 2, qc = lane & 3;                                    \
    const int bm = blockIdx.y * 128, bn = blockIdx.x * 128;                     \
    const int wm = (wid & 3) * 32, wn = (wid >> 2) * 64;                        \
    const int T = K >> 6;                                                       \
    float acc[2][8][4];                                                         \
    _Pragma("unroll")                                                           \
    for (int mt = 0; mt < 2; mt++)                                              \
        _Pragma("unroll")                                                       \
        for (int nt = 0; nt < 8; nt++)                                          \
            _Pragma("unroll")                                                   \
            for (int i = 0; i < 4; i++) acc[mt][nt][i] = 0.f;                   \
    auto load_chunk = [&](int t) {                                              \
        const int k0 = t * 64;                                                  \
        const uint32_t stage = (t & 1) ? (uint32_t)GS_STAGE : 0u;               \
        _Pragma("unroll")                                                       \
        for (int tile = 0; tile < 2; tile++) {                                  \
            const __half* g = (tile == 0) ? A : Bt;                             \
            const int gbase = (tile == 0) ? bm : bn;                            \
            _Pragma("unroll")                                                   \
            for (int i = 0; i < 4; i++) {                                       \
                int idx = tid + 256 * i;                                        \
                int r = idx >> 3, c = idx & 7;                                  \
                cpa16(sb + (stage + tile * GS_TILE + r * GSS + c * 8) * 2,      \
                      g + (size_t)(gbase + r) * K + k0 + c * 8);                \
            }                                                                   \
        }                                                                       \
    };                                                                          \
    load_chunk(0);                                                              \
    CP_COMMIT();                                                                \
    for (int t = 0; t < T; t++) {                                               \
        if (t + 1 < T) { load_chunk(t + 1); CP_COMMIT(); CP_WAIT(1); }          \
        else           { CP_WAIT(0); }                                          \
        __syncthreads();                                                        \
        const uint32_t stage = (t & 1) ? (uint32_t)GS_STAGE : 0u;               \
        _Pragma("unroll")                                                       \
        for (int kk = 0; kk < 4; kk++) {                                        \
            uint32_t b[8][2];                                                   \
            _Pragma("unroll")                                                   \
            for (int ntp = 0; ntp < 4; ntp++) {                                 \
                int row = wn + ntp * 16 + (lane & 7) + ((lane >> 4) & 1) * 8;   \
                int col = kk * 16 + ((lane >> 3) & 1) * 8;                      \
                ldsm4(b[2 * ntp][0], b[2 * ntp][1], b[2 * ntp + 1][0],          \
                      b[2 * ntp + 1][1],                                        \
                      sb + (stage + GS_TILE + row * GSS + col) * 2);            \
            }                                                                   \
            uint32_t a[2][4];                                                   \
            _Pragma("unroll")                                                   \
            for (int mt = 0; mt < 2; mt++) {                                    \
                int row = wm + mt * 16 + (lane & 15);                           \
                int col = kk * 16 + (lane >> 4) * 8;                            \
                ldsm4(a[mt][0], a[mt][1], a[mt][2], a[mt][3],                   \
                      sb + (stage + row * GSS + col) * 2);                      \
            }                                                                   \
            _Pragma("unroll")                                                   \
            for (int mt = 0; mt < 2; mt++)                                      \
                _Pragma("unroll")                                               \
                for (int nt = 0; nt < 8; nt++)                                  \
                    mma_f16(acc[mt][nt], a[mt], b[nt]);                         \
        }                                                                       \
        __syncthreads();                                                        \
    }                                                                           \
    EPILOGUE

__global__ __launch_bounds__(256, 2) void gemm_f16(
    const __half* __restrict__ A, const __half* __restrict__ Bt,
    float* __restrict__ C, int N, int K) {
    GEMM_BODY({
#pragma unroll
        for (int mt = 0; mt < 2; mt++) {
            int r = bm + wm + mt * 16 + gr;
#pragma unroll
            for (int nt = 0; nt < 8; nt++) {
                int c = bn + wn + nt * 8 + 2 * qc;
                *(float2*)(C + (size_t)r * N + c) =
                    make_float2(acc[mt][nt][0], acc[mt][nt][1]);
                *(float2*)(C + (size_t)(r + 8) * N + c) =
                    make_float2(acc[mt][nt][2], acc[mt][nt][3]);
            }
        }
    })
}

__global__ __launch_bounds__(256, 2) void gemm_f16h(
    const __half* __restrict__ A, const __half* __restrict__ Bt,
    __half* __restrict__ C, int N, int K) {
    GEMM_BODY({
#pragma unroll
        for (int mt = 0; mt < 2; mt++) {
            int r = bm + wm + mt * 16 + gr;
#pragma unroll
            for (int nt = 0; nt < 8; nt++) {
                int c = bn + wn + nt * 8 + 2 * qc;
                *(uint32_t*)(C + (size_t)r * N + c) =
                    pack_h2(acc[mt][nt][0], acc[mt][nt][1]);
                *(uint32_t*)(C + (size_t)(r + 8) * N + c) =
                    pack_h2(acc[mt][nt][2], acc[mt][nt][3]);
            }
        }
    })
}

// ---------------------------------------------------------------------------
// RoPE + per-head planes, reading fp16 fused QKV
// ---------------------------------------------------------------------------
__global__ __launch_bounds__(256) void rope_convert(const __half* __restrict__ qkv,
                                                    __half* __restrict__ Qh,
                                                    __half* __restrict__ Kh,
                                                    __half* __restrict__ Vh) {
    __shared__ float cs[64], sn[64];
    const int pos = blockIdx.x, tid = threadIdx.x;
    if (tid < 64) {
        double inv = exp(-(double)tid * (log(10000.0) / 64.0));
        double s, c;
        sincos((double)pos * inv, &s, &c);
        cs[tid] = (float)c;
        sn[tid] = (float)s;
    }
    __syncthreads();
    const __half* row = qkv + (size_t)pos * NQKV;
#pragma unroll
    for (int it = 0; it < 4; it++) {            // Q: 1024 pairs, scaled
        int p = tid + it * 256;
        int head = p >> 6, d = p & 63;
        float c = cs[d], s = sn[d];
        const __half* base = row + head * HDIM;
        float xr = __half2float(base[d]), xi = __half2float(base[d + 64]);
        __half* o = Qh + (size_t)head * SEQ * HDIM + (size_t)pos * HDIM;
        o[d]      = __float2half((xr * c - xi * s) * SCALE);
        o[d + 64] = __float2half((xr * s + xi * c) * SCALE);
    }
    {                                            // K: 256 pairs
        int kvh = tid >> 6, d = tid & 63;
        float c = cs[d], s = sn[d];
        const __half* base = row + 2048 + kvh * HDIM;
        float xr = __half2float(base[d]), xi = __half2float(base[d + 64]);
        __half* o = Kh + (size_t)kvh * SEQ * HDIM + (size_t)pos * HDIM;
        o[d]      = __float2half(xr * c - xi * s);
        o[d + 64] = __float2half(xr * s + xi * c);
    }
#pragma unroll
    for (int j = 0; j < 2; j++) {                // V: copy 512 halfs
        int e = tid * 2 + j;
        int kvh = e >> 7, d = e & 127;
        Vh[(size_t)kvh * SEQ * HDIM + (size_t)pos * HDIM + d] = row[2560 + e];
    }
}

// ---------------------------------------------------------------------------
// Flash attention v5: register-P + fully warp-local softmax stats.
// 8 warps = 4 row-groups x 2 kv-groups; each warp runs an independent online
// softmax over its 32-kv slice (m,l in registers, NO cross-warp exchange in
// the loop -> 1 barrier/iter). kv-group partials merged once at finalize:
//   O = (O0 e^{m0-M} + O1 e^{m1-M}) / (l0 e^{m0-M} + l1 e^{m1-M}).
// ---------------------------------------------------------------------------
#define AST 136
#define AS_Q  0
#define AS_K  (64 * AST)          // 2 buffers (aliased as obuf at finalize)
#define AS_V  (AS_K + 2 * 64 * AST)
#define AS_ST (AS_V + 2 * 64 * AST)   // halfs offset; then 128 floats of stats
#define ATTN_SMEM_BYTES (AS_ST * 2 + 128 * 4)
#define OBUF_STRIDE 132

__global__ __launch_bounds__(256, 2) void attn5(const __half* __restrict__ Qh,
                                                const __half* __restrict__ Kh,
                                                const __half* __restrict__ Vh,
                                                __half* __restrict__ AOh) {
    extern __shared__ __half smh[];
    const uint32_t sb = (uint32_t)__cvta_generic_to_shared(smh);
    float* pm = (float*)(smh + AS_ST);    // [64] wg1 m at finalize
    float* pl = pm + 64;                  // [64] wg1 l at finalize
    float* obuf = (float*)(smh + AS_K);   // 64 x 132 fp32, finalize only

    const int tid = threadIdx.x, wid = tid >> 5, lane = tid & 31;
    const int gr = lane >> 2, qc = lane & 3;
    const int q0 = blockIdx.x * 64;
    const int h  = blockIdx.y;
    const int kvh = h >> 2;
    const int wg   = wid >> 2;           // kv-group: 0 -> kv 0-31, 1 -> 32-63
    const int wrow = (wid & 3) * 16;     // q-row base
    const int wn32 = wg * 32;
    const int r0 = wrow + gr, r1 = wrow + gr + 8;

    const __half* Kp = Kh + (size_t)kvh * SEQ * HDIM;
    const __half* Vp = Vh + (size_t)kvh * SEQ * HDIM;

    // prologue: Q + K0/V0 (each tile: 64 rows x 256B = 1024 x 16B chunks)
    {
        const __half* Qp = Qh + (size_t)h * SEQ * HDIM + (size_t)q0 * HDIM;
#pragma unroll
        for (int i = 0; i < 4; i++) {
            int lin = tid + 256 * i;
            int r = lin >> 4, c = lin & 15;
            cpa16(sb + (AS_Q + r * AST + c * 8) * 2, Qp + (size_t)r * HDIM + c * 8);
            cpa16(sb + (AS_K + r * AST + c * 8) * 2, Kp + (size_t)r * HDIM + c * 8);
            cpa16(sb + (AS_V + r * AST + c * 8) * 2, Vp + (size_t)r * HDIM + c * 8);
        }
        CP_COMMIT();
    }

    float m0 = -INFINITY, m1 = -INFINITY, l0 = 0.f, l1 = 0.f;
    float o[16][4];
#pragma unroll
    for (int j = 0; j < 16; j++)
#pragma unroll
        for (int i = 0; i < 4; i++) o[j][i] = 0.f;

    for (int t = 0; t < 64; t++) {
        CP_WAIT(0);
        __syncthreads();   // sync1: tile t ready; iter t-1 done everywhere
        if (t + 1 < 64) {  // prefetch t+1 into buffer last read at iter t-1
            const int k1 = (t + 1) * 64, buf = (t + 1) & 1;
#pragma unroll
            for (int i = 0; i < 4; i++) {
                int lin = tid + 256 * i;
                int r = lin >> 4, c = lin & 15;
                cpa16(sb + (AS_K + buf * 64 * AST + r * AST + c * 8) * 2,
                      Kp + (size_t)(k1 + r) * HDIM + c * 8);
                cpa16(sb + (AS_V + buf * 64 * AST + r * AST + c * 8) * 2,
                      Vp + (size_t)(k1 + r) * HDIM + c * 8);
            }
            CP_COMMIT();
        }
        const uint32_t kbase = AS_K + (uint32_t)(t & 1) * 64 * AST;
        const uint32_t vbase = AS_V + (uint32_t)(t & 1) * 64 * AST;

        // ---- scores: warp computes S[16 rows][32 kv] in regs ----
        float s[4][4];
#pragma unroll
        for (int nt = 0; nt < 4; nt++)
#pragma unroll
            for (int i = 0; i < 4; i++) s[nt][i] = 0.f;

#pragma unroll
        for (int kk = 0; kk < 8; kk++) {
            uint32_t a[4], b[4][2];
            {
                int row = wrow + (lane & 15);
                int col = kk * 16 + (lane >> 4) * 8;
                ldsm4(a[0], a[1], a[2], a[3], sb + (AS_Q + row * AST + col) * 2);
            }
#pragma unroll
            for (int ntp = 0; ntp < 2; ntp++) {
                int row = wn32 + ntp * 16 + (lane & 7) + ((lane >> 4) & 1) * 8;
                int col = kk * 16 + ((lane >> 3) & 1) * 8;
                ldsm4(b[2 * ntp][0], b[2 * ntp][1], b[2 * ntp + 1][0], b[2 * ntp + 1][1],
                      sb + (kbase + row * AST + col) * 2);
            }
#pragma unroll
            for (int nt = 0; nt < 4; nt++)
                mma_f16(s[nt], a, b[nt]);
        }

        // ---- warp-local online softmax (no cross-warp exchange) ----
        float rmax0 = -INFINITY, rmax1 = -INFINITY;
#pragma unroll
        for (int nt = 0; nt < 4; nt++) {
            rmax0 = fmaxf(rmax0, fmaxf(s[nt][0], s[nt][1]));
            rmax1 = fmaxf(rmax1, fmaxf(s[nt][2], s[nt][3]));
        }
        rmax0 = fmaxf(rmax0, __shfl_xor_sync(0xffffffffu, rmax0, 1));
        rmax0 = fmaxf(rmax0, __shfl_xor_sync(0xffffffffu, rmax0, 2));
        rmax1 = fmaxf(rmax1, __shfl_xor_sync(0xffffffffu, rmax1, 1));
        rmax1 = fmaxf(rmax1, __shfl_xor_sync(0xffffffffu, rmax1, 2));

        float mnew0 = fmaxf(m0, rmax0);
        float mnew1 = fmaxf(m1, rmax1);
        float als0 = __expf(m0 - mnew0);
        float als1 = __expf(m1 - mnew1);
        m0 = mnew0;
        m1 = mnew1;

        float sum0 = 0.f, sum1 = 0.f;
#pragma unroll
        for (int nt = 0; nt < 4; nt++) {
            s[nt][0] = __expf(s[nt][0] - mnew0);
            s[nt][1] = __expf(s[nt][1] - mnew0);
            s[nt][2] = __expf(s[nt][2] - mnew1);
            s[nt][3] = __expf(s[nt][3] - mnew1);
            sum0 += s[nt][0] + s[nt][1];
            sum1 += s[nt][2] + s[nt][3];
        }
        sum0 += __shfl_xor_sync(0xffffffffu, sum0, 1);
        sum0 += __shfl_xor_sync(0xffffffffu, sum0, 2);
        sum1 += __shfl_xor_sync(0xffffffffu, sum1, 1);
        sum1 += __shfl_xor_sync(0xffffffffu, sum1, 2);
        l0 = l0 * als0 + sum0;
        l1 = l1 * als1 + sum1;

        // ---- rescale partial O, then O += P @ V (P from regs) ----
#pragma unroll
        for (int j = 0; j < 16; j++) {
            o[j][0] *= als0; o[j][1] *= als0;
            o[j][2] *= als1; o[j][3] *= als1;
        }
#pragma unroll
        for (int c = 0; c < 2; c++) {
            uint32_t a[4];
            a[0] = pack_h2(s[2 * c][0], s[2 * c][1]);
            a[1] = pack_h2(s[2 * c][2], s[2 * c][3]);
            a[2] = pack_h2(s[2 * c + 1][0], s[2 * c + 1][1]);
            a[3] = pack_h2(s[2 * c + 1][2], s[2 * c + 1][3]);
            const int vrow = wn32 + c * 16 + (lane & 7) + ((lane >> 4) << 3);
#pragma unroll
            for (int nt2 = 0; nt2 < 8; nt2++) {
                int vcol = nt2 * 16 + ((lane >> 3) & 1) * 8;
                uint32_t b0, b1, b2, b3;
                ldsm4t(b0, b1, b2, b3, sb + (vbase + vrow * AST + vcol) * 2);
                uint32_t p0[2] = {b0, b2};
                uint32_t p1[2] = {b1, b3};
                mma_f16(o[nt2 * 2],     a, p0);
                mma_f16(o[nt2 * 2 + 1], a, p1);
            }
        }
    }

    // ---- finalize: merge kv-group partials (obuf aliases K region) ----
    __syncthreads();
    if (wg == 1) {
        if (qc == 0) { pm[r0] = m0; pm[r1] = m1; pl[r0] = l0; pl[r1] = l1; }
#pragma unroll
        for (int j = 0; j < 16; j++) {
            *(float2*)&obuf[r0 * OBUF_STRIDE + j * 8 + 2 * qc] = make_float2(o[j][0], o[j][1]);
            *(float2*)&obuf[r1 * OBUF_STRIDE + j * 8 + 2 * qc] = make_float2(o[j][2], o[j][3]);
        }
    }
    __syncthreads();
    if (wg == 0) {
        float mp0 = pm[r0], lp0 = pl[r0];
        float mp1 = pm[r1], lp1 = pl[r1];
        float M0 = fmaxf(m0, mp0), M1 = fmaxf(m1, mp1);
        float f00 = __expf(m0 - M0), f01 = __expf(mp0 - M0);
        float f10 = __expf(m1 - M1), f11 = __expf(mp1 - M1);
        float inv0 = 1.f / (l0 * f00 + lp0 * f01);
        float inv1 = 1.f / (l1 * f10 + lp1 * f11);
#pragma unroll
        for (int j = 0; j < 16; j++) {
            float2 p0 = *(float2*)&obuf[r0 * OBUF_STRIDE + j * 8 + 2 * qc];
            float2 p1 = *(float2*)&obuf[r1 * OBUF_STRIDE + j * 8 + 2 * qc];
            int c = j * 8 + 2 * qc;
            size_t o0 = (size_t)(q0 + r0) * DMODEL + h * HDIM + c;
            size_t o1 = (size_t)(q0 + r1) * DMODEL + h * HDIM + c;
            *(uint32_t*)(AOh + o0) = pack_h2((o[j][0] * f00 + p0.x * f01) * inv0,
                                             (o[j][1] * f00 + p0.y * f01) * inv0);
            *(uint32_t*)(AOh + o1) = pack_h2((o[j][2] * f10 + p1.x * f11) * inv1,
                                             (o[j][3] * f10 + p1.y * f11) * inv1);
        }
    }
}

// ---------------------------------------------------------------------------
// launch
// ---------------------------------------------------------------------------
extern "C" void kernel_launch(void* const* d_in, const int* in_sizes, int n_in,
                              void* d_out, int out_size) {
    (void)in_sizes; (void)n_in; (void)out_size;
    const float* X  = (const float*)d_in[0];
    const float* Wq = (const float*)d_in[1];
    const float* Wk = (const float*)d_in[2];
    const float* Wv = (const float*)d_in[3];
    const float* Wo = (const float*)d_in[4];
    float* out = (float*)d_out;

    __half *QKVh, *Wt, *Wot, *Xh, *Qh, *Kh, *Vh, *AOh;
    cudaGetSymbolAddress((void**)&QKVh, g_QKVh);
    cudaGetSymbolAddress((void**)&Wt, g_Wt);
    cudaGetSymbolAddress((void**)&Wot, g_Wot);
    cudaGetSymbolAddress((void**)&Xh, g_Xh);
    cudaGetSymbolAddress((void**)&Qh, g_Qh);
    cudaGetSymbolAddress((void**)&Kh, g_Kh);
    cudaGetSymbolAddress((void**)&Vh, g_Vh);
    cudaGetSymbolAddress((void**)&AOh, g_AOh);

    cudaFuncSetAttribute(gemm_f16, cudaFuncAttributeMaxDynamicSharedMemorySize,
                         GEMM_SMEM_BYTES);
    cudaFuncSetAttribute(gemm_f16h, cudaFuncAttributeMaxDynamicSharedMemorySize,
                         GEMM_SMEM_BYTES);
    cudaFuncSetAttribute(attn5, cudaFuncAttributeMaxDynamicSharedMemorySize,
                         ATTN_SMEM_BYTES);

    // 1) weight transposes + X fp16 conversion
    transpose_f16<<<dim3(64, 64), dim3(32, 8)>>>(Wq, Wt, DMODEL, 2048);
    transpose_f16<<<dim3(16, 64), dim3(32, 8)>>>(Wk, Wt + 2048 * DMODEL, DMODEL, 512);
    transpose_f16<<<dim3(16, 64), dim3(32, 8)>>>(Wv, Wt + 2560 * DMODEL, DMODEL, 512);
    transpose_f16<<<dim3(64, 64), dim3(32, 8)>>>(Wo, Wot, DMODEL, 2048);
    convert_f16<<<SEQ * DMODEL / 4 / 256, 256>>>(X, Xh, SEQ * DMODEL / 4);

    // 2) fused QKV projection -> fp16 output (halved traffic)
    gemm_f16h<<<dim3(NQKV / 128, SEQ / 128), 256, GEMM_SMEM_BYTES>>>(
        Xh, Wt, QKVh, NQKV, DMODEL);

    // 3) RoPE + per-head fp16 planes (fp16 in)
    rope_convert<<<SEQ, 256>>>(QKVh, Qh, Kh, Vh);

    // 4) attention (register-P, warp-local stats, 1 barrier/iter)
    attn5<<<dim3(SEQ / 64, NHEAD), 256, ATTN_SMEM_BYTES>>>(Qh, Kh, Vh, AOh);

    // 5) output projection (fp32 out)
    gemm_f16<<<dim3(DMODEL / 128, SEQ / 128), 256, GEMM_SMEM_BYTES>>>(
        AOh, Wot, out, DMODEL, DMODEL);
}

// round 15
// speedup vs baseline: 1.4458x; 1.0168x over previous
#include <cuda_runtime.h>
#include <cuda_fp16.h>
#include <math.h>
#include <stdint.h>

// Problem constants
#define SEQ    4096
#define DMODEL 2048
#define NHEAD  16
#define NKV    4
#define HDIM   128
#define NQKV   3072
#define SCALE  0.08838834764831845f   // 1/sqrt(128)

// ---------------------------------------------------------------------------
// Scratch (device globals; no allocation allowed)
// ---------------------------------------------------------------------------
__device__ __half g_Wt[NQKV * DMODEL];        // fused Wq|Wk|Wv transposed [N,K]
__device__ __half g_Wot[DMODEL * DMODEL];     // Wo transposed [N,K]
__device__ __half g_Xh[SEQ * DMODEL];         // X fp16
__device__ __half g_Qh[NHEAD * SEQ * HDIM];   // per-head planes, rope+scale
__device__ __half g_Kh[NKV * SEQ * HDIM];     // rope applied
__device__ __half g_Vh[NKV * SEQ * HDIM];
__device__ __half g_AOh[SEQ * DMODEL];        // attention out fp16
__device__ float2 g_T1[16 * 64];              // cos/sin of a*256*inv_d
__device__ float2 g_T2[256 * 64];             // cos/sin of b*inv_d

// ---------------------------------------------------------------------------
// helpers
// ---------------------------------------------------------------------------
__device__ __forceinline__ void mma_f16(float c[4], const uint32_t a[4], const uint32_t b[2]) {
    asm volatile(
        "mma.sync.aligned.m16n8k16.row.col.f32.f16.f16.f32 "
        "{%0,%1,%2,%3}, {%4,%5,%6,%7}, {%8,%9}, {%0,%1,%2,%3};\n"
        : "+f"(c[0]), "+f"(c[1]), "+f"(c[2]), "+f"(c[3])
        : "r"(a[0]), "r"(a[1]), "r"(a[2]), "r"(a[3]), "r"(b[0]), "r"(b[1]));
}

__device__ __forceinline__ uint32_t pack_h2(float x, float y) {
    __half2 h = __floats2half2_rn(x, y);
    return *(uint32_t*)&h;
}

__device__ __forceinline__ void cpa16(uint32_t saddr, const void* g) {
    asm volatile("cp.async.cg.shared.global [%0], [%1], 16;" :: "r"(saddr), "l"(g));
}
#define CP_COMMIT() asm volatile("cp.async.commit_group;" ::: "memory")
#define CP_WAIT(n)  asm volatile("cp.async.wait_group %0;" :: "n"(n) : "memory")

__device__ __forceinline__ void ldsm4(uint32_t& r0, uint32_t& r1, uint32_t& r2, uint32_t& r3,
                                      uint32_t addr) {
    asm volatile("ldmatrix.sync.aligned.m8n8.x4.shared.b16 {%0,%1,%2,%3}, [%4];"
                 : "=r"(r0), "=r"(r1), "=r"(r2), "=r"(r3) : "r"(addr));
}
__device__ __forceinline__ void ldsm4t(uint32_t& r0, uint32_t& r1, uint32_t& r2, uint32_t& r3,
                                       uint32_t addr) {
    asm volatile("ldmatrix.sync.aligned.m8n8.x4.trans.shared.b16 {%0,%1,%2,%3}, [%4];"
                 : "=r"(r0), "=r"(r1), "=r"(r2), "=r"(r3) : "r"(addr));
}

// ---------------------------------------------------------------------------
// prep kernels
// ---------------------------------------------------------------------------
__global__ __launch_bounds__(256) void rope_tables() {
    int idx = blockIdx.x * 256 + threadIdx.x;
    if (idx >= 1024 + 16384) return;
    double ang;
    float2* dst;
    if (idx < 1024) {
        int a = idx >> 6, d = idx & 63;
        double inv = exp(-(double)d * (log(10000.0) / 64.0));
        ang = 256.0 * (double)a * inv;
        dst = g_T1 + idx;
    } else {
        int e = idx - 1024;
        int b = e >> 6, d = e & 63;
        double inv = exp(-(double)d * (log(10000.0) / 64.0));
        ang = (double)b * inv;
        dst = g_T2 + e;
    }
    double s, c;
    sincos(ang, &s, &c);
    *dst = make_float2((float)c, (float)s);
}

__global__ __launch_bounds__(256) void transpose_f16(const float* __restrict__ W,
                                                     __half* __restrict__ T,
                                                     int K, int N) {
    __shared__ float t[32][33];
    int tx = threadIdx.x, ty = threadIdx.y;
    int n0 = blockIdx.x * 32, k0 = blockIdx.y * 32;
#pragma unroll
    for (int i = 0; i < 4; i++)
        t[ty + 8 * i][tx] = W[(size_t)(k0 + ty + 8 * i) * N + n0 + tx];
    __syncthreads();
#pragma unroll
    for (int i = 0; i < 4; i++)
        T[(size_t)(n0 + ty + 8 * i) * K + k0 + tx] = __float2half(t[tx][ty + 8 * i]);
}

__global__ __launch_bounds__(256) void convert_f16(const float* __restrict__ src,
                                                   __half* __restrict__ dst, int n4) {
    int i = blockIdx.x * blockDim.x + threadIdx.x;
    if (i >= n4) return;
    float4 v = ((const float4*)src)[i];
    uint2 p;
    p.x = pack_h2(v.x, v.y);
    p.y = pack_h2(v.z, v.w);
    ((uint2*)dst)[i] = p;
}

// ---------------------------------------------------------------------------
// fp16 GEMM core (block 128x128, BK=64, 2-stage cp.async, ldmatrix, occ 2)
// Variadic macro so epilogue blocks may contain top-level commas.
// ---------------------------------------------------------------------------
#define GSS 72
#define GS_TILE  (128 * GSS)
#define GS_STAGE (2 * GS_TILE)
#define GEMM_SMEM_BYTES (2 * GS_STAGE * 2)

#define GEMM_BODY(...)                                                          \
    extern __shared__ __half gsm[];                                             \
    const uint32_t sb = (uint32_t)__cvta_generic_to_shared(gsm);                \
    const int tid = threadIdx.x, wid = tid >> 5, lane = tid & 31;               \
    const int gr = lane >> 2, qc = lane & 3;                                    \
    const int bm = blockIdx.y * 128, bn = blockIdx.x * 128;                     \
    const int wm = (wid & 3) * 32, wn = (wid >> 2) * 64;                        \
    const int T = K >> 6;                                                       \
    float acc[2][8][4];                                                         \
    _Pragma("unroll")                                                           \
    for (int mt = 0; mt < 2; mt++)                                              \
        _Pragma("unroll")                                                       \
        for (int nt = 0; nt < 8; nt++)                                          \
            _Pragma("unroll")                                                   \
            for (int i = 0; i < 4; i++) acc[mt][nt][i] = 0.f;                   \
    auto load_chunk = [&](int t) {                                              \
        const int k0 = t * 64;                                                  \
        const uint32_t stage = (t & 1) ? (uint32_t)GS_STAGE : 0u;               \
        _Pragma("unroll")                                                       \
        for (int tile = 0; tile < 2; tile++) {                                  \
            const __half* g = (tile == 0) ? A : Bt;                             \
            const int gbase = (tile == 0) ? bm : bn;                            \
            _Pragma("unroll")                                                   \
            for (int i = 0; i < 4; i++) {                                       \
                int idx = tid + 256 * i;                                        \
                int r = idx >> 3, c = idx & 7;                                  \
                cpa16(sb + (stage + tile * GS_TILE + r * GSS + c * 8) * 2,      \
                      g + (size_t)(gbase + r) * K + k0 + c * 8);                \
            }                                                                   \
        }                                                                       \
    };                                                                          \
    load_chunk(0);                                                              \
    CP_COMMIT();                                                                \
    for (int t = 0; t < T; t++) {                                               \
        if (t + 1 < T) { load_chunk(t + 1); CP_COMMIT(); CP_WAIT(1); }          \
        else           { CP_WAIT(0); }                                          \
        __syncthreads();                                                        \
        const uint32_t stage = (t & 1) ? (uint32_t)GS_STAGE : 0u;               \
        _Pragma("unroll")                                                       \
        for (int kk = 0; kk < 4; kk++) {                                        \
            uint32_t b[8][2];                                                   \
            _Pragma("unroll")                                                   \
            for (int ntp = 0; ntp < 4; ntp++) {                                 \
                int row = wn + ntp * 16 + (lane & 7) + ((lane >> 4) & 1) * 8;   \
                int col = kk * 16 + ((lane >> 3) & 1) * 8;                      \
                ldsm4(b[2 * ntp][0], b[2 * ntp][1], b[2 * ntp + 1][0],          \
                      b[2 * ntp + 1][1],                                        \
                      sb + (stage + GS_TILE + row * GSS + col) * 2);            \
            }                                                                   \
            uint32_t a[2][4];                                                   \
            _Pragma("unroll")                                                   \
            for (int mt = 0; mt < 2; mt++) {                                    \
                int row = wm + mt * 16 + (lane & 15);                           \
                int col = kk * 16 + (lane >> 4) * 8;                            \
                ldsm4(a[mt][0], a[mt][1], a[mt][2], a[mt][3],                   \
                      sb + (stage + row * GSS + col) * 2);                      \
            }                                                                   \
            _Pragma("unroll")                                                   \
            for (int mt = 0; mt < 2; mt++)                                      \
                _Pragma("unroll")                                               \
                for (int nt = 0; nt < 8; nt++)                                  \
                    mma_f16(acc[mt][nt], a[mt], b[nt]);                         \
        }                                                                       \
        __syncthreads();                                                        \
    }                                                                           \
    __VA_ARGS__

// out-projection: fp32 C
__global__ __launch_bounds__(256, 2) void gemm_f16(
    const __half* __restrict__ A, const __half* __restrict__ Bt,
    float* __restrict__ C, int N, int K) {
    GEMM_BODY({
#pragma unroll
        for (int mt = 0; mt < 2; mt++) {
            int r = bm + wm + mt * 16 + gr;
#pragma unroll
            for (int nt = 0; nt < 8; nt++) {
                int c = bn + wn + nt * 8 + 2 * qc;
                *(float2*)(C + (size_t)r * N + c) =
                    make_float2(acc[mt][nt][0], acc[mt][nt][1]);
                *(float2*)(C + (size_t)(r + 8) * N + c) =
                    make_float2(acc[mt][nt][2], acc[mt][nt][3]);
            }
        }
    })
}

// QKV projection with fused RoPE epilogue -> per-head fp16 planes.
// bn tile maps to exactly one plane: Q (bn<2048, rope+scale), K (<2560, rope),
// V (else, direct). Q/K: stage acc in smem Ct[128][132] (EVEN stride: float2
// stays 8B-aligned), rotate (d,d+64) pairs via angle-addition from g_T1/g_T2,
// write 64B-contiguous plane chunks.
#define CTS 132
__global__ __launch_bounds__(256, 2) void gemm_qkv_rope(
    const __half* __restrict__ A, const __half* __restrict__ Bt,
    __half* __restrict__ Qh, __half* __restrict__ Kh, __half* __restrict__ Vh,
    int N, int K) {
    GEMM_BODY({
        if (bn >= 2560) {
            __half* plane = Vh + (size_t)((bn - 2560) >> 7) * SEQ * HDIM;
#pragma unroll
            for (int mt = 0; mt < 2; mt++) {
                int pos = bm + wm + mt * 16 + gr;
#pragma unroll
                for (int nt = 0; nt < 8; nt++) {
                    int c = wn + nt * 8 + 2 * qc;
                    *(uint32_t*)(plane + (size_t)pos * HDIM + c) =
                        pack_h2(acc[mt][nt][0], acc[mt][nt][1]);
                    *(uint32_t*)(plane + (size_t)(pos + 8) * HDIM + c) =
                        pack_h2(acc[mt][nt][2], acc[mt][nt][3]);
                }
            }
        } else {
            const bool isq = (bn < 2048);
            __half* plane = isq ? (Qh + (size_t)(bn >> 7) * SEQ * HDIM)
                                : (Kh + (size_t)((bn - 2048) >> 7) * SEQ * HDIM);
            const float sc = isq ? SCALE : 1.f;
            float* Ct = (float*)gsm;   // 128 x 132 fp32 = 67584 B <= smem budget
#pragma unroll
            for (int mt = 0; mt < 2; mt++) {
                int r = wm + mt * 16 + gr;
#pragma unroll
                for (int nt = 0; nt < 8; nt++) {
                    int c = wn + nt * 8 + 2 * qc;
                    *(float2*)&Ct[r * CTS + c] =
                        make_float2(acc[mt][nt][0], acc[mt][nt][1]);
                    *(float2*)&Ct[(r + 8) * CTS + c] =
                        make_float2(acc[mt][nt][2], acc[mt][nt][3]);
                }
            }
            __syncthreads();
            const int row = tid >> 1;
            const int cb = (tid & 1) * 32;
            const int pos = bm + row;
            const float2* t1 = g_T1 + ((pos >> 8) << 6);
            const float2* t2 = g_T2 + ((pos & 255) << 6);
            uint32_t outlo[16];
            uint32_t outhi[16];
#pragma unroll
            for (int j = 0; j < 32; j += 2) {
                int d0 = cb + j;
                int d1 = cb + j + 1;
                float2 A0 = t1[d0];
                float2 B0 = t2[d0];
                float2 A1 = t1[d1];
                float2 B1 = t2[d1];
                float c0 = A0.x * B0.x - A0.y * B0.y;
                float s0 = A0.y * B0.x + A0.x * B0.y;
                float c1 = A1.x * B1.x - A1.y * B1.y;
                float s1 = A1.y * B1.x + A1.x * B1.y;
                float xr0 = Ct[row * CTS + d0];
                float xi0 = Ct[row * CTS + d0 + 64];
                float xr1 = Ct[row * CTS + d1];
                float xi1 = Ct[row * CTS + d1 + 64];
                outlo[j >> 1] = pack_h2((xr0 * c0 - xi0 * s0) * sc,
                                        (xr1 * c1 - xi1 * s1) * sc);
                outhi[j >> 1] = pack_h2((xr0 * s0 + xi0 * c0) * sc,
                                        (xr1 * s1 + xi1 * c1) * sc);
            }
            __half* orow = plane + (size_t)pos * HDIM + cb;
#pragma unroll
            for (int u = 0; u < 4; u++) {
                ((uint4*)orow)[u] = ((uint4*)outlo)[u];
                ((uint4*)(orow + 64))[u] = ((uint4*)outhi)[u];
            }
        }
    })
}

// ---------------------------------------------------------------------------
// Flash attention v5 (unchanged from round 12): register-P + warp-local stats,
// 1 barrier/iter; kv-group partials merged at finalize.
// ---------------------------------------------------------------------------
#define AST 136
#define AS_Q  0
#define AS_K  (64 * AST)
#define AS_V  (AS_K + 2 * 64 * AST)
#define AS_ST (AS_V + 2 * 64 * AST)
#define ATTN_SMEM_BYTES (AS_ST * 2 + 128 * 4)
#define OBUF_STRIDE 132

__global__ __launch_bounds__(256, 2) void attn5(const __half* __restrict__ Qh,
                                                const __half* __restrict__ Kh,
                                                const __half* __restrict__ Vh,
                                                __half* __restrict__ AOh) {
    extern __shared__ __half smh[];
    const uint32_t sb = (uint32_t)__cvta_generic_to_shared(smh);
    float* pm = (float*)(smh + AS_ST);
    float* pl = pm + 64;
    float* obuf = (float*)(smh + AS_K);

    const int tid = threadIdx.x, wid = tid >> 5, lane = tid & 31;
    const int gr = lane >> 2, qc = lane & 3;
    const int q0 = blockIdx.x * 64;
    const int h  = blockIdx.y;
    const int kvh = h >> 2;
    const int wg   = wid >> 2;
    const int wrow = (wid & 3) * 16;
    const int wn32 = wg * 32;
    const int r0 = wrow + gr, r1 = wrow + gr + 8;

    const __half* Kp = Kh + (size_t)kvh * SEQ * HDIM;
    const __half* Vp = Vh + (size_t)kvh * SEQ * HDIM;

    {
        const __half* Qp = Qh + (size_t)h * SEQ * HDIM + (size_t)q0 * HDIM;
#pragma unroll
        for (int i = 0; i < 4; i++) {
            int lin = tid + 256 * i;
            int r = lin >> 4, c = lin & 15;
            cpa16(sb + (AS_Q + r * AST + c * 8) * 2, Qp + (size_t)r * HDIM + c * 8);
            cpa16(sb + (AS_K + r * AST + c * 8) * 2, Kp + (size_t)r * HDIM + c * 8);
            cpa16(sb + (AS_V + r * AST + c * 8) * 2, Vp + (size_t)r * HDIM + c * 8);
        }
        CP_COMMIT();
    }

    float m0 = -INFINITY, m1 = -INFINITY, l0 = 0.f, l1 = 0.f;
    float o[16][4];
#pragma unroll
    for (int j = 0; j < 16; j++)
#pragma unroll
        for (int i = 0; i < 4; i++) o[j][i] = 0.f;

    for (int t = 0; t < 64; t++) {
        CP_WAIT(0);
        __syncthreads();
        if (t + 1 < 64) {
            const int k1 = (t + 1) * 64, buf = (t + 1) & 1;
#pragma unroll
            for (int i = 0; i < 4; i++) {
                int lin = tid + 256 * i;
                int r = lin >> 4, c = lin & 15;
                cpa16(sb + (AS_K + buf * 64 * AST + r * AST + c * 8) * 2,
                      Kp + (size_t)(k1 + r) * HDIM + c * 8);
                cpa16(sb + (AS_V + buf * 64 * AST + r * AST + c * 8) * 2,
                      Vp + (size_t)(k1 + r) * HDIM + c * 8);
            }
            CP_COMMIT();
        }
        const uint32_t kbase = AS_K + (uint32_t)(t & 1) * 64 * AST;
        const uint32_t vbase = AS_V + (uint32_t)(t & 1) * 64 * AST;

        float s[4][4];
#pragma unroll
        for (int nt = 0; nt < 4; nt++)
#pragma unroll
            for (int i = 0; i < 4; i++) s[nt][i] = 0.f;

#pragma unroll
        for (int kk = 0; kk < 8; kk++) {
            uint32_t a[4], b[4][2];
            {
                int row = wrow + (lane & 15);
                int col = kk * 16 + (lane >> 4) * 8;
                ldsm4(a[0], a[1], a[2], a[3], sb + (AS_Q + row * AST + col) * 2);
            }
#pragma unroll
            for (int ntp = 0; ntp < 2; ntp++) {
                int row = wn32 + ntp * 16 + (lane & 7) + ((lane >> 4) & 1) * 8;
                int col = kk * 16 + ((lane >> 3) & 1) * 8;
                ldsm4(b[2 * ntp][0], b[2 * ntp][1], b[2 * ntp + 1][0], b[2 * ntp + 1][1],
                      sb + (kbase + row * AST + col) * 2);
            }
#pragma unroll
            for (int nt = 0; nt < 4; nt++)
                mma_f16(s[nt], a, b[nt]);
        }

        float rmax0 = -INFINITY, rmax1 = -INFINITY;
#pragma unroll
        for (int nt = 0; nt < 4; nt++) {
            rmax0 = fmaxf(rmax0, fmaxf(s[nt][0], s[nt][1]));
            rmax1 = fmaxf(rmax1, fmaxf(s[nt][2], s[nt][3]));
        }
        rmax0 = fmaxf(rmax0, __shfl_xor_sync(0xffffffffu, rmax0, 1));
        rmax0 = fmaxf(rmax0, __shfl_xor_sync(0xffffffffu, rmax0, 2));
        rmax1 = fmaxf(rmax1, __shfl_xor_sync(0xffffffffu, rmax1, 1));
        rmax1 = fmaxf(rmax1, __shfl_xor_sync(0xffffffffu, rmax1, 2));

        float mnew0 = fmaxf(m0, rmax0);
        float mnew1 = fmaxf(m1, rmax1);
        float als0 = __expf(m0 - mnew0);
        float als1 = __expf(m1 - mnew1);
        m0 = mnew0;
        m1 = mnew1;

        float sum0 = 0.f, sum1 = 0.f;
#pragma unroll
        for (int nt = 0; nt < 4; nt++) {
            s[nt][0] = __expf(s[nt][0] - mnew0);
            s[nt][1] = __expf(s[nt][1] - mnew0);
            s[nt][2] = __expf(s[nt][2] - mnew1);
            s[nt][3] = __expf(s[nt][3] - mnew1);
            sum0 += s[nt][0] + s[nt][1];
            sum1 += s[nt][2] + s[nt][3];
        }
        sum0 += __shfl_xor_sync(0xffffffffu, sum0, 1);
        sum0 += __shfl_xor_sync(0xffffffffu, sum0, 2);
        sum1 += __shfl_xor_sync(0xffffffffu, sum1, 1);
        sum1 += __shfl_xor_sync(0xffffffffu, sum1, 2);
        l0 = l0 * als0 + sum0;
        l1 = l1 * als1 + sum1;

#pragma unroll
        for (int j = 0; j < 16; j++) {
            o[j][0] *= als0; o[j][1] *= als0;
            o[j][2] *= als1; o[j][3] *= als1;
        }
#pragma unroll
        for (int c = 0; c < 2; c++) {
            uint32_t a[4];
            a[0] = pack_h2(s[2 * c][0], s[2 * c][1]);
            a[1] = pack_h2(s[2 * c][2], s[2 * c][3]);
            a[2] = pack_h2(s[2 * c + 1][0], s[2 * c + 1][1]);
            a[3] = pack_h2(s[2 * c + 1][2], s[2 * c + 1][3]);
            const int vrow = wn32 + c * 16 + (lane & 7) + ((lane >> 4) << 3);
#pragma unroll
            for (int nt2 = 0; nt2 < 8; nt2++) {
                int vcol = nt2 * 16 + ((lane >> 3) & 1) * 8;
                uint32_t b0, b1, b2, b3;
                ldsm4t(b0, b1, b2, b3, sb + (vbase + vrow * AST + vcol) * 2);
                uint32_t p0[2] = {b0, b2};
                uint32_t p1[2] = {b1, b3};
                mma_f16(o[nt2 * 2],     a, p0);
                mma_f16(o[nt2 * 2 + 1], a, p1);
            }
        }
    }

    __syncthreads();
    if (wg == 1) {
        if (qc == 0) { pm[r0] = m0; pm[r1] = m1; pl[r0] = l0; pl[r1] = l1; }
#pragma unroll
        for (int j = 0; j < 16; j++) {
            *(float2*)&obuf[r0 * OBUF_STRIDE + j * 8 + 2 * qc] = make_float2(o[j][0], o[j][1]);
            *(float2*)&obuf[r1 * OBUF_STRIDE + j * 8 + 2 * qc] = make_float2(o[j][2], o[j][3]);
        }
    }
    __syncthreads();
    if (wg == 0) {
        float mp0 = pm[r0], lp0 = pl[r0];
        float mp1 = pm[r1], lp1 = pl[r1];
        float M0 = fmaxf(m0, mp0), M1 = fmaxf(m1, mp1);
        float f00 = __expf(m0 - M0), f01 = __expf(mp0 - M0);
        float f10 = __expf(m1 - M1), f11 = __expf(mp1 - M1);
        float inv0 = 1.f / (l0 * f00 + lp0 * f01);
        float inv1 = 1.f / (l1 * f10 + lp1 * f11);
#pragma unroll
        for (int j = 0; j < 16; j++) {
            float2 p0 = *(float2*)&obuf[r0 * OBUF_STRIDE + j * 8 + 2 * qc];
            float2 p1 = *(float2*)&obuf[r1 * OBUF_STRIDE + j * 8 + 2 * qc];
            int c = j * 8 + 2 * qc;
            size_t o0 = (size_t)(q0 + r0) * DMODEL + h * HDIM + c;
            size_t o1 = (size_t)(q0 + r1) * DMODEL + h * HDIM + c;
            *(uint32_t*)(AOh + o0) = pack_h2((o[j][0] * f00 + p0.x * f01) * inv0,
                                             (o[j][1] * f00 + p0.y * f01) * inv0);
            *(uint32_t*)(AOh + o1) = pack_h2((o[j][2] * f10 + p1.x * f11) * inv1,
                                             (o[j][3] * f10 + p1.y * f11) * inv1);
        }
    }
}

// ---------------------------------------------------------------------------
// launch
// ---------------------------------------------------------------------------
extern "C" void kernel_launch(void* const* d_in, const int* in_sizes, int n_in,
                              void* d_out, int out_size) {
    (void)in_sizes; (void)n_in; (void)out_size;
    const float* X  = (const float*)d_in[0];
    const float* Wq = (const float*)d_in[1];
    const float* Wk = (const float*)d_in[2];
    const float* Wv = (const float*)d_in[3];
    const float* Wo = (const float*)d_in[4];
    float* out = (float*)d_out;

    __half *Wt, *Wot, *Xh, *Qh, *Kh, *Vh, *AOh;
    cudaGetSymbolAddress((void**)&Wt, g_Wt);
    cudaGetSymbolAddress((void**)&Wot, g_Wot);
    cudaGetSymbolAddress((void**)&Xh, g_Xh);
    cudaGetSymbolAddress((void**)&Qh, g_Qh);
    cudaGetSymbolAddress((void**)&Kh, g_Kh);
    cudaGetSymbolAddress((void**)&Vh, g_Vh);
    cudaGetSymbolAddress((void**)&AOh, g_AOh);

    cudaFuncSetAttribute(gemm_f16, cudaFuncAttributeMaxDynamicSharedMemorySize,
                         GEMM_SMEM_BYTES);
    cudaFuncSetAttribute(gemm_qkv_rope, cudaFuncAttributeMaxDynamicSharedMemorySize,
                         GEMM_SMEM_BYTES);
    cudaFuncSetAttribute(attn5, cudaFuncAttributeMaxDynamicSharedMemorySize,
                         ATTN_SMEM_BYTES);

    // 1) rope tables + weight transposes + X fp16 conversion
    rope_tables<<<68, 256>>>();
    transpose_f16<<<dim3(64, 64), dim3(32, 8)>>>(Wq, Wt, DMODEL, 2048);
    transpose_f16<<<dim3(16, 64), dim3(32, 8)>>>(Wk, Wt + 2048 * DMODEL, DMODEL, 512);
    transpose_f16<<<dim3(16, 64), dim3(32, 8)>>>(Wv, Wt + 2560 * DMODEL, DMODEL, 512);
    transpose_f16<<<dim3(64, 64), dim3(32, 8)>>>(Wo, Wot, DMODEL, 2048);
    convert_f16<<<SEQ * DMODEL / 4 / 256, 256>>>(X, Xh, SEQ * DMODEL / 4);

    // 2) fused QKV projection + RoPE -> per-head planes (no QKV round trip)
    gemm_qkv_rope<<<dim3(NQKV / 128, SEQ / 128), 256, GEMM_SMEM_BYTES>>>(
        Xh, Wt, Qh, Kh, Vh, NQKV, DMODEL);

    // 3) attention (register-P, warp-local stats, 1 barrier/iter)
    attn5<<<dim3(SEQ / 64, NHEAD), 256, ATTN_SMEM_BYTES>>>(Qh, Kh, Vh, AOh);

    // 4) output projection (fp32 out)
    gemm_f16<<<dim3(DMODEL / 128, SEQ / 128), 256, GEMM_SMEM_BYTES>>>(
        AOh, Wot, out, DMODEL, DMODEL);
}

// round 16
// speedup vs baseline: 1.5467x; 1.0697x over previous
#include <cuda_runtime.h>
#include <cuda_fp16.h>
#include <math.h>
#include <stdint.h>

// Problem constants
#define SEQ    4096
#define DMODEL 2048
#define NHEAD  16
#define NKV    4
#define HDIM   128
#define NQKV   3072
#define SCALE  0.08838834764831845f   // 1/sqrt(128)

// ---------------------------------------------------------------------------
// Scratch (device globals; no allocation allowed)
// ---------------------------------------------------------------------------
__device__ __half g_Wt[NQKV * DMODEL];        // fused Wq|Wk|Wv transposed [N,K]
__device__ __half g_Wot[DMODEL * DMODEL];     // Wo transposed [N,K]
__device__ __half g_Xh[SEQ * DMODEL];         // X fp16
__device__ __half g_Qh[NHEAD * SEQ * HDIM];   // per-head planes, rope+scale
__device__ __half g_Kh[NKV * SEQ * HDIM];     // rope applied
__device__ __half g_Vh[NKV * SEQ * HDIM];
__device__ __half g_AOh[SEQ * DMODEL];        // attention out fp16
__device__ float2 g_T1[16 * 64];              // cos/sin of a*256*inv_d
__device__ float2 g_T2[256 * 64];             // cos/sin of b*inv_d

// ---------------------------------------------------------------------------
// helpers
// ---------------------------------------------------------------------------
__device__ __forceinline__ void mma_f16(float c[4], const uint32_t a[4], const uint32_t b[2]) {
    asm volatile(
        "mma.sync.aligned.m16n8k16.row.col.f32.f16.f16.f32 "
        "{%0,%1,%2,%3}, {%4,%5,%6,%7}, {%8,%9}, {%0,%1,%2,%3};\n"
        : "+f"(c[0]), "+f"(c[1]), "+f"(c[2]), "+f"(c[3])
        : "r"(a[0]), "r"(a[1]), "r"(a[2]), "r"(a[3]), "r"(b[0]), "r"(b[1]));
}

__device__ __forceinline__ uint32_t pack_h2(float x, float y) {
    __half2 h = __floats2half2_rn(x, y);
    return *(uint32_t*)&h;
}

__device__ __forceinline__ void cpa16(uint32_t saddr, const void* g) {
    asm volatile("cp.async.cg.shared.global [%0], [%1], 16;" :: "r"(saddr), "l"(g));
}
#define CP_COMMIT() asm volatile("cp.async.commit_group;" ::: "memory")
#define CP_WAIT(n)  asm volatile("cp.async.wait_group %0;" :: "n"(n) : "memory")

__device__ __forceinline__ void ldsm4(uint32_t& r0, uint32_t& r1, uint32_t& r2, uint32_t& r3,
                                      uint32_t addr) {
    asm volatile("ldmatrix.sync.aligned.m8n8.x4.shared.b16 {%0,%1,%2,%3}, [%4];"
                 : "=r"(r0), "=r"(r1), "=r"(r2), "=r"(r3) : "r"(addr));
}
__device__ __forceinline__ void ldsm4t(uint32_t& r0, uint32_t& r1, uint32_t& r2, uint32_t& r3,
                                       uint32_t addr) {
    asm volatile("ldmatrix.sync.aligned.m8n8.x4.trans.shared.b16 {%0,%1,%2,%3}, [%4];"
                 : "=r"(r0), "=r"(r1), "=r"(r2), "=r"(r3) : "r"(addr));
}

// ---------------------------------------------------------------------------
// prep kernels
// ---------------------------------------------------------------------------
__global__ __launch_bounds__(256) void rope_tables() {
    int idx = blockIdx.x * 256 + threadIdx.x;
    if (idx >= 1024 + 16384) return;
    double ang;
    float2* dst;
    if (idx < 1024) {
        int a = idx >> 6, d = idx & 63;
        double inv = exp(-(double)d * (log(10000.0) / 64.0));
        ang = 256.0 * (double)a * inv;
        dst = g_T1 + idx;
    } else {
        int e = idx - 1024;
        int b = e >> 6, d = e & 63;
        double inv = exp(-(double)d * (log(10000.0) / 64.0));
        ang = (double)b * inv;
        dst = g_T2 + e;
    }
    double s, c;
    sincos(ang, &s, &c);
    *dst = make_float2((float)c, (float)s);
}

__global__ __launch_bounds__(256) void transpose_f16(const float* __restrict__ W,
                                                     __half* __restrict__ T,
                                                     int K, int N) {
    __shared__ float t[32][33];
    int tx = threadIdx.x, ty = threadIdx.y;
    int n0 = blockIdx.x * 32, k0 = blockIdx.y * 32;
#pragma unroll
    for (int i = 0; i < 4; i++)
        t[ty + 8 * i][tx] = W[(size_t)(k0 + ty + 8 * i) * N + n0 + tx];
    __syncthreads();
#pragma unroll
    for (int i = 0; i < 4; i++)
        T[(size_t)(n0 + ty + 8 * i) * K + k0 + tx] = __float2half(t[tx][ty + 8 * i]);
}

__global__ __launch_bounds__(256) void convert_f16(const float* __restrict__ src,
                                                   __half* __restrict__ dst, int n4) {
    int i = blockIdx.x * blockDim.x + threadIdx.x;
    if (i >= n4) return;
    float4 v = ((const float4*)src)[i];
    uint2 p;
    p.x = pack_h2(v.x, v.y);
    p.y = pack_h2(v.z, v.w);
    ((uint2*)dst)[i] = p;
}

// ---------------------------------------------------------------------------
// fp16 GEMM core (block 128x128, BK=64, 2-stage cp.async, ldmatrix, occ 2)
// ---------------------------------------------------------------------------
#define GSS 72
#define GS_TILE  (128 * GSS)
#define GS_STAGE (2 * GS_TILE)
#define GEMM_SMEM_BYTES (2 * GS_STAGE * 2)

#define GEMM_BODY(...)                                                          \
    extern __shared__ __half gsm[];                                             \
    const uint32_t sb = (uint32_t)__cvta_generic_to_shared(gsm);                \
    const int tid = threadIdx.x, wid = tid >> 5, lane = tid & 31;               \
    const int gr = lane >> 2, qc = lane & 3;                                    \
    const int bm = blockIdx.y * 128, bn = blockIdx.x * 128;                     \
    const int wm = (wid & 3) * 32, wn = (wid >> 2) * 64;                        \
    const int T = K >> 6;                                                       \
    float acc[2][8][4];                                                         \
    _Pragma("unroll")                                                           \
    for (int mt = 0; mt < 2; mt++)                                              \
        _Pragma("unroll")                                                       \
        for (int nt = 0; nt < 8; nt++)                                          \
            _Pragma("unroll")                                                   \
            for (int i = 0; i < 4; i++) acc[mt][nt][i] = 0.f;                   \
    auto load_chunk = [&](int t) {                                              \
        const int k0 = t * 64;                                                  \
        const uint32_t stage = (t & 1) ? (uint32_t)GS_STAGE : 0u;               \
        _Pragma("unroll")                                                       \
        for (int tile = 0; tile < 2; tile++) {                                  \
            const __half* g = (tile == 0) ? A : Bt;                             \
            const int gbase = (tile == 0) ? bm : bn;                            \
            _Pragma("unroll")                                                   \
            for (int i = 0; i < 4; i++) {                                       \
                int idx = tid + 256 * i;                                        \
                int r = idx >> 3, c = idx & 7;                                  \
                cpa16(sb + (stage + tile * GS_TILE + r * GSS + c * 8) * 2,      \
                      g + (size_t)(gbase + r) * K + k0 + c * 8);                \
            }                                                                   \
        }                                                                       \
    };                                                                          \
    load_chunk(0);                                                              \
    CP_COMMIT();                                                                \
    for (int t = 0; t < T; t++) {                                               \
        if (t + 1 < T) { load_chunk(t + 1); CP_COMMIT(); CP_WAIT(1); }          \
        else           { CP_WAIT(0); }                                          \
        __syncthreads();                                                        \
        const uint32_t stage = (t & 1) ? (uint32_t)GS_STAGE : 0u;               \
        _Pragma("unroll")                                                       \
        for (int kk = 0; kk < 4; kk++) {                                        \
            uint32_t b[8][2];                                                   \
            _Pragma("unroll")                                                   \
            for (int ntp = 0; ntp < 4; ntp++) {                                 \
                int row = wn + ntp * 16 + (lane & 7) + ((lane >> 4) & 1) * 8;   \
                int col = kk * 16 + ((lane >> 3) & 1) * 8;                      \
                ldsm4(b[2 * ntp][0], b[2 * ntp][1], b[2 * ntp + 1][0],          \
                      b[2 * ntp + 1][1],                                        \
                      sb + (stage + GS_TILE + row * GSS + col) * 2);            \
            }                                                                   \
            uint32_t a[2][4];                                                   \
            _Pragma("unroll")                                                   \
            for (int mt = 0; mt < 2; mt++) {                                    \
                int row = wm + mt * 16 + (lane & 15);                           \
                int col = kk * 16 + (lane >> 4) * 8;                            \
                ldsm4(a[mt][0], a[mt][1], a[mt][2], a[mt][3],                   \
                      sb + (stage + row * GSS + col) * 2);                      \
            }                                                                   \
            _Pragma("unroll")                                                   \
            for (int mt = 0; mt < 2; mt++)                                      \
                _Pragma("unroll")                                               \
                for (int nt = 0; nt < 8; nt++)                                  \
                    mma_f16(acc[mt][nt], a[mt], b[nt]);                         \
        }                                                                       \
        __syncthreads();                                                        \
    }                                                                           \
    __VA_ARGS__

// out-projection: fp32 C
__global__ __launch_bounds__(256, 2) void gemm_f16(
    const __half* __restrict__ A, const __half* __restrict__ Bt,
    float* __restrict__ C, int N, int K) {
    GEMM_BODY({
#pragma unroll
        for (int mt = 0; mt < 2; mt++) {
            int r = bm + wm + mt * 16 + gr;
#pragma unroll
            for (int nt = 0; nt < 8; nt++) {
                int c = bn + wn + nt * 8 + 2 * qc;
                *(float2*)(C + (size_t)r * N + c) =
                    make_float2(acc[mt][nt][0], acc[mt][nt][1]);
                *(float2*)(C + (size_t)(r + 8) * N + c) =
                    make_float2(acc[mt][nt][2], acc[mt][nt][3]);
            }
        }
    })
}

// QKV projection with fused RoPE epilogue -> per-head fp16 planes.
#define CTS 132
__global__ __launch_bounds__(256, 2) void gemm_qkv_rope(
    const __half* __restrict__ A, const __half* __restrict__ Bt,
    __half* __restrict__ Qh, __half* __restrict__ Kh, __half* __restrict__ Vh,
    int N, int K) {
    GEMM_BODY({
        if (bn >= 2560) {
            __half* plane = Vh + (size_t)((bn - 2560) >> 7) * SEQ * HDIM;
#pragma unroll
            for (int mt = 0; mt < 2; mt++) {
                int pos = bm + wm + mt * 16 + gr;
#pragma unroll
                for (int nt = 0; nt < 8; nt++) {
                    int c = wn + nt * 8 + 2 * qc;
                    *(uint32_t*)(plane + (size_t)pos * HDIM + c) =
                        pack_h2(acc[mt][nt][0], acc[mt][nt][1]);
                    *(uint32_t*)(plane + (size_t)(pos + 8) * HDIM + c) =
                        pack_h2(acc[mt][nt][2], acc[mt][nt][3]);
                }
            }
        } else {
            const bool isq = (bn < 2048);
            __half* plane = isq ? (Qh + (size_t)(bn >> 7) * SEQ * HDIM)
                                : (Kh + (size_t)((bn - 2048) >> 7) * SEQ * HDIM);
            const float sc = isq ? SCALE : 1.f;
            float* Ct = (float*)gsm;   // 128 x 132 fp32 (even stride: f2 aligned)
#pragma unroll
            for (int mt = 0; mt < 2; mt++) {
                int r = wm + mt * 16 + gr;
#pragma unroll
                for (int nt = 0; nt < 8; nt++) {
                    int c = wn + nt * 8 + 2 * qc;
                    *(float2*)&Ct[r * CTS + c] =
                        make_float2(acc[mt][nt][0], acc[mt][nt][1]);
                    *(float2*)&Ct[(r + 8) * CTS + c] =
                        make_float2(acc[mt][nt][2], acc[mt][nt][3]);
                }
            }
            __syncthreads();
            const int row = tid >> 1;
            const int cb = (tid & 1) * 32;
            const int pos = bm + row;
            const float2* t1 = g_T1 + ((pos >> 8) << 6);
            const float2* t2 = g_T2 + ((pos & 255) << 6);
            uint32_t outlo[16];
            uint32_t outhi[16];
#pragma unroll
            for (int j = 0; j < 32; j += 2) {
                int d0 = cb + j;
                int d1 = cb + j + 1;
                float2 A0 = t1[d0];
                float2 B0 = t2[d0];
                float2 A1 = t1[d1];
                float2 B1 = t2[d1];
                float c0 = A0.x * B0.x - A0.y * B0.y;
                float s0 = A0.y * B0.x + A0.x * B0.y;
                float c1 = A1.x * B1.x - A1.y * B1.y;
                float s1 = A1.y * B1.x + A1.x * B1.y;
                float xr0 = Ct[row * CTS + d0];
                float xi0 = Ct[row * CTS + d0 + 64];
                float xr1 = Ct[row * CTS + d1];
                float xi1 = Ct[row * CTS + d1 + 64];
                outlo[j >> 1] = pack_h2((xr0 * c0 - xi0 * s0) * sc,
                                        (xr1 * c1 - xi1 * s1) * sc);
                outhi[j >> 1] = pack_h2((xr0 * s0 + xi0 * c0) * sc,
                                        (xr1 * s1 + xi1 * c1) * sc);
            }
            __half* orow = plane + (size_t)pos * HDIM + cb;
#pragma unroll
            for (int u = 0; u < 4; u++) {
                ((uint4*)orow)[u] = ((uint4*)outlo)[u];
                ((uint4*)(orow + 64))[u] = ((uint4*)outhi)[u];
            }
        }
    })
}

// ---------------------------------------------------------------------------
// Flash attention v6: GQA-shared KV. Block = 64 q x 4 heads (one kv-head),
// 512 thr / 16 warps = 4 heads x 4 row-groups. Each warp owns 16 q-rows of
// one head and the FULL 64-kv width: completely warp-local softmax, no merge,
// no finalize buffers. K/V loaded once serves 4 heads -> KV L2 traffic / 4.
// smem: Q 256x136 (4 head planes) + K/V 2x64x136 each = ~136 KB, occ 1.
// ---------------------------------------------------------------------------
#define AST 136
#define A6_Q  0                        // 256 rows (4 heads x 64 q)
#define A6_K  (256 * AST)              // 2 buffers x 64 rows
#define A6_V  (A6_K + 2 * 64 * AST)    // 2 buffers x 64 rows
#define ATTN6_SMEM_BYTES ((A6_V + 2 * 64 * AST) * 2)

__global__ __launch_bounds__(512, 1) void attn6(const __half* __restrict__ Qh,
                                                const __half* __restrict__ Kh,
                                                const __half* __restrict__ Vh,
                                                __half* __restrict__ AOh) {
    extern __shared__ __half smh[];
    const uint32_t sb = (uint32_t)__cvta_generic_to_shared(smh);

    const int tid = threadIdx.x, wid = tid >> 5, lane = tid & 31;
    const int gr = lane >> 2, qc = lane & 3;
    const int q0 = blockIdx.x * 64;
    const int kvh = blockIdx.y;
    const int hl   = wid >> 2;            // head-local 0..3
    const int h    = kvh * 4 + hl;        // global head
    const int wrow = (wid & 3) * 16;      // q-row base within head tile
    const int r0 = wrow + gr, r1 = wrow + gr + 8;

    const __half* Kp = Kh + (size_t)kvh * SEQ * HDIM;
    const __half* Vp = Vh + (size_t)kvh * SEQ * HDIM;

    // prologue: Q (4 head planes, 256 rows = 4096 chunks) + K0/V0 (1024 each)
    {
#pragma unroll
        for (int i = 0; i < 8; i++) {
            int lin = tid + 512 * i;
            int r = lin >> 4, c = lin & 15;       // r: 0..255
            int qhl = r >> 6, qr = r & 63;
            cpa16(sb + (A6_Q + r * AST + c * 8) * 2,
                  Qh + (size_t)(kvh * 4 + qhl) * SEQ * HDIM +
                      (size_t)(q0 + qr) * HDIM + c * 8);
        }
#pragma unroll
        for (int i = 0; i < 2; i++) {
            int lin = tid + 512 * i;
            int r = lin >> 4, c = lin & 15;       // r: 0..63
            cpa16(sb + (A6_K + r * AST + c * 8) * 2, Kp + (size_t)r * HDIM + c * 8);
            cpa16(sb + (A6_V + r * AST + c * 8) * 2, Vp + (size_t)r * HDIM + c * 8);
        }
        CP_COMMIT();
    }

    float m0 = -INFINITY, m1 = -INFINITY, l0 = 0.f, l1 = 0.f;
    float o[16][4];
#pragma unroll
    for (int j = 0; j < 16; j++)
#pragma unroll
        for (int i = 0; i < 4; i++) o[j][i] = 0.f;

    const uint32_t qbase = A6_Q + (uint32_t)hl * 64 * AST;

    for (int t = 0; t < 64; t++) {
        CP_WAIT(0);
        __syncthreads();   // tile t ready; iter t-1 done everywhere
        if (t + 1 < 64) {
            const int k1 = (t + 1) * 64, buf = (t + 1) & 1;
#pragma unroll
            for (int i = 0; i < 2; i++) {
                int lin = tid + 512 * i;
                int r = lin >> 4, c = lin & 15;
                cpa16(sb + (A6_K + buf * 64 * AST + r * AST + c * 8) * 2,
                      Kp + (size_t)(k1 + r) * HDIM + c * 8);
                cpa16(sb + (A6_V + buf * 64 * AST + r * AST + c * 8) * 2,
                      Vp + (size_t)(k1 + r) * HDIM + c * 8);
            }
            CP_COMMIT();
        }
        const uint32_t kbase = A6_K + (uint32_t)(t & 1) * 64 * AST;
        const uint32_t vbase = A6_V + (uint32_t)(t & 1) * 64 * AST;

        // ---- scores: S[16 rows][64 kv] in regs ----
        float s[8][4];
#pragma unroll
        for (int nt = 0; nt < 8; nt++)
#pragma unroll
            for (int i = 0; i < 4; i++) s[nt][i] = 0.f;

#pragma unroll
        for (int kk = 0; kk < 8; kk++) {
            uint32_t a[4], b[8][2];
            {
                int row = wrow + (lane & 15);
                int col = kk * 16 + (lane >> 4) * 8;
                ldsm4(a[0], a[1], a[2], a[3], sb + (qbase + row * AST + col) * 2);
            }
#pragma unroll
            for (int ntp = 0; ntp < 4; ntp++) {
                int row = ntp * 16 + (lane & 7) + ((lane >> 4) & 1) * 8;
                int col = kk * 16 + ((lane >> 3) & 1) * 8;
                ldsm4(b[2 * ntp][0], b[2 * ntp][1], b[2 * ntp + 1][0], b[2 * ntp + 1][1],
                      sb + (kbase + row * AST + col) * 2);
            }
#pragma unroll
            for (int nt = 0; nt < 8; nt++)
                mma_f16(s[nt], a, b[nt]);
        }

        // ---- fully warp-local online softmax over all 64 kv ----
        float rmax0 = -INFINITY, rmax1 = -INFINITY;
#pragma unroll
        for (int nt = 0; nt < 8; nt++) {
            rmax0 = fmaxf(rmax0, fmaxf(s[nt][0], s[nt][1]));
            rmax1 = fmaxf(rmax1, fmaxf(s[nt][2], s[nt][3]));
        }
        rmax0 = fmaxf(rmax0, __shfl_xor_sync(0xffffffffu, rmax0, 1));
        rmax0 = fmaxf(rmax0, __shfl_xor_sync(0xffffffffu, rmax0, 2));
        rmax1 = fmaxf(rmax1, __shfl_xor_sync(0xffffffffu, rmax1, 1));
        rmax1 = fmaxf(rmax1, __shfl_xor_sync(0xffffffffu, rmax1, 2));

        float mnew0 = fmaxf(m0, rmax0);
        float mnew1 = fmaxf(m1, rmax1);
        float als0 = __expf(m0 - mnew0);
        float als1 = __expf(m1 - mnew1);
        m0 = mnew0;
        m1 = mnew1;

        float sum0 = 0.f, sum1 = 0.f;
#pragma unroll
        for (int nt = 0; nt < 8; nt++) {
            s[nt][0] = __expf(s[nt][0] - mnew0);
            s[nt][1] = __expf(s[nt][1] - mnew0);
            s[nt][2] = __expf(s[nt][2] - mnew1);
            s[nt][3] = __expf(s[nt][3] - mnew1);
            sum0 += s[nt][0] + s[nt][1];
            sum1 += s[nt][2] + s[nt][3];
        }
        sum0 += __shfl_xor_sync(0xffffffffu, sum0, 1);
        sum0 += __shfl_xor_sync(0xffffffffu, sum0, 2);
        sum1 += __shfl_xor_sync(0xffffffffu, sum1, 1);
        sum1 += __shfl_xor_sync(0xffffffffu, sum1, 2);
        l0 = l0 * als0 + sum0;
        l1 = l1 * als1 + sum1;

        // ---- rescale partial O, then O += P @ V (P from regs) ----
#pragma unroll
        for (int j = 0; j < 16; j++) {
            o[j][0] *= als0; o[j][1] *= als0;
            o[j][2] *= als1; o[j][3] *= als1;
        }
#pragma unroll
        for (int c = 0; c < 4; c++) {
            uint32_t a[4];
            a[0] = pack_h2(s[2 * c][0], s[2 * c][1]);
            a[1] = pack_h2(s[2 * c][2], s[2 * c][3]);
            a[2] = pack_h2(s[2 * c + 1][0], s[2 * c + 1][1]);
            a[3] = pack_h2(s[2 * c + 1][2], s[2 * c + 1][3]);
            const int vrow = c * 16 + (lane & 7) + ((lane >> 4) << 3);
#pragma unroll
            for (int nt2 = 0; nt2 < 8; nt2++) {
                int vcol = nt2 * 16 + ((lane >> 3) & 1) * 8;
                uint32_t b0, b1, b2, b3;
                ldsm4t(b0, b1, b2, b3, sb + (vbase + vrow * AST + vcol) * 2);
                uint32_t p0[2] = {b0, b2};
                uint32_t p1[2] = {b1, b3};
                mma_f16(o[nt2 * 2],     a, p0);
                mma_f16(o[nt2 * 2 + 1], a, p1);
            }
        }
    }

    // ---- finalize: divide by l, store (each q-row owned by one warp) ----
    {
        float inv0 = 1.f / l0;
        float inv1 = 1.f / l1;
#pragma unroll
        for (int j = 0; j < 16; j++) {
            int c = j * 8 + 2 * qc;
            size_t o0 = (size_t)(q0 + r0) * DMODEL + h * HDIM + c;
            size_t o1 = (size_t)(q0 + r1) * DMODEL + h * HDIM + c;
            *(uint32_t*)(AOh + o0) = pack_h2(o[j][0] * inv0, o[j][1] * inv0);
            *(uint32_t*)(AOh + o1) = pack_h2(o[j][2] * inv1, o[j][3] * inv1);
        }
    }
}

// ---------------------------------------------------------------------------
// launch
// ---------------------------------------------------------------------------
extern "C" void kernel_launch(void* const* d_in, const int* in_sizes, int n_in,
                              void* d_out, int out_size) {
    (void)in_sizes; (void)n_in; (void)out_size;
    const float* X  = (const float*)d_in[0];
    const float* Wq = (const float*)d_in[1];
    const float* Wk = (const float*)d_in[2];
    const float* Wv = (const float*)d_in[3];
    const float* Wo = (const float*)d_in[4];
    float* out = (float*)d_out;

    __half *Wt, *Wot, *Xh, *Qh, *Kh, *Vh, *AOh;
    cudaGetSymbolAddress((void**)&Wt, g_Wt);
    cudaGetSymbolAddress((void**)&Wot, g_Wot);
    cudaGetSymbolAddress((void**)&Xh, g_Xh);
    cudaGetSymbolAddress((void**)&Qh, g_Qh);
    cudaGetSymbolAddress((void**)&Kh, g_Kh);
    cudaGetSymbolAddress((void**)&Vh, g_Vh);
    cudaGetSymbolAddress((void**)&AOh, g_AOh);

    cudaFuncSetAttribute(gemm_f16, cudaFuncAttributeMaxDynamicSharedMemorySize,
                         GEMM_SMEM_BYTES);
    cudaFuncSetAttribute(gemm_qkv_rope, cudaFuncAttributeMaxDynamicSharedMemorySize,
                         GEMM_SMEM_BYTES);
    cudaFuncSetAttribute(attn6, cudaFuncAttributeMaxDynamicSharedMemorySize,
                         ATTN6_SMEM_BYTES);

    // 1) rope tables + weight transposes + X fp16 conversion
    rope_tables<<<68, 256>>>();
    transpose_f16<<<dim3(64, 64), dim3(32, 8)>>>(Wq, Wt, DMODEL, 2048);
    transpose_f16<<<dim3(16, 64), dim3(32, 8)>>>(Wk, Wt + 2048 * DMODEL, DMODEL, 512);
    transpose_f16<<<dim3(16, 64), dim3(32, 8)>>>(Wv, Wt + 2560 * DMODEL, DMODEL, 512);
    transpose_f16<<<dim3(64, 64), dim3(32, 8)>>>(Wo, Wot, DMODEL, 2048);
    convert_f16<<<SEQ * DMODEL / 4 / 256, 256>>>(X, Xh, SEQ * DMODEL / 4);

    // 2) fused QKV projection + RoPE -> per-head planes
    gemm_qkv_rope<<<dim3(NQKV / 128, SEQ / 128), 256, GEMM_SMEM_BYTES>>>(
        Xh, Wt, Qh, Kh, Vh, NQKV, DMODEL);

    // 3) attention (GQA-shared KV: 64q x 4 heads per block, KV traffic /4)
    attn6<<<dim3(SEQ / 64, NKV), 512, ATTN6_SMEM_BYTES>>>(Qh, Kh, Vh, AOh);

    // 4) output projection (fp32 out)
    gemm_f16<<<dim3(DMODEL / 128, SEQ / 128), 256, GEMM_SMEM_BYTES>>>(
        AOh, Wot, out, DMODEL, DMODEL);
}

// round 17
// speedup vs baseline: 1.5846x; 1.0245x over previous
#include <cuda_runtime.h>
#include <cuda_fp16.h>
#include <math.h>
#include <stdint.h>

// Problem constants
#define SEQ    4096
#define DMODEL 2048
#define NHEAD  16
#define NKV    4
#define HDIM   128
#define NQKV   3072
#define SCALE  0.08838834764831845f            // 1/sqrt(128)
#define QSC    (0.08838834764831845f * 1.4426950408889634f)  // SCALE * log2(e)

// ---------------------------------------------------------------------------
// Scratch (device globals; no allocation allowed)
// ---------------------------------------------------------------------------
__device__ __half g_Wt[NQKV * DMODEL];        // fused Wq|Wk|Wv transposed [N,K]
__device__ __half g_Wot[DMODEL * DMODEL];     // Wo transposed [N,K]
__device__ __half g_Xh[SEQ * DMODEL];         // X fp16
__device__ __half g_Qh[NHEAD * SEQ * HDIM];   // per-head planes, rope+log2-scale
__device__ __half g_Kh[NKV * SEQ * HDIM];     // rope applied
__device__ __half g_Vh[NKV * SEQ * HDIM];
__device__ __half g_AOh[SEQ * DMODEL];        // attention out fp16
__device__ float2 g_T1[16 * 64];              // cos/sin of a*256*inv_d
__device__ float2 g_T2[256 * 64];             // cos/sin of b*inv_d

// ---------------------------------------------------------------------------
// helpers
// ---------------------------------------------------------------------------
__device__ __forceinline__ void mma_f16(float c[4], const uint32_t a[4], const uint32_t b[2]) {
    asm volatile(
        "mma.sync.aligned.m16n8k16.row.col.f32.f16.f16.f32 "
        "{%0,%1,%2,%3}, {%4,%5,%6,%7}, {%8,%9}, {%0,%1,%2,%3};\n"
        : "+f"(c[0]), "+f"(c[1]), "+f"(c[2]), "+f"(c[3])
        : "r"(a[0]), "r"(a[1]), "r"(a[2]), "r"(a[3]), "r"(b[0]), "r"(b[1]));
}

__device__ __forceinline__ uint32_t pack_h2(float x, float y) {
    __half2 h = __floats2half2_rn(x, y);
    return *(uint32_t*)&h;
}

__device__ __forceinline__ float ex2(float x) {   // raw MUFU.EX2 (base-2 exp)
    float r;
    asm("ex2.approx.ftz.f32 %0, %1;" : "=f"(r) : "f"(x));
    return r;
}

__device__ __forceinline__ void cpa16(uint32_t saddr, const void* g) {
    asm volatile("cp.async.cg.shared.global [%0], [%1], 16;" :: "r"(saddr), "l"(g));
}
#define CP_COMMIT() asm volatile("cp.async.commit_group;" ::: "memory")
#define CP_WAIT(n)  asm volatile("cp.async.wait_group %0;" :: "n"(n) : "memory")

__device__ __forceinline__ void ldsm4(uint32_t& r0, uint32_t& r1, uint32_t& r2, uint32_t& r3,
                                      uint32_t addr) {
    asm volatile("ldmatrix.sync.aligned.m8n8.x4.shared.b16 {%0,%1,%2,%3}, [%4];"
                 : "=r"(r0), "=r"(r1), "=r"(r2), "=r"(r3) : "r"(addr));
}
__device__ __forceinline__ void ldsm4t(uint32_t& r0, uint32_t& r1, uint32_t& r2, uint32_t& r3,
                                       uint32_t addr) {
    asm volatile("ldmatrix.sync.aligned.m8n8.x4.trans.shared.b16 {%0,%1,%2,%3}, [%4];"
                 : "=r"(r0), "=r"(r1), "=r"(r2), "=r"(r3) : "r"(addr));
}

// ---------------------------------------------------------------------------
// prep kernels (fused: 2 launches total)
// ---------------------------------------------------------------------------
// all four weight transposes in one launch (blockIdx-ranged)
__global__ __launch_bounds__(256) void transpose_all(
    const float* __restrict__ Wq, const float* __restrict__ Wk,
    const float* __restrict__ Wv, const float* __restrict__ Wo,
    __half* __restrict__ Wt, __half* __restrict__ Wot) {
    __shared__ float t[32][33];
    int b = blockIdx.x;
    const float* W;
    __half* T;
    int N, tile;
    if (b < 4096)      { W = Wq; T = Wt;                      N = 2048; tile = b; }
    else if (b < 5120) { W = Wk; T = Wt + 2048 * DMODEL;      N = 512;  tile = b - 4096; }
    else if (b < 6144) { W = Wv; T = Wt + 2560 * DMODEL;      N = 512;  tile = b - 5120; }
    else               { W = Wo; T = Wot;                     N = 2048; tile = b - 6144; }
    const int K = DMODEL;
    const int ntx = N >> 5;
    const int n0 = (tile % ntx) * 32;
    const int k0 = (tile / ntx) * 32;
    int tx = threadIdx.x, ty = threadIdx.y;
#pragma unroll
    for (int i = 0; i < 4; i++)
        t[ty + 8 * i][tx] = W[(size_t)(k0 + ty + 8 * i) * N + n0 + tx];
    __syncthreads();
#pragma unroll
    for (int i = 0; i < 4; i++)
        T[(size_t)(n0 + ty + 8 * i) * K + k0 + tx] = __float2half(t[tx][ty + 8 * i]);
}

// X->fp16 conversion + rope tables in one launch
#define CONV_BLOCKS (SEQ * DMODEL / 4 / 256)   // 8192
__global__ __launch_bounds__(256) void prep_misc(const float* __restrict__ X,
                                                 __half* __restrict__ Xh) {
    if (blockIdx.x < CONV_BLOCKS) {
        int i = blockIdx.x * 256 + threadIdx.x;
        float4 v = ((const float4*)X)[i];
        uint2 p;
        p.x = pack_h2(v.x, v.y);
        p.y = pack_h2(v.z, v.w);
        ((uint2*)Xh)[i] = p;
    } else {
        int idx = (blockIdx.x - CONV_BLOCKS) * 256 + threadIdx.x;
        if (idx >= 1024 + 16384) return;
        double ang;
        float2* dst;
        if (idx < 1024) {
            int a = idx >> 6, d = idx & 63;
            double inv = exp(-(double)d * (log(10000.0) / 64.0));
            ang = 256.0 * (double)a * inv;
            dst = g_T1 + idx;
        } else {
            int e = idx - 1024;
            int b = e >> 6, d = e & 63;
            double inv = exp(-(double)d * (log(10000.0) / 64.0));
            ang = (double)b * inv;
            dst = g_T2 + e;
        }
        double s, c;
        sincos(ang, &s, &c);
        *dst = make_float2((float)c, (float)s);
    }
}

// ---------------------------------------------------------------------------
// fp16 GEMM core (block 128x128, BK=64, 2-stage cp.async, ldmatrix, occ 2)
// ---------------------------------------------------------------------------
#define GSS 72
#define GS_TILE  (128 * GSS)
#define GS_STAGE (2 * GS_TILE)
#define GEMM_SMEM_BYTES (2 * GS_STAGE * 2)

#define GEMM_BODY(...)                                                          \
    extern __shared__ __half gsm[];                                             \
    const uint32_t sb = (uint32_t)__cvta_generic_to_shared(gsm);                \
    const int tid = threadIdx.x, wid = tid >> 5, lane = tid & 31;               \
    const int gr = lane >> 2, qc = lane & 3;                                    \
    const int bm = blockIdx.y * 128, bn = blockIdx.x * 128;                     \
    const int wm = (wid & 3) * 32, wn = (wid >> 2) * 64;                        \
    const int T = K >> 6;                                                       \
    float acc[2][8][4];                                                         \
    _Pragma("unroll")                                                           \
    for (int mt = 0; mt < 2; mt++)                                              \
        _Pragma("unroll")                                                       \
        for (int nt = 0; nt < 8; nt++)                                          \
            _Pragma("unroll")                                                   \
            for (int i = 0; i < 4; i++) acc[mt][nt][i] = 0.f;                   \
    auto load_chunk = [&](int t) {                                              \
        const int k0 = t * 64;                                                  \
        const uint32_t stage = (t & 1) ? (uint32_t)GS_STAGE : 0u;               \
        _Pragma("unroll")                                                       \
        for (int tile = 0; tile < 2; tile++) {                                  \
            const __half* g = (tile == 0) ? A : Bt;                             \
            const int gbase = (tile == 0) ? bm : bn;                            \
            _Pragma("unroll")                                                   \
            for (int i = 0; i < 4; i++) {                                       \
                int idx = tid + 256 * i;                                        \
                int r = idx >> 3, c = idx & 7;                                  \
                cpa16(sb + (stage + tile * GS_TILE + r * GSS + c * 8) * 2,      \
                      g + (size_t)(gbase + r) * K + k0 + c * 8);                \
            }                                                                   \
        }                                                                       \
    };                                                                          \
    load_chunk(0);                                                              \
    CP_COMMIT();                                                                \
    for (int t = 0; t < T; t++) {                                               \
        if (t + 1 < T) { load_chunk(t + 1); CP_COMMIT(); CP_WAIT(1); }          \
        else           { CP_WAIT(0); }                                          \
        __syncthreads();                                                        \
        const uint32_t stage = (t & 1) ? (uint32_t)GS_STAGE : 0u;               \
        _Pragma("unroll")                                                       \
        for (int kk = 0; kk < 4; kk++) {                                        \
            uint32_t b[8][2];                                                   \
            _Pragma("unroll")                                                   \
            for (int ntp = 0; ntp < 4; ntp++) {                                 \
                int row = wn + ntp * 16 + (lane & 7) + ((lane >> 4) & 1) * 8;   \
                int col = kk * 16 + ((lane >> 3) & 1) * 8;                      \
                ldsm4(b[2 * ntp][0], b[2 * ntp][1], b[2 * ntp + 1][0],          \
                      b[2 * ntp + 1][1],                                        \
                      sb + (stage + GS_TILE + row * GSS + col) * 2);            \
            }                                                                   \
            uint32_t a[2][4];                                                   \
            _Pragma("unroll")                                                   \
            for (int mt = 0; mt < 2; mt++) {                                    \
                int row = wm + mt * 16 + (lane & 15);                           \
                int col = kk * 16 + (lane >> 4) * 8;                            \
                ldsm4(a[mt][0], a[mt][1], a[mt][2], a[mt][3],                   \
                      sb + (stage + row * GSS + col) * 2);                      \
            }                                                                   \
            _Pragma("unroll")                                                   \
            for (int mt = 0; mt < 2; mt++)                                      \
                _Pragma("unroll")                                               \
                for (int nt = 0; nt < 8; nt++)                                  \
                    mma_f16(acc[mt][nt], a[mt], b[nt]);                         \
        }                                                                       \
        __syncthreads();                                                        \
    }                                                                           \
    __VA_ARGS__

// out-projection: fp32 C
__global__ __launch_bounds__(256, 2) void gemm_f16(
    const __half* __restrict__ A, const __half* __restrict__ Bt,
    float* __restrict__ C, int N, int K) {
    GEMM_BODY({
#pragma unroll
        for (int mt = 0; mt < 2; mt++) {
            int r = bm + wm + mt * 16 + gr;
#pragma unroll
            for (int nt = 0; nt < 8; nt++) {
                int c = bn + wn + nt * 8 + 2 * qc;
                *(float2*)(C + (size_t)r * N + c) =
                    make_float2(acc[mt][nt][0], acc[mt][nt][1]);
                *(float2*)(C + (size_t)(r + 8) * N + c) =
                    make_float2(acc[mt][nt][2], acc[mt][nt][3]);
            }
        }
    })
}

// QKV projection with fused RoPE epilogue -> per-head fp16 planes.
// Q scaled by SCALE*log2(e) so attention scores land in base-2 domain.
#define CTS 132
__global__ __launch_bounds__(256, 2) void gemm_qkv_rope(
    const __half* __restrict__ A, const __half* __restrict__ Bt,
    __half* __restrict__ Qh, __half* __restrict__ Kh, __half* __restrict__ Vh,
    int N, int K) {
    GEMM_BODY({
        if (bn >= 2560) {
            __half* plane = Vh + (size_t)((bn - 2560) >> 7) * SEQ * HDIM;
#pragma unroll
            for (int mt = 0; mt < 2; mt++) {
                int pos = bm + wm + mt * 16 + gr;
#pragma unroll
                for (int nt = 0; nt < 8; nt++) {
                    int c = wn + nt * 8 + 2 * qc;
                    *(uint32_t*)(plane + (size_t)pos * HDIM + c) =
                        pack_h2(acc[mt][nt][0], acc[mt][nt][1]);
                    *(uint32_t*)(plane + (size_t)(pos + 8) * HDIM + c) =
                        pack_h2(acc[mt][nt][2], acc[mt][nt][3]);
                }
            }
        } else {
            const bool isq = (bn < 2048);
            __half* plane = isq ? (Qh + (size_t)(bn >> 7) * SEQ * HDIM)
                                : (Kh + (size_t)((bn - 2048) >> 7) * SEQ * HDIM);
            const float sc = isq ? QSC : 1.f;
            float* Ct = (float*)gsm;   // 128 x 132 fp32 (even stride: f2 aligned)
#pragma unroll
            for (int mt = 0; mt < 2; mt++) {
                int r = wm + mt * 16 + gr;
#pragma unroll
                for (int nt = 0; nt < 8; nt++) {
                    int c = wn + nt * 8 + 2 * qc;
                    *(float2*)&Ct[r * CTS + c] =
                        make_float2(acc[mt][nt][0], acc[mt][nt][1]);
                    *(float2*)&Ct[(r + 8) * CTS + c] =
                        make_float2(acc[mt][nt][2], acc[mt][nt][3]);
                }
            }
            __syncthreads();
            const int row = tid >> 1;
            const int cb = (tid & 1) * 32;
            const int pos = bm + row;
            const float2* t1 = g_T1 + ((pos >> 8) << 6);
            const float2* t2 = g_T2 + ((pos & 255) << 6);
            uint32_t outlo[16];
            uint32_t outhi[16];
#pragma unroll
            for (int j = 0; j < 32; j += 2) {
                int d0 = cb + j;
                int d1 = cb + j + 1;
                float2 A0 = t1[d0];
                float2 B0 = t2[d0];
                float2 A1 = t1[d1];
                float2 B1 = t2[d1];
                float c0 = A0.x * B0.x - A0.y * B0.y;
                float s0 = A0.y * B0.x + A0.x * B0.y;
                float c1 = A1.x * B1.x - A1.y * B1.y;
                float s1 = A1.y * B1.x + A1.x * B1.y;
                float xr0 = Ct[row * CTS + d0];
                float xi0 = Ct[row * CTS + d0 + 64];
                float xr1 = Ct[row * CTS + d1];
                float xi1 = Ct[row * CTS + d1 + 64];
                outlo[j >> 1] = pack_h2((xr0 * c0 - xi0 * s0) * sc,
                                        (xr1 * c1 - xi1 * s1) * sc);
                outhi[j >> 1] = pack_h2((xr0 * s0 + xi0 * c0) * sc,
                                        (xr1 * s1 + xi1 * c1) * sc);
            }
            __half* orow = plane + (size_t)pos * HDIM + cb;
#pragma unroll
            for (int u = 0; u < 4; u++) {
                ((uint4*)orow)[u] = ((uint4*)outlo)[u];
                ((uint4*)(orow + 64))[u] = ((uint4*)outhi)[u];
            }
        }
    })
}

// ---------------------------------------------------------------------------
// Flash attention v6: GQA-shared KV, base-2 softmax (scores pre-scaled by
// log2e in Q). Block = 64 q x 4 heads (one kv-head), 512 thr / 16 warps.
// Each warp: 16 q-rows of one head, full 64-kv width, warp-local stats.
// ---------------------------------------------------------------------------
#define AST 136
#define A6_Q  0
#define A6_K  (256 * AST)
#define A6_V  (A6_K + 2 * 64 * AST)
#define ATTN6_SMEM_BYTES ((A6_V + 2 * 64 * AST) * 2)

__global__ __launch_bounds__(512, 1) void attn6(const __half* __restrict__ Qh,
                                                const __half* __restrict__ Kh,
                                                const __half* __restrict__ Vh,
                                                __half* __restrict__ AOh) {
    extern __shared__ __half smh[];
    const uint32_t sb = (uint32_t)__cvta_generic_to_shared(smh);

    const int tid = threadIdx.x, wid = tid >> 5, lane = tid & 31;
    const int gr = lane >> 2, qc = lane & 3;
    const int q0 = blockIdx.x * 64;
    const int kvh = blockIdx.y;
    const int hl   = wid >> 2;
    const int h    = kvh * 4 + hl;
    const int wrow = (wid & 3) * 16;
    const int r0 = wrow + gr, r1 = wrow + gr + 8;

    const __half* Kp = Kh + (size_t)kvh * SEQ * HDIM;
    const __half* Vp = Vh + (size_t)kvh * SEQ * HDIM;

    {
#pragma unroll
        for (int i = 0; i < 8; i++) {
            int lin = tid + 512 * i;
            int r = lin >> 4, c = lin & 15;
            int qhl = r >> 6, qr = r & 63;
            cpa16(sb + (A6_Q + r * AST + c * 8) * 2,
                  Qh + (size_t)(kvh * 4 + qhl) * SEQ * HDIM +
                      (size_t)(q0 + qr) * HDIM + c * 8);
        }
#pragma unroll
        for (int i = 0; i < 2; i++) {
            int lin = tid + 512 * i;
            int r = lin >> 4, c = lin & 15;
            cpa16(sb + (A6_K + r * AST + c * 8) * 2, Kp + (size_t)r * HDIM + c * 8);
            cpa16(sb + (A6_V + r * AST + c * 8) * 2, Vp + (size_t)r * HDIM + c * 8);
        }
        CP_COMMIT();
    }

    float m0 = -INFINITY, m1 = -INFINITY, l0 = 0.f, l1 = 0.f;
    float o[16][4];
#pragma unroll
    for (int j = 0; j < 16; j++)
#pragma unroll
        for (int i = 0; i < 4; i++) o[j][i] = 0.f;

    const uint32_t qbase = A6_Q + (uint32_t)hl * 64 * AST;

    for (int t = 0; t < 64; t++) {
        CP_WAIT(0);
        __syncthreads();
        if (t + 1 < 64) {
            const int k1 = (t + 1) * 64, buf = (t + 1) & 1;
#pragma unroll
            for (int i = 0; i < 2; i++) {
                int lin = tid + 512 * i;
                int r = lin >> 4, c = lin & 15;
                cpa16(sb + (A6_K + buf * 64 * AST + r * AST + c * 8) * 2,
                      Kp + (size_t)(k1 + r) * HDIM + c * 8);
                cpa16(sb + (A6_V + buf * 64 * AST + r * AST + c * 8) * 2,
                      Vp + (size_t)(k1 + r) * HDIM + c * 8);
            }
            CP_COMMIT();
        }
        const uint32_t kbase = A6_K + (uint32_t)(t & 1) * 64 * AST;
        const uint32_t vbase = A6_V + (uint32_t)(t & 1) * 64 * AST;

        float s[8][4];
#pragma unroll
        for (int nt = 0; nt < 8; nt++)
#pragma unroll
            for (int i = 0; i < 4; i++) s[nt][i] = 0.f;

#pragma unroll
        for (int kk = 0; kk < 8; kk++) {
            uint32_t a[4], b[8][2];
            {
                int row = wrow + (lane & 15);
                int col = kk * 16 + (lane >> 4) * 8;
                ldsm4(a[0], a[1], a[2], a[3], sb + (qbase + row * AST + col) * 2);
            }
#pragma unroll
            for (int ntp = 0; ntp < 4; ntp++) {
                int row = ntp * 16 + (lane & 7) + ((lane >> 4) & 1) * 8;
                int col = kk * 16 + ((lane >> 3) & 1) * 8;
                ldsm4(b[2 * ntp][0], b[2 * ntp][1], b[2 * ntp + 1][0], b[2 * ntp + 1][1],
                      sb + (kbase + row * AST + col) * 2);
            }
#pragma unroll
            for (int nt = 0; nt < 8; nt++)
                mma_f16(s[nt], a, b[nt]);
        }

        // ---- warp-local online softmax (base-2 domain, raw EX2) ----
        float rmax0 = -INFINITY, rmax1 = -INFINITY;
#pragma unroll
        for (int nt = 0; nt < 8; nt++) {
            rmax0 = fmaxf(rmax0, fmaxf(s[nt][0], s[nt][1]));
            rmax1 = fmaxf(rmax1, fmaxf(s[nt][2], s[nt][3]));
        }
        rmax0 = fmaxf(rmax0, __shfl_xor_sync(0xffffffffu, rmax0, 1));
        rmax0 = fmaxf(rmax0, __shfl_xor_sync(0xffffffffu, rmax0, 2));
        rmax1 = fmaxf(rmax1, __shfl_xor_sync(0xffffffffu, rmax1, 1));
        rmax1 = fmaxf(rmax1, __shfl_xor_sync(0xffffffffu, rmax1, 2));

        float mnew0 = fmaxf(m0, rmax0);
        float mnew1 = fmaxf(m1, rmax1);
        float als0 = ex2(m0 - mnew0);
        float als1 = ex2(m1 - mnew1);
        m0 = mnew0;
        m1 = mnew1;

        float sum0 = 0.f, sum1 = 0.f;
#pragma unroll
        for (int nt = 0; nt < 8; nt++) {
            s[nt][0] = ex2(s[nt][0] - mnew0);
            s[nt][1] = ex2(s[nt][1] - mnew0);
            s[nt][2] = ex2(s[nt][2] - mnew1);
            s[nt][3] = ex2(s[nt][3] - mnew1);
            sum0 += s[nt][0] + s[nt][1];
            sum1 += s[nt][2] + s[nt][3];
        }
        sum0 += __shfl_xor_sync(0xffffffffu, sum0, 1);
        sum0 += __shfl_xor_sync(0xffffffffu, sum0, 2);
        sum1 += __shfl_xor_sync(0xffffffffu, sum1, 1);
        sum1 += __shfl_xor_sync(0xffffffffu, sum1, 2);
        l0 = l0 * als0 + sum0;
        l1 = l1 * als1 + sum1;

#pragma unroll
        for (int j = 0; j < 16; j++) {
            o[j][0] *= als0; o[j][1] *= als0;
            o[j][2] *= als1; o[j][3] *= als1;
        }
#pragma unroll
        for (int c = 0; c < 4; c++) {
            uint32_t a[4];
            a[0] = pack_h2(s[2 * c][0], s[2 * c][1]);
            a[1] = pack_h2(s[2 * c][2], s[2 * c][3]);
            a[2] = pack_h2(s[2 * c + 1][0], s[2 * c + 1][1]);
            a[3] = pack_h2(s[2 * c + 1][2], s[2 * c + 1][3]);
            const int vrow = c * 16 + (lane & 7) + ((lane >> 4) << 3);
#pragma unroll
            for (int nt2 = 0; nt2 < 8; nt2++) {
                int vcol = nt2 * 16 + ((lane >> 3) & 1) * 8;
                uint32_t b0, b1, b2, b3;
                ldsm4t(b0, b1, b2, b3, sb + (vbase + vrow * AST + vcol) * 2);
                uint32_t p0[2] = {b0, b2};
                uint32_t p1[2] = {b1, b3};
                mma_f16(o[nt2 * 2],     a, p0);
                mma_f16(o[nt2 * 2 + 1], a, p1);
            }
        }
    }

    {
        float inv0 = 1.f / l0;
        float inv1 = 1.f / l1;
#pragma unroll
        for (int j = 0; j < 16; j++) {
            int c = j * 8 + 2 * qc;
            size_t o0 = (size_t)(q0 + r0) * DMODEL + h * HDIM + c;
            size_t o1 = (size_t)(q0 + r1) * DMODEL + h * HDIM + c;
            *(uint32_t*)(AOh + o0) = pack_h2(o[j][0] * inv0, o[j][1] * inv0);
            *(uint32_t*)(AOh + o1) = pack_h2(o[j][2] * inv1, o[j][3] * inv1);
        }
    }
}

// ---------------------------------------------------------------------------
// launch
// ---------------------------------------------------------------------------
extern "C" void kernel_launch(void* const* d_in, const int* in_sizes, int n_in,
                              void* d_out, int out_size) {
    (void)in_sizes; (void)n_in; (void)out_size;
    const float* X  = (const float*)d_in[0];
    const float* Wq = (const float*)d_in[1];
    const float* Wk = (const float*)d_in[2];
    const float* Wv = (const float*)d_in[3];
    const float* Wo = (const float*)d_in[4];
    float* out = (float*)d_out;

    __half *Wt, *Wot, *Xh, *Qh, *Kh, *Vh, *AOh;
    cudaGetSymbolAddress((void**)&Wt, g_Wt);
    cudaGetSymbolAddress((void**)&Wot, g_Wot);
    cudaGetSymbolAddress((void**)&Xh, g_Xh);
    cudaGetSymbolAddress((void**)&Qh, g_Qh);
    cudaGetSymbolAddress((void**)&Kh, g_Kh);
    cudaGetSymbolAddress((void**)&Vh, g_Vh);
    cudaGetSymbolAddress((void**)&AOh, g_AOh);

    cudaFuncSetAttribute(gemm_f16, cudaFuncAttributeMaxDynamicSharedMemorySize,
                         GEMM_SMEM_BYTES);
    cudaFuncSetAttribute(gemm_qkv_rope, cudaFuncAttributeMaxDynamicSharedMemorySize,
                         GEMM_SMEM_BYTES);
    cudaFuncSetAttribute(attn6, cudaFuncAttributeMaxDynamicSharedMemorySize,
                         ATTN6_SMEM_BYTES);

    // 1) fused prep: X conversion + rope tables; all 4 weight transposes
    prep_misc<<<CONV_BLOCKS + 68, 256>>>(X, Xh);
    transpose_all<<<10240, dim3(32, 8)>>>(Wq, Wk, Wv, Wo, Wt, Wot);

    // 2) fused QKV projection + RoPE -> per-head planes (Q in log2 domain)
    gemm_qkv_rope<<<dim3(NQKV / 128, SEQ / 128), 256, GEMM_SMEM_BYTES>>>(
        Xh, Wt, Qh, Kh, Vh, NQKV, DMODEL);

    // 3) attention (GQA-shared KV, base-2 softmax)
    attn6<<<dim3(SEQ / 64, NKV), 512, ATTN6_SMEM_BYTES>>>(Qh, Kh, Vh, AOh);

    // 4) output projection (fp32 out)
    gemm_f16<<<dim3(DMODEL / 128, SEQ / 128), 256, GEMM_SMEM_BYTES>>>(
        AOh, Wot, out, DMODEL, DMODEL);
}